// round 1
// baseline (speedup 1.0000x reference)
#include <cuda_runtime.h>
#include <math.h>

// Problem constants
#define B_   8
#define N_   4096
#define D_   768
#define H_   12
#define M_   64
#define L_   4
#define HD_  64
#define BM_  (B_ * M_)      // 512
#define DH_  (4 * D_)       // 3072
#define ATTN_SCALE 0.125f   // 1/sqrt(64)

// ---------------------------------------------------------------------------
// Scratch (device globals — no cudaMalloc allowed)
// ---------------------------------------------------------------------------
__device__ float g_S[B_ * H_ * M_ * N_];     // 25.2M floats: attn logits/probs (also pooling logits)
__device__ float g_x[BM_ * D_];              // pooled / layer output
__device__ float g_queries[BM_ * D_];
__device__ float g_q2[BM_ * D_];             // [b][m][h*64+e]
__device__ float g_qt[B_ * H_ * M_ * D_];    // q-tilde [b][h][m][d]
__device__ float g_ot[B_ * H_ * M_ * D_];    // o-tilde [b][h][m][d]
__device__ float g_Wf[H_ * D_ * HD_];        // fused vw@hw per head
__device__ float g_bias2[H_ * HD_];          // vb@hw + hb
__device__ float g_o2[BM_ * D_];
__device__ float g_o3[BM_ * D_];
__device__ float g_x1[BM_ * D_];
__device__ float g_hid[BM_ * DH_];
__device__ float g_mout[BM_ * D_];

// ---------------------------------------------------------------------------
// Generic batched SGEMM: C = alpha * A @ op(B) (+ bias) (+ gelu)
//   A: [M,K] row-major (lda), B: NN -> [K,N] (ldb), TRANSB -> [N,K] (ldb)
//   2-index batching: grid.z = I*J, strides per operand for i and j.
//   Tile 128x128x8, 256 threads, 8x8 per thread, double-buffered SMEM.
// Requires: K % 8 == 0, N % 4 == 0, all lds/offsets multiple of 4 floats.
// ---------------------------------------------------------------------------
template <bool TRANSB>
__global__ __launch_bounds__(256, 2)
void sgemm_kernel(const float* __restrict__ A, const float* __restrict__ Bm,
                  float* __restrict__ C, const float* __restrict__ bias,
                  int M, int N, int K, int lda, int ldb, int ldc,
                  long sAi, long sAj, long sBi, long sBj, long sCi, long sCj,
                  long sbj, int J, float alpha, int act)
{
    const int BK = 8;
    int bz = blockIdx.z;
    int bi = bz / J, bj = bz - bi * J;
    A  += (size_t)bi * sAi + (size_t)bj * sAj;
    Bm += (size_t)bi * sBi + (size_t)bj * sBj;
    C  += (size_t)bi * sCi + (size_t)bj * sCj;
    if (bias) bias += (size_t)bj * sbj;

    __shared__ __align__(16) float As[2][BK][128];
    __shared__ __align__(16) float Bs[2][BK][128];

    int tid = threadIdx.x;
    int tx = tid & 15, ty = tid >> 4;
    int row0 = blockIdx.y * 128;
    int col0 = blockIdx.x * 128;

    // loader indices
    int arow = tid >> 1;           // 0..127
    int acol = (tid & 1) << 2;     // 0 or 4
    int bk   = tid >> 5;           // NN: 0..7
    int bn   = (tid & 31) << 2;    // NN: 0..124

    float acc[8][8];
#pragma unroll
    for (int i = 0; i < 8; i++)
#pragma unroll
        for (int j = 0; j < 8; j++) acc[i][j] = 0.f;

    auto loadA = [&](int buf, int k0) {
        int r = row0 + arow;
        float4 v = make_float4(0.f, 0.f, 0.f, 0.f);
        if (r < M) v = *(const float4*)(A + (size_t)r * lda + k0 + acol);
        As[buf][acol + 0][arow] = v.x;
        As[buf][acol + 1][arow] = v.y;
        As[buf][acol + 2][arow] = v.z;
        As[buf][acol + 3][arow] = v.w;
    };
    auto loadB = [&](int buf, int k0) {
        if (TRANSB) {
            int n = col0 + arow;
            float4 v = make_float4(0.f, 0.f, 0.f, 0.f);
            if (n < N) v = *(const float4*)(Bm + (size_t)n * ldb + k0 + acol);
            Bs[buf][acol + 0][arow] = v.x;
            Bs[buf][acol + 1][arow] = v.y;
            Bs[buf][acol + 2][arow] = v.z;
            Bs[buf][acol + 3][arow] = v.w;
        } else {
            int n = col0 + bn;
            float4 v = make_float4(0.f, 0.f, 0.f, 0.f);
            if (n < N) v = *(const float4*)(Bm + (size_t)(k0 + bk) * ldb + n);
            *(float4*)&Bs[buf][bk][bn] = v;
        }
    };

    loadA(0, 0);
    loadB(0, 0);
    __syncthreads();
    int buf = 0;
    for (int k0 = 0; k0 < K; k0 += BK) {
        if (k0 + BK < K) { loadA(buf ^ 1, k0 + BK); loadB(buf ^ 1, k0 + BK); }
#pragma unroll
        for (int kk = 0; kk < BK; kk++) {
            float4 a0 = *(const float4*)&As[buf][kk][ty * 4];
            float4 a1 = *(const float4*)&As[buf][kk][ty * 4 + 64];
            float4 b0 = *(const float4*)&Bs[buf][kk][tx * 4];
            float4 b1 = *(const float4*)&Bs[buf][kk][tx * 4 + 64];
            float ar[8] = {a0.x, a0.y, a0.z, a0.w, a1.x, a1.y, a1.z, a1.w};
            float br[8] = {b0.x, b0.y, b0.z, b0.w, b1.x, b1.y, b1.z, b1.w};
#pragma unroll
            for (int i = 0; i < 8; i++)
#pragma unroll
                for (int j = 0; j < 8; j++) acc[i][j] += ar[i] * br[j];
        }
        buf ^= 1;
        __syncthreads();
    }

#pragma unroll
    for (int i = 0; i < 8; i++) {
        int r = row0 + ty * 4 + (i >> 2) * 64 + (i & 3);
        if (r >= M) continue;
#pragma unroll
        for (int j = 0; j < 8; j++) {
            int c = col0 + tx * 4 + (j >> 2) * 64 + (j & 3);
            if (c >= N) continue;
            float v = acc[i][j] * alpha;
            if (bias) v += bias[c];
            if (act == 1) v = 0.5f * v * (1.f + erff(v * 0.7071067811865475f));
            C[(size_t)r * ldc + c] = v;
        }
    }
}

// ---------------------------------------------------------------------------
// Row softmax (in place), one block per row
// ---------------------------------------------------------------------------
__global__ void softmax_kernel(float* __restrict__ X, int ncols)
{
    float* row = X + (size_t)blockIdx.x * ncols;
    __shared__ float red[256];
    int tid = threadIdx.x;
    float m = -1e30f;
    for (int c = tid; c < ncols; c += 256) m = fmaxf(m, row[c]);
    red[tid] = m; __syncthreads();
    for (int s = 128; s > 0; s >>= 1) {
        if (tid < s) red[tid] = fmaxf(red[tid], red[tid + s]);
        __syncthreads();
    }
    m = red[0];
    __syncthreads();
    float sum = 0.f;
    for (int c = tid; c < ncols; c += 256) {
        float e = __expf(row[c] - m);
        row[c] = e;
        sum += e;
    }
    red[tid] = sum; __syncthreads();
    for (int s = 128; s > 0; s >>= 1) {
        if (tid < s) red[tid] += red[tid + s];
        __syncthreads();
    }
    float inv = 1.f / red[0];
    for (int c = tid; c < ncols; c += 256) row[c] *= inv;
}

// ---------------------------------------------------------------------------
// out[r,:] = LayerNorm(a[r,:] + b[r,:]) * g + beta   (row length = D_ = 768)
// ---------------------------------------------------------------------------
__global__ void add_ln_kernel(const float* __restrict__ Xa, const float* __restrict__ Xb,
                              const float* __restrict__ g, const float* __restrict__ beta,
                              float* __restrict__ out)
{
    int r = blockIdx.x;
    const float* a = Xa + (size_t)r * D_;
    const float* b = Xb + (size_t)r * D_;
    float* o = out + (size_t)r * D_;
    __shared__ float red[256];
    int tid = threadIdx.x;
    float v[3];
    float s = 0.f;
#pragma unroll
    for (int i = 0; i < 3; i++) { int c = tid + i * 256; v[i] = a[c] + b[c]; s += v[i]; }
    red[tid] = s; __syncthreads();
    for (int st = 128; st > 0; st >>= 1) {
        if (tid < st) red[tid] += red[tid + st];
        __syncthreads();
    }
    float mean = red[0] * (1.f / D_);
    __syncthreads();
    s = 0.f;
#pragma unroll
    for (int i = 0; i < 3; i++) { float d = v[i] - mean; s += d * d; }
    red[tid] = s; __syncthreads();
    for (int st = 128; st > 0; st >>= 1) {
        if (tid < st) red[tid] += red[tid + st];
        __syncthreads();
    }
    float rstd = rsqrtf(red[0] * (1.f / D_) + 1e-5f);
#pragma unroll
    for (int i = 0; i < 3; i++) {
        int c = tid + i * 256;
        o[c] = (v[i] - mean) * rstd * g[c] + beta[c];
    }
}

// queries[b,m,d] = x[b,m,d] + qc[m,d] (broadcast over b)
__global__ void make_queries_kernel(const float* __restrict__ x, const float* __restrict__ qc,
                                    float* __restrict__ q)
{
    int i = blockIdx.x * 256 + threadIdx.x;   // 512*768 total
    int d = i % D_;
    int m = (i / D_) & (M_ - 1);
    q[i] = x[i] + qc[m * D_ + d];
}

// bias2[h,f] = sum_e vb[h,e]*hw[h,e,f] + hb[h,f]
__global__ void bias2_kernel(const float* __restrict__ vb, const float* __restrict__ hw,
                             const float* __restrict__ hb, float* __restrict__ out)
{
    int idx = blockIdx.x * 64 + threadIdx.x;   // <<<12,64>>>
    int h = idx >> 6, f = idx & 63;
    const float* vbh = vb + h * 64;
    const float* hwh = hw + h * 4096;
    float s = hb[idx];
#pragma unroll 8
    for (int e = 0; e < 64; e++) s += vbh[e] * hwh[e * 64 + f];
    out[idx] = s;
}

// ---------------------------------------------------------------------------
// Host side
// ---------------------------------------------------------------------------
static void gemm(bool transB, const float* A, const float* B, float* C, const float* bias,
                 int M, int N, int K, int lda, int ldb, int ldc,
                 long sAi, long sAj, long sBi, long sBj, long sCi, long sCj,
                 long sbj, int I, int J, float alpha, int act)
{
    dim3 grid((N + 127) / 128, (M + 127) / 128, I * J);
    if (transB)
        sgemm_kernel<true><<<grid, 256>>>(A, B, C, bias, M, N, K, lda, ldb, ldc,
                                          sAi, sAj, sBi, sBj, sCi, sCj, sbj, J, alpha, act);
    else
        sgemm_kernel<false><<<grid, 256>>>(A, B, C, bias, M, N, K, lda, ldb, ldc,
                                           sAi, sAj, sBi, sBj, sCi, sCj, sbj, J, alpha, act);
}

template <typename T>
static T* sym(const void* symbol)
{
    void* p = nullptr;
    cudaGetSymbolAddress(&p, symbol);
    return (T*)p;
}

extern "C" void kernel_launch(void* const* d_in, const int* in_sizes, int n_in,
                              void* d_out, int out_size)
{
    const float* latent = (const float*)d_in[0];   // [8,4096,768]
    const float* selector = (const float*)d_in[1]; // [64,768]
    const float* qc = (const float*)d_in[2];       // [4,64,768]
    const float* qw = (const float*)d_in[3];       // [4,12,768,64]
    const float* qb = (const float*)d_in[4];       // [4,12,64]
    const float* kw = (const float*)d_in[5];       // [4,12,768,64]
    // kb (d_in[6]) cancels in softmax exactly — per-row constant shift
    const float* vw = (const float*)d_in[7];       // [4,12,768,64]
    const float* vb = (const float*)d_in[8];       // [4,12,64]
    const float* hw = (const float*)d_in[9];       // [4,12,64,64]
    const float* hb = (const float*)d_in[10];      // [4,12,64]
    const float* ow = (const float*)d_in[11];      // [4,768,768]
    const float* ob = (const float*)d_in[12];      // [4,768]
    const float* w1 = (const float*)d_in[13];      // [4,768,3072]
    const float* b1 = (const float*)d_in[14];      // [4,3072]
    const float* w2 = (const float*)d_in[15];      // [4,3072,768]
    const float* b2 = (const float*)d_in[16];      // [4,768]
    const float* g1 = (const float*)d_in[17];      // [4,768]
    const float* be1 = (const float*)d_in[18];     // [4,768]
    const float* g2 = (const float*)d_in[19];      // [4,768]
    const float* be2 = (const float*)d_in[20];     // [4,768]

    float* S   = sym<float>(g_S);
    float* x   = sym<float>(g_x);
    float* qu  = sym<float>(g_queries);
    float* q2  = sym<float>(g_q2);
    float* qt  = sym<float>(g_qt);
    float* ot  = sym<float>(g_ot);
    float* Wf  = sym<float>(g_Wf);
    float* bi2 = sym<float>(g_bias2);
    float* o2  = sym<float>(g_o2);
    float* o3  = sym<float>(g_o3);
    float* x1  = sym<float>(g_x1);
    float* hid = sym<float>(g_hid);
    float* mo  = sym<float>(g_mout);
    float* out = (float*)d_out;

    const long LAT_B = (long)N_ * D_;          // 3145728
    const long WHD   = (long)D_ * HD_;         // 49152  (per-head 768x64)
    const long WL    = (long)H_ * WHD;         // 589824 (per-layer qkv weights)

    // ---- Stage 0: soft-selection pooling ----
    // logits[b,m,n] = selector[m,:] . latent[b,n,:]
    gemm(true, selector, latent, S, nullptr,
         M_, N_, D_, D_, D_, N_,
         0, 0, LAT_B, 0, (long)M_ * N_, 0, 0, B_, 1, 1.0f, 0);
    softmax_kernel<<<B_ * M_, 256>>>(S, N_);
    // x[b,m,d] = weights[b,m,:] @ latent[b,:,d]
    gemm(false, S, latent, x, nullptr,
         M_, D_, N_, N_, D_, D_,
         (long)M_ * N_, 0, LAT_B, 0, (long)M_ * D_, 0, 0, B_, 1, 1.0f, 0);

    // ---- L transformer layers ----
    for (int l = 0; l < L_; l++) {
        // queries = qc[l] + x
        make_queries_kernel<<<(BM_ * D_) / 256, 256>>>(x, qc + (long)l * M_ * D_, qu);

        // q2[b,m,h*64+e] = queries @ qw[l,h] + qb[l,h]   (batched over h)
        gemm(false, qu, qw + (long)l * WL, q2, qb + (long)l * H_ * HD_,
             BM_, HD_, D_, D_, HD_, D_,
             0, 0, 0, WHD, 0, HD_, HD_, 1, H_, 1.0f, 0);

        // qt[b,h,m,d] = q2[b,:,h,:] @ kw[l,h]^T   (batched over (b,h))
        gemm(true, q2, kw + (long)l * WL, qt, nullptr,
             M_, D_, HD_, D_, HD_, D_,
             (long)M_ * D_, HD_, 0, WHD, (long)H_ * M_ * D_, (long)M_ * D_,
             0, B_, H_, 1.0f, 0);

        // S[b, h*64+m, n] = scale * qt_b @ latent_b^T   (batched over b)
        gemm(true, qt, latent, S, nullptr,
             H_ * M_, N_, D_, D_, D_, N_,
             (long)H_ * M_ * D_, 0, LAT_B, 0, (long)H_ * M_ * N_, 0,
             0, B_, 1, ATTN_SCALE, 0);

        softmax_kernel<<<B_ * H_ * M_, 256>>>(S, N_);

        // ot[b,h,m,d] = P_b @ latent_b   (batched over b)
        gemm(false, S, latent, ot, nullptr,
             H_ * M_, D_, N_, N_, D_, D_,
             (long)H_ * M_ * N_, 0, LAT_B, 0, (long)H_ * M_ * D_, 0,
             0, B_, 1, 1.0f, 0);

        // Wf[h] = vw[l,h] @ hw[l,h]    (768x64 @ 64x64, batched over h)
        gemm(false, vw + (long)l * WL, hw + (long)l * H_ * HD_ * HD_, Wf, nullptr,
             D_, HD_, HD_, HD_, HD_, HD_,
             0, WHD, 0, (long)HD_ * HD_, 0, WHD, 0, 1, H_, 1.0f, 0);
        bias2_kernel<<<H_, 64>>>(vb + (long)l * H_ * HD_, hw + (long)l * H_ * HD_ * HD_,
                                 hb + (long)l * H_ * HD_, bi2);

        // o2[b,m,h*64+f] = ot[b,h,:,:] @ Wf[h] + bias2[h]  (batched over (b,h))
        gemm(false, ot, Wf, o2, bi2,
             M_, HD_, D_, D_, HD_, D_,
             (long)H_ * M_ * D_, WHD, 0, WHD, (long)M_ * D_, HD_,
             HD_, B_, H_, 1.0f, 0);

        // o3 = o2 @ ow[l] + ob[l]
        gemm(false, o2, ow + (long)l * D_ * D_, o3, ob + (long)l * D_,
             BM_, D_, D_, D_, D_, D_,
             0, 0, 0, 0, 0, 0, 0, 1, 1, 1.0f, 0);

        // x1 = LN(o3 + queries)
        add_ln_kernel<<<BM_, 256>>>(o3, qu, g1 + (long)l * D_, be1 + (long)l * D_, x1);

        // hid = gelu(x1 @ w1[l] + b1[l])
        gemm(false, x1, w1 + (long)l * D_ * DH_, hid, b1 + (long)l * DH_,
             BM_, DH_, D_, D_, DH_, DH_,
             0, 0, 0, 0, 0, 0, 0, 1, 1, 1.0f, 1);

        // mout = hid @ w2[l] + b2[l]
        gemm(false, hid, w2 + (long)l * DH_ * D_, mo, b2 + (long)l * D_,
             BM_, D_, DH_, DH_, D_, D_,
             0, 0, 0, 0, 0, 0, 0, 1, 1, 1.0f, 0);

        // x = LN(x1 + mout)  — final layer writes straight to d_out
        add_ln_kernel<<<BM_, 256>>>(x1, mo, g2 + (long)l * D_, be2 + (long)l * D_,
                                    (l == L_ - 1) ? out : x);
    }
}

// round 2
// speedup vs baseline: 1.5461x; 1.5461x over previous
#include <cuda_runtime.h>
#include <math.h>
#include <stdint.h>

// Problem constants
#define B_   8
#define N_   4096
#define D_   768
#define H_   12
#define M_   64
#define L_   4
#define HD_  64
#define BM_  (B_ * M_)      // 512
#define DH_  (4 * D_)       // 3072
#define ATTN_SCALE 0.125f   // 1/sqrt(64)

// ---------------------------------------------------------------------------
// Scratch (device globals — no cudaMalloc allowed)
// ---------------------------------------------------------------------------
__device__ float g_S[B_ * H_ * M_ * N_];     // attn logits/probs (also pooling logits)
__device__ float g_x[BM_ * D_];              // pooled / layer output
__device__ float g_queries[BM_ * D_];
__device__ float g_q2[BM_ * D_];             // [b][m][h*64+e]
__device__ float g_qt[B_ * H_ * M_ * D_];    // q-tilde [b][h][m][d]
__device__ float g_ot[B_ * H_ * M_ * D_];    // o-tilde [b][h][m][d]
__device__ float g_Wf[H_ * D_ * HD_];        // fused vw@hw per head
__device__ float g_bias2[H_ * HD_];          // vb@hw + hb
__device__ float g_o2[BM_ * D_];
__device__ float g_o3[BM_ * D_];
__device__ float g_x1[BM_ * D_];
__device__ float g_hid[BM_ * DH_];
__device__ float g_mout[BM_ * D_];

// ---------------------------------------------------------------------------
// tf32 helpers
// ---------------------------------------------------------------------------
__device__ __forceinline__ unsigned f2tf32(float x)
{
    unsigned r;
    asm("cvt.rna.tf32.f32 %0, %1;" : "=r"(r) : "f"(x));
    return r;
}
__device__ __forceinline__ uint4 cvt4(float4 v)
{
    uint4 u;
    u.x = f2tf32(v.x); u.y = f2tf32(v.y); u.z = f2tf32(v.z); u.w = f2tf32(v.w);
    return u;
}
__device__ __forceinline__ void mma_tf32(float c[4], const unsigned a[4], const unsigned b[2])
{
    asm volatile(
        "mma.sync.aligned.m16n8k8.row.col.f32.tf32.tf32.f32 "
        "{%0,%1,%2,%3}, {%4,%5,%6,%7}, {%8,%9}, {%0,%1,%2,%3};\n"
        : "+f"(c[0]), "+f"(c[1]), "+f"(c[2]), "+f"(c[3])
        : "r"(a[0]), "r"(a[1]), "r"(a[2]), "r"(a[3]), "r"(b[0]), "r"(b[1]));
}

// ---------------------------------------------------------------------------
// Tensor-core batched GEMM (tf32): C = alpha * A @ op(B) (+ bias) (+ gelu)
// CTA tile 128(M) x 256(N) x 16(K); 256 threads = 8 warps of 64x64;
// mma m16n8k8; double-buffered dynamic smem (60KB), pad-20 conflict-free layout.
// Requires K % 16 == 0. Row masking on A/C supported (M arbitrary).
// ---------------------------------------------------------------------------
#define TG_SMEM_BYTES ((2 * 128 * 20 + 2 * 256 * 20) * 4)

template <bool TRANSB>
__global__ __launch_bounds__(256)
void tgemm_kernel(const float* __restrict__ A, const float* __restrict__ Bm,
                  float* __restrict__ C, const float* __restrict__ bias,
                  int M, int N, int K, int lda, int ldb, int ldc,
                  long sAi, long sAj, long sBi, long sBj, long sCi, long sCj,
                  long sbj, int J, float alpha, int act)
{
    extern __shared__ unsigned sm_[];
    unsigned* As = sm_;              // [2][128][20]
    unsigned* Bs = sm_ + 2 * 128 * 20; // [2][256][20]

    int bz = blockIdx.z;
    int bi = bz / J, bj = bz - bi * J;
    A  += (size_t)bi * sAi + (size_t)bj * sAj;
    Bm += (size_t)bi * sBi + (size_t)bj * sBj;
    C  += (size_t)bi * sCi + (size_t)bj * sCj;
    if (bias) bias += (size_t)bj * sbj;

    const int tid = threadIdx.x;
    const int lane = tid & 31;
    const int g = lane >> 2, t = lane & 3;
    const int warp = tid >> 5;
    const int wm = (warp & 1) << 6;   // 0 / 64
    const int wn = (warp >> 1) << 6;  // 0..192
    const int row0 = blockIdx.y * 128;
    const int col0 = blockIdx.x * 256;

    // A loader mapping: thread -> (row, kchunk)
    const int a_r = tid >> 1;
    const int a_k = (tid & 1) << 2;   // 0 or 4; second float4 at +8
    // B NN loader mapping
    const int bn_k = tid & 15;
    const int bn_n = (tid >> 4) << 4;

    float acc[4][8][4];
#pragma unroll
    for (int i = 0; i < 4; i++)
#pragma unroll
        for (int j = 0; j < 8; j++)
#pragma unroll
            for (int v = 0; v < 4; v++) acc[i][j][v] = 0.f;

    float4 fa0, fa1;
    float4 fb[4];

    auto ldgA = [&](int k0) {
        int r = row0 + a_r;
        fa0 = make_float4(0.f, 0.f, 0.f, 0.f);
        fa1 = fa0;
        if (r < M) {
            const float* p = A + (size_t)r * lda + k0 + a_k;
            fa0 = *(const float4*)p;
            fa1 = *(const float4*)(p + 8);
        }
    };
    auto ldgB = [&](int k0) {
        if (TRANSB) {
            int n = col0 + tid;
            float4 z = make_float4(0.f, 0.f, 0.f, 0.f);
            fb[0] = fb[1] = fb[2] = fb[3] = z;
            if (n < N) {
                const float* p = Bm + (size_t)n * ldb + k0;
#pragma unroll
                for (int j = 0; j < 4; j++) fb[j] = *(const float4*)(p + 4 * j);
            }
        } else {
            const float* p = Bm + (size_t)(k0 + bn_k) * ldb + col0 + bn_n;
#pragma unroll
            for (int j = 0; j < 4; j++) {
                int n = col0 + bn_n + 4 * j;
                fb[j] = (n < N) ? *(const float4*)(p + 4 * j)
                                : make_float4(0.f, 0.f, 0.f, 0.f);
            }
        }
    };
    auto stsA = [&](int buf) {
        unsigned* d = As + buf * 2560 + a_r * 20 + a_k;
        *(uint4*)d = cvt4(fa0);
        *(uint4*)(d + 8) = cvt4(fa1);
    };
    auto stsB = [&](int buf) {
        if (TRANSB) {
            unsigned* d = Bs + buf * 5120 + tid * 20;
#pragma unroll
            for (int j = 0; j < 4; j++) *(uint4*)(d + 4 * j) = cvt4(fb[j]);
        } else {
            unsigned* d = Bs + buf * 5120;
#pragma unroll
            for (int j = 0; j < 4; j++) {
                int nb = bn_n + 4 * j;
                d[(nb + 0) * 20 + bn_k] = f2tf32(fb[j].x);
                d[(nb + 1) * 20 + bn_k] = f2tf32(fb[j].y);
                d[(nb + 2) * 20 + bn_k] = f2tf32(fb[j].z);
                d[(nb + 3) * 20 + bn_k] = f2tf32(fb[j].w);
            }
        }
    };
    auto compute = [&](int buf) {
        const unsigned* Ab = As + buf * 2560;
        const unsigned* Bb = Bs + buf * 5120;
#pragma unroll
        for (int ks = 0; ks < 16; ks += 8) {
            unsigned af[4][4];
#pragma unroll
            for (int mt = 0; mt < 4; mt++) {
                int r = wm + mt * 16 + g;
                af[mt][0] = Ab[r * 20 + ks + t];
                af[mt][1] = Ab[(r + 8) * 20 + ks + t];
                af[mt][2] = Ab[r * 20 + ks + t + 4];
                af[mt][3] = Ab[(r + 8) * 20 + ks + t + 4];
            }
            unsigned bf[8][2];
#pragma unroll
            for (int nt = 0; nt < 8; nt++) {
                int c = wn + nt * 8 + g;
                bf[nt][0] = Bb[c * 20 + ks + t];
                bf[nt][1] = Bb[c * 20 + ks + t + 4];
            }
#pragma unroll
            for (int mt = 0; mt < 4; mt++)
#pragma unroll
                for (int nt = 0; nt < 8; nt++)
                    mma_tf32(acc[mt][nt], af[mt], bf[nt]);
        }
    };

    ldgA(0); ldgB(0);
    stsA(0); stsB(0);
    __syncthreads();
    int buf = 0;
    for (int k0 = 0; k0 < K; k0 += 16) {
        bool more = (k0 + 16) < K;
        if (more) { ldgA(k0 + 16); ldgB(k0 + 16); }
        compute(buf);
        if (more) {
            stsA(buf ^ 1); stsB(buf ^ 1);
            __syncthreads();
            buf ^= 1;
        }
    }

    // Epilogue
#pragma unroll
    for (int mt = 0; mt < 4; mt++) {
#pragma unroll
        for (int v = 0; v < 2; v++) {
            int r = row0 + wm + mt * 16 + g + v * 8;
            if (r >= M) continue;
#pragma unroll
            for (int nt = 0; nt < 8; nt++) {
                int c = col0 + wn + nt * 8 + 2 * t;
                if (c >= N) continue;
                float v0 = acc[mt][nt][v * 2 + 0] * alpha;
                float v1 = acc[mt][nt][v * 2 + 1] * alpha;
                if (bias) { v0 += bias[c]; v1 += bias[c + 1]; }
                if (act == 1) {
                    v0 = 0.5f * v0 * (1.f + erff(v0 * 0.7071067811865475f));
                    v1 = 0.5f * v1 * (1.f + erff(v1 * 0.7071067811865475f));
                }
                float2 o = make_float2(v0, v1);
                *(float2*)&C[(size_t)r * ldc + c] = o;
            }
        }
    }
}

// ---------------------------------------------------------------------------
// fp32 SGEMM (kept for the small per-head GEMMs): identical to round 1
// ---------------------------------------------------------------------------
template <bool TRANSB>
__global__ __launch_bounds__(256, 2)
void sgemm_kernel(const float* __restrict__ A, const float* __restrict__ Bm,
                  float* __restrict__ C, const float* __restrict__ bias,
                  int M, int N, int K, int lda, int ldb, int ldc,
                  long sAi, long sAj, long sBi, long sBj, long sCi, long sCj,
                  long sbj, int J, float alpha, int act)
{
    const int BK = 8;
    int bz = blockIdx.z;
    int bi = bz / J, bj = bz - bi * J;
    A  += (size_t)bi * sAi + (size_t)bj * sAj;
    Bm += (size_t)bi * sBi + (size_t)bj * sBj;
    C  += (size_t)bi * sCi + (size_t)bj * sCj;
    if (bias) bias += (size_t)bj * sbj;

    __shared__ __align__(16) float As[2][BK][128];
    __shared__ __align__(16) float Bs[2][BK][128];

    int tid = threadIdx.x;
    int tx = tid & 15, ty = tid >> 4;
    int row0 = blockIdx.y * 128;
    int col0 = blockIdx.x * 128;

    int arow = tid >> 1;
    int acol = (tid & 1) << 2;
    int bk   = tid >> 5;
    int bn   = (tid & 31) << 2;

    float acc[8][8];
#pragma unroll
    for (int i = 0; i < 8; i++)
#pragma unroll
        for (int j = 0; j < 8; j++) acc[i][j] = 0.f;

    auto loadA = [&](int buf, int k0) {
        int r = row0 + arow;
        float4 v = make_float4(0.f, 0.f, 0.f, 0.f);
        if (r < M) v = *(const float4*)(A + (size_t)r * lda + k0 + acol);
        As[buf][acol + 0][arow] = v.x;
        As[buf][acol + 1][arow] = v.y;
        As[buf][acol + 2][arow] = v.z;
        As[buf][acol + 3][arow] = v.w;
    };
    auto loadB = [&](int buf, int k0) {
        if (TRANSB) {
            int n = col0 + arow;
            float4 v = make_float4(0.f, 0.f, 0.f, 0.f);
            if (n < N) v = *(const float4*)(Bm + (size_t)n * ldb + k0 + acol);
            Bs[buf][acol + 0][arow] = v.x;
            Bs[buf][acol + 1][arow] = v.y;
            Bs[buf][acol + 2][arow] = v.z;
            Bs[buf][acol + 3][arow] = v.w;
        } else {
            int n = col0 + bn;
            float4 v = make_float4(0.f, 0.f, 0.f, 0.f);
            if (n < N) v = *(const float4*)(Bm + (size_t)(k0 + bk) * ldb + n);
            *(float4*)&Bs[buf][bk][bn] = v;
        }
    };

    loadA(0, 0);
    loadB(0, 0);
    __syncthreads();
    int buf = 0;
    for (int k0 = 0; k0 < K; k0 += BK) {
        if (k0 + BK < K) { loadA(buf ^ 1, k0 + BK); loadB(buf ^ 1, k0 + BK); }
#pragma unroll
        for (int kk = 0; kk < BK; kk++) {
            float4 a0 = *(const float4*)&As[buf][kk][ty * 4];
            float4 a1 = *(const float4*)&As[buf][kk][ty * 4 + 64];
            float4 b0 = *(const float4*)&Bs[buf][kk][tx * 4];
            float4 b1 = *(const float4*)&Bs[buf][kk][tx * 4 + 64];
            float ar[8] = {a0.x, a0.y, a0.z, a0.w, a1.x, a1.y, a1.z, a1.w};
            float br[8] = {b0.x, b0.y, b0.z, b0.w, b1.x, b1.y, b1.z, b1.w};
#pragma unroll
            for (int i = 0; i < 8; i++)
#pragma unroll
                for (int j = 0; j < 8; j++) acc[i][j] += ar[i] * br[j];
        }
        buf ^= 1;
        __syncthreads();
    }

#pragma unroll
    for (int i = 0; i < 8; i++) {
        int r = row0 + ty * 4 + (i >> 2) * 64 + (i & 3);
        if (r >= M) continue;
#pragma unroll
        for (int j = 0; j < 8; j++) {
            int c = col0 + tx * 4 + (j >> 2) * 64 + (j & 3);
            if (c >= N) continue;
            float v = acc[i][j] * alpha;
            if (bias) v += bias[c];
            if (act == 1) v = 0.5f * v * (1.f + erff(v * 0.7071067811865475f));
            C[(size_t)r * ldc + c] = v;
        }
    }
}

// ---------------------------------------------------------------------------
// Register-resident softmax for ncols == 4096 (one read + one write)
// ---------------------------------------------------------------------------
__global__ __launch_bounds__(256)
void softmax4096_kernel(float* __restrict__ X)
{
    float* row = X + (size_t)blockIdx.x * 4096;
    int tid = threadIdx.x;
    float4 v[4];
#pragma unroll
    for (int j = 0; j < 4; j++) v[j] = *(float4*)(row + tid * 16 + 4 * j);

    float m = -1e30f;
#pragma unroll
    for (int j = 0; j < 4; j++) {
        m = fmaxf(m, fmaxf(fmaxf(v[j].x, v[j].y), fmaxf(v[j].z, v[j].w)));
    }
    __shared__ float red[8];
#pragma unroll
    for (int s = 16; s > 0; s >>= 1) m = fmaxf(m, __shfl_xor_sync(0xffffffffu, m, s));
    if ((tid & 31) == 0) red[tid >> 5] = m;
    __syncthreads();
    m = red[0];
#pragma unroll
    for (int w = 1; w < 8; w++) m = fmaxf(m, red[w]);

    float sum = 0.f;
#pragma unroll
    for (int j = 0; j < 4; j++) {
        v[j].x = __expf(v[j].x - m); sum += v[j].x;
        v[j].y = __expf(v[j].y - m); sum += v[j].y;
        v[j].z = __expf(v[j].z - m); sum += v[j].z;
        v[j].w = __expf(v[j].w - m); sum += v[j].w;
    }
#pragma unroll
    for (int s = 16; s > 0; s >>= 1) sum += __shfl_xor_sync(0xffffffffu, sum, s);
    __syncthreads();
    if ((tid & 31) == 0) red[tid >> 5] = sum;
    __syncthreads();
    sum = 0.f;
#pragma unroll
    for (int w = 0; w < 8; w++) sum += red[w];
    float inv = 1.f / sum;
#pragma unroll
    for (int j = 0; j < 4; j++) {
        v[j].x *= inv; v[j].y *= inv; v[j].z *= inv; v[j].w *= inv;
        *(float4*)(row + tid * 16 + 4 * j) = v[j];
    }
}

// ---------------------------------------------------------------------------
// out[r,:] = LayerNorm(a[r,:] + b[r,:]) * g + beta   (row length = 768)
// ---------------------------------------------------------------------------
__global__ void add_ln_kernel(const float* __restrict__ Xa, const float* __restrict__ Xb,
                              const float* __restrict__ g, const float* __restrict__ beta,
                              float* __restrict__ out)
{
    int r = blockIdx.x;
    const float* a = Xa + (size_t)r * D_;
    const float* b = Xb + (size_t)r * D_;
    float* o = out + (size_t)r * D_;
    __shared__ float red[256];
    int tid = threadIdx.x;
    float v[3];
    float s = 0.f;
#pragma unroll
    for (int i = 0; i < 3; i++) { int c = tid + i * 256; v[i] = a[c] + b[c]; s += v[i]; }
    red[tid] = s; __syncthreads();
    for (int st = 128; st > 0; st >>= 1) {
        if (tid < st) red[tid] += red[tid + st];
        __syncthreads();
    }
    float mean = red[0] * (1.f / D_);
    __syncthreads();
    s = 0.f;
#pragma unroll
    for (int i = 0; i < 3; i++) { float d = v[i] - mean; s += d * d; }
    red[tid] = s; __syncthreads();
    for (int st = 128; st > 0; st >>= 1) {
        if (tid < st) red[tid] += red[tid + st];
        __syncthreads();
    }
    float rstd = rsqrtf(red[0] * (1.f / D_) + 1e-5f);
#pragma unroll
    for (int i = 0; i < 3; i++) {
        int c = tid + i * 256;
        o[c] = (v[i] - mean) * rstd * g[c] + beta[c];
    }
}

// queries[b,m,d] = x[b,m,d] + qc[m,d]
__global__ void make_queries_kernel(const float* __restrict__ x, const float* __restrict__ qc,
                                    float* __restrict__ q)
{
    int i = blockIdx.x * 256 + threadIdx.x;
    int d = i % D_;
    int m = (i / D_) & (M_ - 1);
    q[i] = x[i] + qc[m * D_ + d];
}

// bias2[h,f] = sum_e vb[h,e]*hw[h,e,f] + hb[h,f]
__global__ void bias2_kernel(const float* __restrict__ vb, const float* __restrict__ hw,
                             const float* __restrict__ hb, float* __restrict__ out)
{
    int idx = blockIdx.x * 64 + threadIdx.x;
    int h = idx >> 6, f = idx & 63;
    const float* vbh = vb + h * 64;
    const float* hwh = hw + h * 4096;
    float s = hb[idx];
#pragma unroll 8
    for (int e = 0; e < 64; e++) s += vbh[e] * hwh[e * 64 + f];
    out[idx] = s;
}

// ---------------------------------------------------------------------------
// Host side
// ---------------------------------------------------------------------------
static void gemm(bool transB, const float* A, const float* B, float* C, const float* bias,
                 int M, int N, int K, int lda, int ldb, int ldc,
                 long sAi, long sAj, long sBi, long sBj, long sCi, long sCj,
                 long sbj, int I, int J, float alpha, int act)
{
    dim3 grid((N + 127) / 128, (M + 127) / 128, I * J);
    if (transB)
        sgemm_kernel<true><<<grid, 256>>>(A, B, C, bias, M, N, K, lda, ldb, ldc,
                                          sAi, sAj, sBi, sBj, sCi, sCj, sbj, J, alpha, act);
    else
        sgemm_kernel<false><<<grid, 256>>>(A, B, C, bias, M, N, K, lda, ldb, ldc,
                                           sAi, sAj, sBi, sBj, sCi, sCj, sbj, J, alpha, act);
}

static void tgemm(bool transB, const float* A, const float* B, float* C, const float* bias,
                  int M, int N, int K, int lda, int ldb, int ldc,
                  long sAi, long sAj, long sBi, long sBj, long sCi, long sCj,
                  long sbj, int I, int J, float alpha, int act)
{
    dim3 grid((N + 255) / 256, (M + 127) / 128, I * J);
    if (transB)
        tgemm_kernel<true><<<grid, 256, TG_SMEM_BYTES>>>(A, B, C, bias, M, N, K, lda, ldb, ldc,
                                                         sAi, sAj, sBi, sBj, sCi, sCj, sbj, J, alpha, act);
    else
        tgemm_kernel<false><<<grid, 256, TG_SMEM_BYTES>>>(A, B, C, bias, M, N, K, lda, ldb, ldc,
                                                          sAi, sAj, sBi, sBj, sCi, sCj, sbj, J, alpha, act);
}

template <typename T>
static T* sym(const void* symbol)
{
    void* p = nullptr;
    cudaGetSymbolAddress(&p, symbol);
    return (T*)p;
}

extern "C" void kernel_launch(void* const* d_in, const int* in_sizes, int n_in,
                              void* d_out, int out_size)
{
    cudaFuncSetAttribute(tgemm_kernel<true>, cudaFuncAttributeMaxDynamicSharedMemorySize, TG_SMEM_BYTES);
    cudaFuncSetAttribute(tgemm_kernel<false>, cudaFuncAttributeMaxDynamicSharedMemorySize, TG_SMEM_BYTES);

    const float* latent = (const float*)d_in[0];   // [8,4096,768]
    const float* selector = (const float*)d_in[1]; // [64,768]
    const float* qc = (const float*)d_in[2];       // [4,64,768]
    const float* qw = (const float*)d_in[3];       // [4,12,768,64]
    const float* qb = (const float*)d_in[4];       // [4,12,64]
    const float* kw = (const float*)d_in[5];       // [4,12,768,64]
    // kb (d_in[6]) cancels exactly in softmax
    const float* vw = (const float*)d_in[7];       // [4,12,768,64]
    const float* vb = (const float*)d_in[8];       // [4,12,64]
    const float* hw = (const float*)d_in[9];       // [4,12,64,64]
    const float* hb = (const float*)d_in[10];      // [4,12,64]
    const float* ow = (const float*)d_in[11];      // [4,768,768]
    const float* ob = (const float*)d_in[12];      // [4,768]
    const float* w1 = (const float*)d_in[13];      // [4,768,3072]
    const float* b1 = (const float*)d_in[14];      // [4,3072]
    const float* w2 = (const float*)d_in[15];      // [4,3072,768]
    const float* b2 = (const float*)d_in[16];      // [4,768]
    const float* g1 = (const float*)d_in[17];      // [4,768]
    const float* be1 = (const float*)d_in[18];     // [4,768]
    const float* g2 = (const float*)d_in[19];      // [4,768]
    const float* be2 = (const float*)d_in[20];     // [4,768]

    float* S   = sym<float>(g_S);
    float* x   = sym<float>(g_x);
    float* qu  = sym<float>(g_queries);
    float* q2  = sym<float>(g_q2);
    float* qt  = sym<float>(g_qt);
    float* ot  = sym<float>(g_ot);
    float* Wf  = sym<float>(g_Wf);
    float* bi2 = sym<float>(g_bias2);
    float* o2  = sym<float>(g_o2);
    float* o3  = sym<float>(g_o3);
    float* x1  = sym<float>(g_x1);
    float* hid = sym<float>(g_hid);
    float* mo  = sym<float>(g_mout);
    float* out = (float*)d_out;

    const long LAT_B = (long)N_ * D_;
    const long WHD   = (long)D_ * HD_;
    const long WL    = (long)H_ * WHD;

    // ---- Stage 0: soft-selection pooling ----
    tgemm(true, selector, latent, S, nullptr,
          M_, N_, D_, D_, D_, N_,
          0, 0, LAT_B, 0, (long)M_ * N_, 0, 0, B_, 1, 1.0f, 0);
    softmax4096_kernel<<<B_ * M_, 256>>>(S);
    tgemm(false, S, latent, x, nullptr,
          M_, D_, N_, N_, D_, D_,
          (long)M_ * N_, 0, LAT_B, 0, (long)M_ * D_, 0, 0, B_, 1, 1.0f, 0);

    // ---- L transformer layers ----
    for (int l = 0; l < L_; l++) {
        make_queries_kernel<<<(BM_ * D_) / 256, 256>>>(x, qc + (long)l * M_ * D_, qu);

        // q2 = queries @ qw + qb   (fp32, batched over h)
        gemm(false, qu, qw + (long)l * WL, q2, qb + (long)l * H_ * HD_,
             BM_, HD_, D_, D_, HD_, D_,
             0, 0, 0, WHD, 0, HD_, HD_, 1, H_, 1.0f, 0);

        // qt = q2 @ kw^T   (fp32, batched over (b,h))
        gemm(true, q2, kw + (long)l * WL, qt, nullptr,
             M_, D_, HD_, D_, HD_, D_,
             (long)M_ * D_, HD_, 0, WHD, (long)H_ * M_ * D_, (long)M_ * D_,
             0, B_, H_, 1.0f, 0);

        // S = scale * qt @ latent^T   (tf32 tensor, batched over b)
        tgemm(true, qt, latent, S, nullptr,
              H_ * M_, N_, D_, D_, D_, N_,
              (long)H_ * M_ * D_, 0, LAT_B, 0, (long)H_ * M_ * N_, 0,
              0, B_, 1, ATTN_SCALE, 0);

        softmax4096_kernel<<<B_ * H_ * M_, 256>>>(S);

        // ot = P @ latent   (tf32 tensor, batched over b)
        tgemm(false, S, latent, ot, nullptr,
              H_ * M_, D_, N_, N_, D_, D_,
              (long)H_ * M_ * N_, 0, LAT_B, 0, (long)H_ * M_ * D_, 0,
              0, B_, 1, 1.0f, 0);

        // Wf[h] = vw[l,h] @ hw[l,h]   (fp32, batched over h)
        gemm(false, vw + (long)l * WL, hw + (long)l * H_ * HD_ * HD_, Wf, nullptr,
             D_, HD_, HD_, HD_, HD_, HD_,
             0, WHD, 0, (long)HD_ * HD_, 0, WHD, 0, 1, H_, 1.0f, 0);
        bias2_kernel<<<H_, 64>>>(vb + (long)l * H_ * HD_, hw + (long)l * H_ * HD_ * HD_,
                                 hb + (long)l * H_ * HD_, bi2);

        // o2 = ot @ Wf + bias2   (fp32, batched over (b,h))
        gemm(false, ot, Wf, o2, bi2,
             M_, HD_, D_, D_, HD_, D_,
             (long)H_ * M_ * D_, WHD, 0, WHD, (long)M_ * D_, HD_,
             HD_, B_, H_, 1.0f, 0);

        // o3 = o2 @ ow + ob   (tf32 tensor)
        tgemm(false, o2, ow + (long)l * D_ * D_, o3, ob + (long)l * D_,
              BM_, D_, D_, D_, D_, D_,
              0, 0, 0, 0, 0, 0, 0, 1, 1, 1.0f, 0);

        // x1 = LN(o3 + queries)
        add_ln_kernel<<<BM_, 256>>>(o3, qu, g1 + (long)l * D_, be1 + (long)l * D_, x1);

        // hid = gelu(x1 @ w1 + b1)   (tf32 tensor)
        tgemm(false, x1, w1 + (long)l * D_ * DH_, hid, b1 + (long)l * DH_,
              BM_, DH_, D_, D_, DH_, DH_,
              0, 0, 0, 0, 0, 0, 0, 1, 1, 1.0f, 1);

        // mout = hid @ w2 + b2   (tf32 tensor)
        tgemm(false, hid, w2 + (long)l * DH_ * D_, mo, b2 + (long)l * D_,
              BM_, D_, DH_, DH_, D_, D_,
              0, 0, 0, 0, 0, 0, 0, 1, 1, 1.0f, 0);

        // x = LN(x1 + mout)
        add_ln_kernel<<<BM_, 256>>>(x1, mo, g2 + (long)l * D_, be2 + (long)l * D_,
                                    (l == L_ - 1) ? out : x);
    }
}

// round 3
// speedup vs baseline: 3.2135x; 2.0785x over previous
#include <cuda_runtime.h>
#include <math.h>
#include <stdint.h>

// Problem constants
#define B_   8
#define N_   4096
#define D_   768
#define H_   12
#define M_   64
#define L_   4
#define HD_  64
#define BM_  (B_ * M_)      // 512
#define DH_  (4 * D_)       // 3072
#define ATTN_SCALE 0.125f

// ---------------------------------------------------------------------------
// Scratch (device globals)
// ---------------------------------------------------------------------------
__device__ float g_S[B_ * H_ * M_ * N_];
__device__ float g_x[BM_ * D_];
__device__ float g_queries[BM_ * D_];
__device__ float g_q2[BM_ * D_];
__device__ float g_qt[B_ * H_ * M_ * D_];
__device__ float g_ot[B_ * H_ * M_ * D_];
__device__ float g_Wf[H_ * D_ * HD_];
__device__ float g_bias2[H_ * HD_];
__device__ float g_o3[BM_ * D_];
__device__ float g_x1[BM_ * D_];
__device__ float g_hid[BM_ * DH_];
__device__ float g_mout[BM_ * D_];
__device__ float g_Wq[L_ * D_ * D_];         // transposed qw: [l][d][h*64+e]
__device__ float g_part[8 * BM_ * D_];       // split-K partials (max 8 chunks)
__device__ float g_px[4 * B_ * M_ * D_];     // pooling split-K partials

// ---------------------------------------------------------------------------
// helpers
// ---------------------------------------------------------------------------
__device__ __forceinline__ unsigned f2tf32(float x)
{
    unsigned r;
    asm("cvt.rna.tf32.f32 %0, %1;" : "=r"(r) : "f"(x));
    return r;
}
__device__ __forceinline__ void mma_tf32(float c[4], const unsigned a[4], const unsigned b[2])
{
    asm volatile(
        "mma.sync.aligned.m16n8k8.row.col.f32.tf32.tf32.f32 "
        "{%0,%1,%2,%3}, {%4,%5,%6,%7}, {%8,%9}, {%0,%1,%2,%3};\n"
        : "+f"(c[0]), "+f"(c[1]), "+f"(c[2]), "+f"(c[3])
        : "r"(a[0]), "r"(a[1]), "r"(a[2]), "r"(a[3]), "r"(b[0]), "r"(b[1]));
}
__device__ __forceinline__ uint32_t smem_u32(const void* p)
{
    return (uint32_t)__cvta_generic_to_shared(p);
}
__device__ __forceinline__ void cpasync16(uint32_t dst, const void* src, int sz)
{
    asm volatile("cp.async.cg.shared.global [%0], [%1], 16, %2;\n"
                 :: "r"(dst), "l"(src), "r"(sz));
}
__device__ __forceinline__ void cp_commit()
{
    asm volatile("cp.async.commit_group;\n");
}
__device__ __forceinline__ void cp_wait2()
{
    asm volatile("cp.async.wait_group 2;\n");
}

// ---------------------------------------------------------------------------
// tgemm v3: tf32 tensor GEMM, 128x128x16 tile, 4-stage cp.async pipeline.
// 256 threads = 8 warps, warp tile 32x64 (2 mt x 8 nt of m16n8k8).
// A smem: [stage][128][20] (m-major rows of k16). TRANSB B same layout (n rows).
// NN B smem: [stage][16][136] (k rows of n128). Requires K%16==0, N%128==0
// (all call sites satisfy), M arbitrary (row guard).
// ---------------------------------------------------------------------------
#define TG_STAGES 4
#define TG_SMEM_T ((TG_STAGES * 128 * 20 * 2) * 4)                 // 81920
#define TG_SMEM_N ((TG_STAGES * 128 * 20 + TG_STAGES * 16 * 136) * 4) // 75776

template <bool TRANSB>
__global__ __launch_bounds__(256, 2)
void tgemm_kernel(const float* __restrict__ A, const float* __restrict__ Bm,
                  float* __restrict__ C, const float* __restrict__ bias,
                  int M, int N, int K, int lda, int ldb, int ldc,
                  long sAi, long sAj, long sBi, long sBj, long sCi, long sCj,
                  long sbj, int J, float alpha, int act)
{
    extern __shared__ float sm[];
    float* As = sm;                              // [4][128][20]
    float* Bs = sm + TG_STAGES * 128 * 20;       // T: [4][128][20]  N: [4][16][136]

    int bz = blockIdx.z;
    int bi = bz / J, bj = bz - bi * J;
    A  += (size_t)bi * sAi + (size_t)bj * sAj;
    Bm += (size_t)bi * sBi + (size_t)bj * sBj;
    C  += (size_t)bi * sCi + (size_t)bj * sCj;
    if (bias) bias += (size_t)bj * sbj;

    const int tid = threadIdx.x;
    const int lane = tid & 31;
    const int g = lane >> 2, t = lane & 3;
    const int warp = tid >> 5;
    const int wm = (warp & 3) * 32;
    const int wn = (warp >> 2) * 64;
    const int row0 = blockIdx.y * 128;
    const int col0 = blockIdx.x * 128;

    const uint32_t sA = smem_u32(As);
    const uint32_t sB = smem_u32(Bs);

    // loader mapping
    const int l_r  = tid >> 1;
    const int l_kc = (tid & 1) * 8;
    const int lb_k = tid >> 4;          // NN
    const int lb_n = (tid & 15) * 8;    // NN

    float acc[2][8][4];
#pragma unroll
    for (int i = 0; i < 2; i++)
#pragma unroll
        for (int j = 0; j < 8; j++)
#pragma unroll
            for (int v = 0; v < 4; v++) acc[i][j][v] = 0.f;

    auto issue = [&](int s, int k0) {
        // A tile
        {
            int r = row0 + l_r;
            bool ok = (r < M);
            const float* ga = ok ? (A + (size_t)r * lda + k0 + l_kc) : A;
            int sz = ok ? 16 : 0;
            uint32_t da = sA + (uint32_t)((s * 128 * 20 + l_r * 20 + l_kc) * 4);
            cpasync16(da, ga, sz);
            cpasync16(da + 16, ga + 4, sz);
        }
        if (TRANSB) {
            int n = col0 + l_r;
            bool ok = (n < N);
            const float* gb = ok ? (Bm + (size_t)n * ldb + k0 + l_kc) : Bm;
            int sz = ok ? 16 : 0;
            uint32_t db = sB + (uint32_t)((s * 128 * 20 + l_r * 20 + l_kc) * 4);
            cpasync16(db, gb, sz);
            cpasync16(db + 16, gb + 4, sz);
        } else {
            const float* gb = Bm + (size_t)(k0 + lb_k) * ldb + col0 + lb_n;
            uint32_t db = sB + (uint32_t)((s * 16 * 136 + lb_k * 136 + lb_n) * 4);
            cpasync16(db, gb, 16);
            cpasync16(db + 16, gb + 4, 16);
        }
    };

    auto compute = [&](int buf) {
        const float* Ab = As + buf * (128 * 20);
        const float* Bb = Bs + buf * (TRANSB ? 128 * 20 : 16 * 136);
#pragma unroll
        for (int ks = 0; ks < 16; ks += 8) {
            unsigned af[2][4];
#pragma unroll
            for (int mt = 0; mt < 2; mt++) {
                int r = wm + mt * 16 + g;
                af[mt][0] = f2tf32(Ab[r * 20 + ks + t]);
                af[mt][1] = f2tf32(Ab[(r + 8) * 20 + ks + t]);
                af[mt][2] = f2tf32(Ab[r * 20 + ks + t + 4]);
                af[mt][3] = f2tf32(Ab[(r + 8) * 20 + ks + t + 4]);
            }
            unsigned bf[8][2];
#pragma unroll
            for (int nt = 0; nt < 8; nt++) {
                int c = wn + nt * 8 + g;
                if (TRANSB) {
                    bf[nt][0] = f2tf32(Bb[c * 20 + ks + t]);
                    bf[nt][1] = f2tf32(Bb[c * 20 + ks + t + 4]);
                } else {
                    bf[nt][0] = f2tf32(Bb[(ks + t) * 136 + c]);
                    bf[nt][1] = f2tf32(Bb[(ks + t + 4) * 136 + c]);
                }
            }
#pragma unroll
            for (int mt = 0; mt < 2; mt++)
#pragma unroll
                for (int nt = 0; nt < 8; nt++)
                    mma_tf32(acc[mt][nt], af[mt], bf[nt]);
        }
    };

    const int KT = K >> 4;
    // prologue: stages 0..2
#pragma unroll
    for (int s = 0; s < TG_STAGES - 1; s++) {
        if (s < KT) issue(s, s * 16);
        cp_commit();
    }

    for (int kt = 0; kt < KT; kt++) {
        cp_wait2();
        __syncthreads();
        compute(kt & 3);
        int ns = kt + TG_STAGES - 1;
        if (ns < KT) issue(ns & 3, ns * 16);
        cp_commit();
    }

    // Epilogue
#pragma unroll
    for (int mt = 0; mt < 2; mt++) {
#pragma unroll
        for (int v = 0; v < 2; v++) {
            int r = row0 + wm + mt * 16 + g + v * 8;
            if (r >= M) continue;
#pragma unroll
            for (int nt = 0; nt < 8; nt++) {
                int c = col0 + wn + nt * 8 + 2 * t;
                float v0 = acc[mt][nt][v * 2 + 0] * alpha;
                float v1 = acc[mt][nt][v * 2 + 1] * alpha;
                if (bias) { v0 += bias[c]; v1 += bias[c + 1]; }
                if (act == 1) {
                    v0 = 0.5f * v0 * (1.f + erff(v0 * 0.7071067811865475f));
                    v1 = 0.5f * v1 * (1.f + erff(v1 * 0.7071067811865475f));
                }
                *(float2*)&C[(size_t)r * ldc + c] = make_float2(v0, v1);
            }
        }
    }
}

// ---------------------------------------------------------------------------
// sgemm64: fp32 GEMM for small shapes. 64x64 tile, 128 threads, BK=16.
// Requires M%64==0, N%64==0, K%16==0 (all call sites exact).
// ---------------------------------------------------------------------------
template <bool TRANSB>
__global__ __launch_bounds__(128)
void sgemm64_kernel(const float* __restrict__ A, const float* __restrict__ Bm,
                    float* __restrict__ C, const float* __restrict__ bias,
                    int K, int lda, int ldb, int ldc,
                    long sAi, long sAj, long sBi, long sBj, long sCi, long sCj,
                    long sbj, int J, float alpha)
{
    __shared__ float As[2][16][68];
    __shared__ float Bs[2][16][68];

    int bz = blockIdx.z;
    int bi = bz / J, bj = bz - bi * J;
    A  += (size_t)bi * sAi + (size_t)bj * sAj;
    Bm += (size_t)bi * sBi + (size_t)bj * sBj;
    C  += (size_t)bi * sCi + (size_t)bj * sCj;
    if (bias) bias += (size_t)bj * sbj;

    const int tid = threadIdx.x;
    const int row_t = tid & 15;     // rows row_t*4..+3
    const int col_t = tid >> 4;     // cols col_t*8..+7
    const int row0 = blockIdx.y * 64;
    const int col0 = blockIdx.x * 64;

    const int l_r  = tid >> 1;
    const int l_kc = (tid & 1) * 8;
    const int lb_k = tid >> 3;          // NN: 0..15
    const int lb_n = (tid & 7) * 8;     // NN

    float acc[4][8];
#pragma unroll
    for (int i = 0; i < 4; i++)
#pragma unroll
        for (int j = 0; j < 8; j++) acc[i][j] = 0.f;

    auto load = [&](int buf, int k0) {
        // A: [m][k] gmem -> As[k][m] transpose
        {
            const float* p = A + (size_t)(row0 + l_r) * lda + k0 + l_kc;
            float4 v0 = *(const float4*)p;
            float4 v1 = *(const float4*)(p + 4);
            As[buf][l_kc + 0][l_r] = v0.x; As[buf][l_kc + 1][l_r] = v0.y;
            As[buf][l_kc + 2][l_r] = v0.z; As[buf][l_kc + 3][l_r] = v0.w;
            As[buf][l_kc + 4][l_r] = v1.x; As[buf][l_kc + 5][l_r] = v1.y;
            As[buf][l_kc + 6][l_r] = v1.z; As[buf][l_kc + 7][l_r] = v1.w;
        }
        if (TRANSB) {
            const float* p = Bm + (size_t)(col0 + l_r) * ldb + k0 + l_kc;
            float4 v0 = *(const float4*)p;
            float4 v1 = *(const float4*)(p + 4);
            Bs[buf][l_kc + 0][l_r] = v0.x; Bs[buf][l_kc + 1][l_r] = v0.y;
            Bs[buf][l_kc + 2][l_r] = v0.z; Bs[buf][l_kc + 3][l_r] = v0.w;
            Bs[buf][l_kc + 4][l_r] = v1.x; Bs[buf][l_kc + 5][l_r] = v1.y;
            Bs[buf][l_kc + 6][l_r] = v1.z; Bs[buf][l_kc + 7][l_r] = v1.w;
        } else {
            const float* p = Bm + (size_t)(k0 + lb_k) * ldb + col0 + lb_n;
            *(float4*)&Bs[buf][lb_k][lb_n] = *(const float4*)p;
            *(float4*)&Bs[buf][lb_k][lb_n + 4] = *(const float4*)(p + 4);
        }
    };

    load(0, 0);
    __syncthreads();
    int buf = 0;
    for (int k0 = 0; k0 < K; k0 += 16) {
        if (k0 + 16 < K) load(buf ^ 1, k0 + 16);
#pragma unroll
        for (int kk = 0; kk < 16; kk++) {
            float4 a = *(const float4*)&As[buf][kk][row_t * 4];
            float4 b0 = *(const float4*)&Bs[buf][kk][col_t * 8];
            float4 b1 = *(const float4*)&Bs[buf][kk][col_t * 8 + 4];
            float ar[4] = {a.x, a.y, a.z, a.w};
            float br[8] = {b0.x, b0.y, b0.z, b0.w, b1.x, b1.y, b1.z, b1.w};
#pragma unroll
            for (int i = 0; i < 4; i++)
#pragma unroll
                for (int j = 0; j < 8; j++) acc[i][j] += ar[i] * br[j];
        }
        buf ^= 1;
        __syncthreads();
    }

#pragma unroll
    for (int i = 0; i < 4; i++) {
        int r = row0 + row_t * 4 + i;
#pragma unroll
        for (int j = 0; j < 8; j++) {
            int c = col0 + col_t * 8 + j;
            float v = acc[i][j] * alpha;
            if (bias) v += bias[c];
            C[(size_t)r * ldc + c] = v;
        }
    }
}

// ---------------------------------------------------------------------------
// split-K reduce: out[i] = sum_c part[i + c*cs] (+ bias[i % nb])
// ---------------------------------------------------------------------------
__global__ void reduce_kernel(const float* __restrict__ part, const float* __restrict__ bias,
                              float* __restrict__ out, int total, int C, long cs, int nb)
{
    int i = blockIdx.x * 256 + threadIdx.x;
    if (i >= total) return;
    float s = 0.f;
    for (int c = 0; c < C; c++) s += part[i + (size_t)c * cs];
    if (bias) s += bias[i % nb];
    out[i] = s;
}

// qw[l][h][d][e] -> Wq[l][d][h*64+e]
__global__ void qwT_kernel(const float* __restrict__ qw, float* __restrict__ Wq)
{
    int idx = blockIdx.x * 256 + threadIdx.x;   // L*H*D*HD = 2359296
    int e = idx & 63;
    int d = (idx >> 6) % D_;
    int h = ((idx >> 6) / D_) % H_;
    int l = (idx >> 6) / (D_ * H_);
    Wq[((size_t)l * D_ + d) * D_ + h * 64 + e] = qw[idx];
}

// ---------------------------------------------------------------------------
// softmax over 4096 cols (register-resident)
// ---------------------------------------------------------------------------
__global__ __launch_bounds__(256)
void softmax4096_kernel(float* __restrict__ X)
{
    float* row = X + (size_t)blockIdx.x * 4096;
    int tid = threadIdx.x;
    float4 v[4];
#pragma unroll
    for (int j = 0; j < 4; j++) v[j] = *(float4*)(row + tid * 16 + 4 * j);

    float m = -1e30f;
#pragma unroll
    for (int j = 0; j < 4; j++)
        m = fmaxf(m, fmaxf(fmaxf(v[j].x, v[j].y), fmaxf(v[j].z, v[j].w)));
    __shared__ float red[8];
#pragma unroll
    for (int s = 16; s > 0; s >>= 1) m = fmaxf(m, __shfl_xor_sync(0xffffffffu, m, s));
    if ((tid & 31) == 0) red[tid >> 5] = m;
    __syncthreads();
    m = red[0];
#pragma unroll
    for (int w = 1; w < 8; w++) m = fmaxf(m, red[w]);

    float sum = 0.f;
#pragma unroll
    for (int j = 0; j < 4; j++) {
        v[j].x = __expf(v[j].x - m); sum += v[j].x;
        v[j].y = __expf(v[j].y - m); sum += v[j].y;
        v[j].z = __expf(v[j].z - m); sum += v[j].z;
        v[j].w = __expf(v[j].w - m); sum += v[j].w;
    }
#pragma unroll
    for (int s = 16; s > 0; s >>= 1) sum += __shfl_xor_sync(0xffffffffu, sum, s);
    __syncthreads();
    if ((tid & 31) == 0) red[tid >> 5] = sum;
    __syncthreads();
    sum = 0.f;
#pragma unroll
    for (int w = 0; w < 8; w++) sum += red[w];
    float inv = 1.f / sum;
#pragma unroll
    for (int j = 0; j < 4; j++) {
        v[j].x *= inv; v[j].y *= inv; v[j].z *= inv; v[j].w *= inv;
        *(float4*)(row + tid * 16 + 4 * j) = v[j];
    }
}

// ---------------------------------------------------------------------------
// LayerNorm(a+b)*g + beta  (row len 768)
// ---------------------------------------------------------------------------
__global__ void add_ln_kernel(const float* __restrict__ Xa, const float* __restrict__ Xb,
                              const float* __restrict__ g, const float* __restrict__ beta,
                              float* __restrict__ out)
{
    int r = blockIdx.x;
    const float* a = Xa + (size_t)r * D_;
    const float* b = Xb + (size_t)r * D_;
    float* o = out + (size_t)r * D_;
    __shared__ float red[256];
    int tid = threadIdx.x;
    float v[3];
    float s = 0.f;
#pragma unroll
    for (int i = 0; i < 3; i++) { int c = tid + i * 256; v[i] = a[c] + b[c]; s += v[i]; }
    red[tid] = s; __syncthreads();
    for (int st = 128; st > 0; st >>= 1) {
        if (tid < st) red[tid] += red[tid + st];
        __syncthreads();
    }
    float mean = red[0] * (1.f / D_);
    __syncthreads();
    s = 0.f;
#pragma unroll
    for (int i = 0; i < 3; i++) { float d = v[i] - mean; s += d * d; }
    red[tid] = s; __syncthreads();
    for (int st = 128; st > 0; st >>= 1) {
        if (tid < st) red[tid] += red[tid + st];
        __syncthreads();
    }
    float rstd = rsqrtf(red[0] * (1.f / D_) + 1e-5f);
#pragma unroll
    for (int i = 0; i < 3; i++) {
        int c = tid + i * 256;
        o[c] = (v[i] - mean) * rstd * g[c] + beta[c];
    }
}

__global__ void make_queries_kernel(const float* __restrict__ x, const float* __restrict__ qc,
                                    float* __restrict__ q)
{
    int i = blockIdx.x * 256 + threadIdx.x;
    int d = i % D_;
    int m = (i / D_) & (M_ - 1);
    q[i] = x[i] + qc[m * D_ + d];
}

__global__ void bias2_kernel(const float* __restrict__ vb, const float* __restrict__ hw,
                             const float* __restrict__ hb, float* __restrict__ out)
{
    int idx = blockIdx.x * 64 + threadIdx.x;
    int h = idx >> 6, f = idx & 63;
    const float* vbh = vb + h * 64;
    const float* hwh = hw + h * 4096;
    float s = hb[idx];
#pragma unroll 8
    for (int e = 0; e < 64; e++) s += vbh[e] * hwh[e * 64 + f];
    out[idx] = s;
}

// ---------------------------------------------------------------------------
// Host side
// ---------------------------------------------------------------------------
static void tgemm(bool transB, const float* A, const float* B, float* C, const float* bias,
                  int M, int N, int K, int lda, int ldb, int ldc,
                  long sAi, long sAj, long sBi, long sBj, long sCi, long sCj,
                  long sbj, int I, int J, float alpha, int act)
{
    dim3 grid(N / 128, (M + 127) / 128, I * J);
    if (transB)
        tgemm_kernel<true><<<grid, 256, TG_SMEM_T>>>(A, B, C, bias, M, N, K, lda, ldb, ldc,
                                                     sAi, sAj, sBi, sBj, sCi, sCj, sbj, J, alpha, act);
    else
        tgemm_kernel<false><<<grid, 256, TG_SMEM_N>>>(A, B, C, bias, M, N, K, lda, ldb, ldc,
                                                      sAi, sAj, sBi, sBj, sCi, sCj, sbj, J, alpha, act);
}

static void sgemm64(bool transB, const float* A, const float* B, float* C, const float* bias,
                    int M, int N, int K, int lda, int ldb, int ldc,
                    long sAi, long sAj, long sBi, long sBj, long sCi, long sCj,
                    long sbj, int I, int J, float alpha)
{
    dim3 grid(N / 64, M / 64, I * J);
    if (transB)
        sgemm64_kernel<true><<<grid, 128>>>(A, B, C, bias, K, lda, ldb, ldc,
                                            sAi, sAj, sBi, sBj, sCi, sCj, sbj, J, alpha);
    else
        sgemm64_kernel<false><<<grid, 128>>>(A, B, C, bias, K, lda, ldb, ldc,
                                             sAi, sAj, sBi, sBj, sCi, sCj, sbj, J, alpha);
}

template <typename T>
static T* sym(const void* symbol)
{
    void* p = nullptr;
    cudaGetSymbolAddress(&p, symbol);
    return (T*)p;
}

extern "C" void kernel_launch(void* const* d_in, const int* in_sizes, int n_in,
                              void* d_out, int out_size)
{
    cudaFuncSetAttribute(tgemm_kernel<true>, cudaFuncAttributeMaxDynamicSharedMemorySize, TG_SMEM_T);
    cudaFuncSetAttribute(tgemm_kernel<false>, cudaFuncAttributeMaxDynamicSharedMemorySize, TG_SMEM_T);

    const float* latent = (const float*)d_in[0];
    const float* selector = (const float*)d_in[1];
    const float* qc = (const float*)d_in[2];
    const float* qw = (const float*)d_in[3];
    const float* qb = (const float*)d_in[4];
    const float* kw = (const float*)d_in[5];
    // kb (d_in[6]) cancels exactly in softmax
    const float* vw = (const float*)d_in[7];
    const float* vb = (const float*)d_in[8];
    const float* hw = (const float*)d_in[9];
    const float* hb = (const float*)d_in[10];
    const float* ow = (const float*)d_in[11];
    const float* ob = (const float*)d_in[12];
    const float* w1 = (const float*)d_in[13];
    const float* b1 = (const float*)d_in[14];
    const float* w2 = (const float*)d_in[15];
    const float* b2 = (const float*)d_in[16];
    const float* g1 = (const float*)d_in[17];
    const float* be1 = (const float*)d_in[18];
    const float* g2 = (const float*)d_in[19];
    const float* be2 = (const float*)d_in[20];

    float* S   = sym<float>(g_S);
    float* x   = sym<float>(g_x);
    float* qu  = sym<float>(g_queries);
    float* q2  = sym<float>(g_q2);
    float* qt  = sym<float>(g_qt);
    float* ot  = sym<float>(g_ot);
    float* Wf  = sym<float>(g_Wf);
    float* bi2 = sym<float>(g_bias2);
    float* o3  = sym<float>(g_o3);
    float* x1  = sym<float>(g_x1);
    float* hid = sym<float>(g_hid);
    float* mo  = sym<float>(g_mout);
    float* Wq  = sym<float>(g_Wq);
    float* part = sym<float>(g_part);
    float* px  = sym<float>(g_px);
    float* out = (float*)d_out;

    const long LAT_B = (long)N_ * D_;     // 3145728
    const long WHD   = (long)D_ * HD_;    // 49152
    const long WL    = (long)H_ * WHD;    // 589824
    const long PCH   = (long)BM_ * D_;    // 393216 (split-K chunk stride)

    // qw transpose for dense q-projection (all layers)
    qwT_kernel<<<(L_ * H_ * D_ * HD_) / 256, 256>>>(qw, Wq);

    // ---- pooling ----
    tgemm(true, selector, latent, S, nullptr,
          M_, N_, D_, D_, D_, N_,
          0, 0, LAT_B, 0, (long)M_ * N_, 0, 0, B_, 1, 1.0f, 0);
    softmax4096_kernel<<<B_ * M_, 256>>>(S);
    // x = P @ latent, split-K 4 over K=4096: I=b(8), J=chunk(4)
    tgemm(false, S, latent, px, nullptr,
          M_, D_, 1024, N_, D_, D_,
          (long)M_ * N_, 1024, LAT_B, (long)1024 * D_,
          (long)M_ * D_, (long)B_ * M_ * D_, 0, B_, 4, 1.0f, 0);
    reduce_kernel<<<(B_ * M_ * D_ + 255) / 256, 256>>>(px, nullptr, x,
                                                       B_ * M_ * D_, 4, (long)B_ * M_ * D_, D_);

    for (int l = 0; l < L_; l++) {
        make_queries_kernel<<<(BM_ * D_) / 256, 256>>>(x, qc + (long)l * M_ * D_, qu);

        // q2 = queries @ Wq'[l] + qb[l]  (tf32, split-K 4)
        tgemm(false, qu, Wq + (long)l * D_ * D_, part, nullptr,
              BM_, D_, 192, D_, D_, D_,
              0, 192, 0, (long)192 * D_, 0, PCH, 0, 1, 4, 1.0f, 0);
        reduce_kernel<<<(BM_ * D_ + 255) / 256, 256>>>(part, qb + (long)l * D_, q2,
                                                       BM_ * D_, 4, PCH, D_);

        // qt[b,h*64+m, :] = q2[b,:,h-block] @ kw[l,h]^T  (fp32, batched (b,h))
        sgemm64(true, q2, kw + (long)l * WL, qt, nullptr,
                M_, D_, HD_, D_, HD_, D_,
                (long)M_ * D_, HD_, 0, WHD, (long)H_ * M_ * D_, (long)M_ * D_,
                0, B_, H_, 1.0f);

        // S = scale * qt @ latent^T  (tf32, batched b)
        tgemm(true, qt, latent, S, nullptr,
              H_ * M_, N_, D_, D_, D_, N_,
              (long)H_ * M_ * D_, 0, LAT_B, 0, (long)H_ * M_ * N_, 0,
              0, B_, 1, ATTN_SCALE, 0);

        softmax4096_kernel<<<B_ * H_ * M_, 256>>>(S);

        // ot = P @ latent  (tf32, batched b)
        tgemm(false, S, latent, ot, nullptr,
              H_ * M_, D_, N_, N_, D_, D_,
              (long)H_ * M_ * N_, 0, LAT_B, 0, (long)H_ * M_ * D_, 0,
              0, B_, 1, 1.0f, 0);

        // Wf[h] = vw[l,h] @ hw[l,h]  (fp32)
        sgemm64(false, vw + (long)l * WL, hw + (long)l * H_ * HD_ * HD_, Wf, nullptr,
                D_, HD_, HD_, HD_, HD_, HD_,
                0, WHD, 0, (long)HD_ * HD_, 0, WHD, 0, 1, H_, 1.0f);
        bias2_kernel<<<H_, 64>>>(vb + (long)l * H_ * HD_, hw + (long)l * H_ * HD_ * HD_,
                                 hb + (long)l * H_ * HD_, bi2);

        // o2 (reuse q2 buffer) = ot @ Wf + bias2  (fp32, batched (b,h))
        sgemm64(false, ot, Wf, q2, bi2,
                M_, HD_, D_, D_, HD_, D_,
                (long)H_ * M_ * D_, WHD, 0, WHD, (long)M_ * D_, HD_,
                HD_, B_, H_, 1.0f);

        // o3 = o2 @ ow[l] + ob[l]  (tf32, split-K 4)
        tgemm(false, q2, ow + (long)l * D_ * D_, part, nullptr,
              BM_, D_, 192, D_, D_, D_,
              0, 192, 0, (long)192 * D_, 0, PCH, 0, 1, 4, 1.0f, 0);
        reduce_kernel<<<(BM_ * D_ + 255) / 256, 256>>>(part, ob + (long)l * D_, o3,
                                                       BM_ * D_, 4, PCH, D_);

        add_ln_kernel<<<BM_, 256>>>(o3, qu, g1 + (long)l * D_, be1 + (long)l * D_, x1);

        // hid = gelu(x1 @ w1 + b1)  (tf32)
        tgemm(false, x1, w1 + (long)l * D_ * DH_, hid, b1 + (long)l * DH_,
              BM_, DH_, D_, D_, DH_, DH_,
              0, 0, 0, 0, 0, 0, 0, 1, 1, 1.0f, 1);

        // mout = hid @ w2 + b2  (tf32, split-K 8)
        tgemm(false, hid, w2 + (long)l * DH_ * D_, part, nullptr,
              BM_, D_, 384, DH_, D_, D_,
              0, 384, 0, (long)384 * D_, 0, PCH, 0, 1, 8, 1.0f, 0);
        reduce_kernel<<<(BM_ * D_ + 255) / 256, 256>>>(part, b2 + (long)l * D_, mo,
                                                       BM_ * D_, 8, PCH, D_);

        add_ln_kernel<<<BM_, 256>>>(x1, mo, g2 + (long)l * D_, be2 + (long)l * D_,
                                    (l == L_ - 1) ? out : x);
    }
}

// round 4
// speedup vs baseline: 5.4692x; 1.7019x over previous
#include <cuda_runtime.h>
#include <cuda_fp16.h>
#include <math.h>
#include <stdint.h>

// Problem constants
#define B_   8
#define N_   4096
#define D_   768
#define H_   12
#define M_   64
#define L_   4
#define HD_  64
#define BM_  (B_ * M_)      // 512
#define DH_  (4 * D_)       // 3072
#define ATTN_SCALE 0.125f

// ---------------------------------------------------------------------------
// Scratch (device globals)
// ---------------------------------------------------------------------------
__device__ float g_S[B_ * H_ * M_ * N_];     // fp32 logits
__device__ float g_x[BM_ * D_];
__device__ float g_queries[BM_ * D_];
__device__ float g_q2[BM_ * D_];
__device__ float g_ot[B_ * H_ * M_ * D_];
__device__ float g_Wf[H_ * D_ * HD_];
__device__ float g_bias2[H_ * HD_];
__device__ float g_o3[BM_ * D_];
__device__ float g_x1[BM_ * D_];
__device__ float g_mout[BM_ * D_];
__device__ float g_part[8 * BM_ * D_];       // split-K partials
__device__ float g_px[4 * B_ * M_ * D_];

// fp16 operand buffers
__device__ __half g_lat_h[B_ * N_ * D_];     // latent fp16 [b][n][d]
__device__ __half g_latT_h[B_ * N_ * D_];    // latent^T fp16 [b][d][n]
__device__ __half g_P[B_ * H_ * M_ * N_];    // probs fp16
__device__ __half g_Wq_h[L_ * D_ * D_];      // qw as [l][h*64+e][d]
__device__ __half g_owT_h[L_ * D_ * D_];     // ow^T per layer [f][d]
__device__ __half g_w1T_h[L_ * D_ * DH_];    // w1^T [l][4D][D]
__device__ __half g_w2T_h[L_ * DH_ * D_];    // w2^T [l][D][4D]
__device__ __half g_sel_h[M_ * D_];
__device__ __half g_qu_h[BM_ * D_];
__device__ __half g_qt_h[B_ * H_ * M_ * D_];
__device__ __half g_o2_h[BM_ * D_];
__device__ __half g_x1_h[BM_ * D_];
__device__ __half g_hid_h[BM_ * DH_];

// ---------------------------------------------------------------------------
// helpers
// ---------------------------------------------------------------------------
__device__ __forceinline__ void mma_f16(float c[4], const uint32_t a[4], const uint32_t b[2])
{
    asm volatile(
        "mma.sync.aligned.m16n8k16.row.col.f32.f16.f16.f32 "
        "{%0,%1,%2,%3}, {%4,%5,%6,%7}, {%8,%9}, {%0,%1,%2,%3};\n"
        : "+f"(c[0]), "+f"(c[1]), "+f"(c[2]), "+f"(c[3])
        : "r"(a[0]), "r"(a[1]), "r"(a[2]), "r"(a[3]), "r"(b[0]), "r"(b[1]));
}
__device__ __forceinline__ uint32_t smem_u32(const void* p)
{
    return (uint32_t)__cvta_generic_to_shared(p);
}
__device__ __forceinline__ void cpasync16(uint32_t dst, const void* src, int sz)
{
    asm volatile("cp.async.cg.shared.global [%0], [%1], 16, %2;\n"
                 :: "r"(dst), "l"(src), "r"(sz));
}
__device__ __forceinline__ void cp_commit() { asm volatile("cp.async.commit_group;\n"); }
__device__ __forceinline__ void cp_wait2()  { asm volatile("cp.async.wait_group 2;\n"); }

// ---------------------------------------------------------------------------
// hgemm: fp16 tensor GEMM, C(fp32 or fp16) = alpha * A @ B^T (+bias)(+gelu)
// A: [M][K] row-major fp16 (lda). B: [N][K] k-major fp16 (ldb).
// CTA 128x128x32, 128 threads = 4 warps of 64x64 (mt4 x nt8), m16n8k16.
// 4-stage cp.async. Requires K%32==0, N%128==0; M arbitrary (guarded).
// ---------------------------------------------------------------------------
#define HG_STAGES 4
#define HG_SMEM (2 * HG_STAGES * 128 * 40 * 2)   // 81920 bytes

__global__ __launch_bounds__(128, 2)
void hgemm_kernel(const __half* __restrict__ A, const __half* __restrict__ Bm,
                  float* __restrict__ C, __half* __restrict__ Ch,
                  const float* __restrict__ bias,
                  int M, int N, int K, int lda, int ldb, int ldc,
                  long sAi, long sAj, long sBi, long sBj, long sCi, long sCj,
                  long sbj, int J, float alpha, int act)
{
    extern __shared__ __half sm[];
    __half* As = sm;                         // [4][128][40]
    __half* Bs = sm + HG_STAGES * 128 * 40;  // [4][128][40]

    int bz = blockIdx.z;
    int bi = bz / J, bj = bz - bi * J;
    A  += (size_t)bi * sAi + (size_t)bj * sAj;
    Bm += (size_t)bi * sBi + (size_t)bj * sBj;
    if (bias) bias += (size_t)bj * sbj;
    size_t coff = (size_t)bi * sCi + (size_t)bj * sCj;

    const int tid = threadIdx.x;
    const int lane = tid & 31;
    const int g = lane >> 2, t = lane & 3;
    const int warp = tid >> 5;
    const int wm = (warp & 1) * 64;
    const int wn = (warp >> 1) * 64;
    const int row0 = blockIdx.y * 128;
    const int col0 = blockIdx.x * 128;

    const uint32_t sA = smem_u32(As);
    const uint32_t sB = smem_u32(Bs);

    float acc[4][8][4];
#pragma unroll
    for (int i = 0; i < 4; i++)
#pragma unroll
        for (int j = 0; j < 8; j++)
#pragma unroll
            for (int v = 0; v < 4; v++) acc[i][j][v] = 0.f;

    // loader: 512 16B-chunk tasks per operand tile / 128 threads = 4 each
    auto issue = [&](int st, int k0) {
#pragma unroll
        for (int s = 0; s < 4; s++) {
            int idx = s * 128 + tid;
            int row = idx >> 2;
            int ch  = (idx & 3) * 8;        // half offset within k32
            // A (guarded rows)
            {
                int r = row0 + row;
                bool ok = (r < M);
                const __half* ga = ok ? (A + (size_t)r * lda + k0 + ch) : A;
                uint32_t da = sA + (uint32_t)(((st * 128 + row) * 40 + ch) * 2);
                cpasync16(da, ga, ok ? 16 : 0);
            }
            // B (N%128==0, unguarded)
            {
                const __half* gb = Bm + (size_t)(col0 + row) * ldb + k0 + ch;
                uint32_t db = sB + (uint32_t)(((st * 128 + row) * 40 + ch) * 2);
                cpasync16(db, gb, 16);
            }
        }
    };

    auto compute = [&](int buf) {
        const __half* Ab = As + buf * (128 * 40);
        const __half* Bb = Bs + buf * (128 * 40);
#pragma unroll
        for (int ko = 0; ko < 32; ko += 16) {
            uint32_t af[4][4];
#pragma unroll
            for (int mt = 0; mt < 4; mt++) {
                int r = wm + mt * 16 + g;
                af[mt][0] = *(const uint32_t*)(Ab + r * 40 + ko + 2 * t);
                af[mt][1] = *(const uint32_t*)(Ab + (r + 8) * 40 + ko + 2 * t);
                af[mt][2] = *(const uint32_t*)(Ab + r * 40 + ko + 2 * t + 8);
                af[mt][3] = *(const uint32_t*)(Ab + (r + 8) * 40 + ko + 2 * t + 8);
            }
            uint32_t bf[8][2];
#pragma unroll
            for (int nt = 0; nt < 8; nt++) {
                int c = wn + nt * 8 + g;
                bf[nt][0] = *(const uint32_t*)(Bb + c * 40 + ko + 2 * t);
                bf[nt][1] = *(const uint32_t*)(Bb + c * 40 + ko + 2 * t + 8);
            }
#pragma unroll
            for (int mt = 0; mt < 4; mt++)
#pragma unroll
                for (int nt = 0; nt < 8; nt++)
                    mma_f16(acc[mt][nt], af[mt], bf[nt]);
        }
    };

    const int KT = K >> 5;
#pragma unroll
    for (int s = 0; s < HG_STAGES - 1; s++) {
        if (s < KT) issue(s, s * 32);
        cp_commit();
    }

    for (int kt = 0; kt < KT; kt++) {
        cp_wait2();
        __syncthreads();
        compute(kt & 3);
        int ns = kt + HG_STAGES - 1;
        if (ns < KT) issue(ns & 3, ns * 32);
        cp_commit();
    }

    // Epilogue
#pragma unroll
    for (int mt = 0; mt < 4; mt++) {
#pragma unroll
        for (int v = 0; v < 2; v++) {
            int r = row0 + wm + mt * 16 + g + v * 8;
            if (r >= M) continue;
#pragma unroll
            for (int nt = 0; nt < 8; nt++) {
                int c = col0 + wn + nt * 8 + 2 * t;
                float v0 = acc[mt][nt][v * 2 + 0] * alpha;
                float v1 = acc[mt][nt][v * 2 + 1] * alpha;
                if (bias) { v0 += bias[c]; v1 += bias[c + 1]; }
                if (act == 1) {
                    v0 = 0.5f * v0 * (1.f + erff(v0 * 0.7071067811865475f));
                    v1 = 0.5f * v1 * (1.f + erff(v1 * 0.7071067811865475f));
                }
                if (Ch) {
                    *(__half2*)&Ch[coff + (size_t)r * ldc + c] = __floats2half2_rn(v0, v1);
                } else {
                    *(float2*)&C[coff + (size_t)r * ldc + c] = make_float2(v0, v1);
                }
            }
        }
    }
}

// ---------------------------------------------------------------------------
// sgemm64: fp32 GEMM for small shapes, optional fp16 output.
// ---------------------------------------------------------------------------
template <bool TRANSB>
__global__ __launch_bounds__(128)
void sgemm64_kernel(const float* __restrict__ A, const float* __restrict__ Bm,
                    float* __restrict__ C, __half* __restrict__ Ch,
                    const float* __restrict__ bias,
                    int K, int lda, int ldb, int ldc,
                    long sAi, long sAj, long sBi, long sBj, long sCi, long sCj,
                    long sbj, int J, float alpha)
{
    __shared__ float As[2][16][68];
    __shared__ float Bs[2][16][68];

    int bz = blockIdx.z;
    int bi = bz / J, bj = bz - bi * J;
    A  += (size_t)bi * sAi + (size_t)bj * sAj;
    Bm += (size_t)bi * sBi + (size_t)bj * sBj;
    size_t coff = (size_t)bi * sCi + (size_t)bj * sCj;
    if (bias) bias += (size_t)bj * sbj;

    const int tid = threadIdx.x;
    const int row_t = tid & 15;
    const int col_t = tid >> 4;
    const int row0 = blockIdx.y * 64;
    const int col0 = blockIdx.x * 64;

    const int l_r  = tid >> 1;
    const int l_kc = (tid & 1) * 8;
    const int lb_k = tid >> 3;
    const int lb_n = (tid & 7) * 8;

    float acc[4][8];
#pragma unroll
    for (int i = 0; i < 4; i++)
#pragma unroll
        for (int j = 0; j < 8; j++) acc[i][j] = 0.f;

    auto load = [&](int buf, int k0) {
        {
            const float* p = A + (size_t)(row0 + l_r) * lda + k0 + l_kc;
            float4 v0 = *(const float4*)p;
            float4 v1 = *(const float4*)(p + 4);
            As[buf][l_kc + 0][l_r] = v0.x; As[buf][l_kc + 1][l_r] = v0.y;
            As[buf][l_kc + 2][l_r] = v0.z; As[buf][l_kc + 3][l_r] = v0.w;
            As[buf][l_kc + 4][l_r] = v1.x; As[buf][l_kc + 5][l_r] = v1.y;
            As[buf][l_kc + 6][l_r] = v1.z; As[buf][l_kc + 7][l_r] = v1.w;
        }
        if (TRANSB) {
            const float* p = Bm + (size_t)(col0 + l_r) * ldb + k0 + l_kc;
            float4 v0 = *(const float4*)p;
            float4 v1 = *(const float4*)(p + 4);
            Bs[buf][l_kc + 0][l_r] = v0.x; Bs[buf][l_kc + 1][l_r] = v0.y;
            Bs[buf][l_kc + 2][l_r] = v0.z; Bs[buf][l_kc + 3][l_r] = v0.w;
            Bs[buf][l_kc + 4][l_r] = v1.x; Bs[buf][l_kc + 5][l_r] = v1.y;
            Bs[buf][l_kc + 6][l_r] = v1.z; Bs[buf][l_kc + 7][l_r] = v1.w;
        } else {
            const float* p = Bm + (size_t)(k0 + lb_k) * ldb + col0 + lb_n;
            *(float4*)&Bs[buf][lb_k][lb_n] = *(const float4*)p;
            *(float4*)&Bs[buf][lb_k][lb_n + 4] = *(const float4*)(p + 4);
        }
    };

    load(0, 0);
    __syncthreads();
    int buf = 0;
    for (int k0 = 0; k0 < K; k0 += 16) {
        if (k0 + 16 < K) load(buf ^ 1, k0 + 16);
#pragma unroll
        for (int kk = 0; kk < 16; kk++) {
            float4 a = *(const float4*)&As[buf][kk][row_t * 4];
            float4 b0 = *(const float4*)&Bs[buf][kk][col_t * 8];
            float4 b1 = *(const float4*)&Bs[buf][kk][col_t * 8 + 4];
            float ar[4] = {a.x, a.y, a.z, a.w};
            float br[8] = {b0.x, b0.y, b0.z, b0.w, b1.x, b1.y, b1.z, b1.w};
#pragma unroll
            for (int i = 0; i < 4; i++)
#pragma unroll
                for (int j = 0; j < 8; j++) acc[i][j] += ar[i] * br[j];
        }
        buf ^= 1;
        __syncthreads();
    }

#pragma unroll
    for (int i = 0; i < 4; i++) {
        int r = row0 + row_t * 4 + i;
#pragma unroll
        for (int j = 0; j < 8; j++) {
            int c = col0 + col_t * 8 + j;
            float v = acc[i][j] * alpha;
            if (bias) v += bias[c];
            if (Ch) Ch[coff + (size_t)r * ldc + c] = __float2half_rn(v);
            else    C[coff + (size_t)r * ldc + c] = v;
        }
    }
}

// ---------------------------------------------------------------------------
// split-K reduce: s = sum_c part[i+c*cs] (+bias) (gelu?) -> fp32 and/or fp16
// ---------------------------------------------------------------------------
__global__ void reduce_kernel(const float* __restrict__ part, const float* __restrict__ bias,
                              float* __restrict__ outF, __half* __restrict__ outH,
                              int total, int C, long cs, int nb, int act)
{
    int i = blockIdx.x * 256 + threadIdx.x;
    if (i >= total) return;
    float s = 0.f;
    for (int c = 0; c < C; c++) s += part[i + (size_t)c * cs];
    if (bias) s += bias[i % nb];
    if (act) s = 0.5f * s * (1.f + erff(s * 0.7071067811865475f));
    if (outH) outH[i] = __float2half_rn(s);
    if (outF) outF[i] = s;
}

// ---------------------------------------------------------------------------
// transpose + convert: in [R][C] fp32 -> out [C][R] fp16, batched
// ---------------------------------------------------------------------------
__global__ void tconv_kernel(const float* __restrict__ in, __half* __restrict__ out,
                             int R, int C, long sIn, long sOut)
{
    __shared__ float tbuf[32][33];
    in  += (size_t)blockIdx.z * sIn;
    out += (size_t)blockIdx.z * sOut;
    int r0 = blockIdx.y * 32, c0 = blockIdx.x * 32;
    int tx = threadIdx.x, ty = threadIdx.y;
#pragma unroll
    for (int i = 0; i < 4; i++)
        tbuf[ty + i * 8][tx] = in[(size_t)(r0 + ty + i * 8) * C + c0 + tx];
    __syncthreads();
#pragma unroll
    for (int i = 0; i < 4; i++)
        out[(size_t)(c0 + ty + i * 8) * R + r0 + tx] = __float2half_rn(tbuf[tx][ty + i * 8]);
}

// elementwise fp32 -> fp16
__global__ void cvt_kernel(const float* __restrict__ in, __half* __restrict__ out, int n)
{
    int i = (blockIdx.x * 256 + threadIdx.x) * 4;
    if (i >= n) return;
    float4 v = *(const float4*)(in + i);
    *(__half2*)(out + i)     = __floats2half2_rn(v.x, v.y);
    *(__half2*)(out + i + 2) = __floats2half2_rn(v.z, v.w);
}

// ---------------------------------------------------------------------------
// softmax over 4096 cols: fp32 in -> fp16 out
// ---------------------------------------------------------------------------
__global__ __launch_bounds__(256)
void softmax4096_kernel(const float* __restrict__ X, __half* __restrict__ O)
{
    const float* row = X + (size_t)blockIdx.x * 4096;
    __half* orow = O + (size_t)blockIdx.x * 4096;
    int tid = threadIdx.x;
    float4 v[4];
#pragma unroll
    for (int j = 0; j < 4; j++) v[j] = *(const float4*)(row + tid * 16 + 4 * j);

    float m = -1e30f;
#pragma unroll
    for (int j = 0; j < 4; j++)
        m = fmaxf(m, fmaxf(fmaxf(v[j].x, v[j].y), fmaxf(v[j].z, v[j].w)));
    __shared__ float red[8];
#pragma unroll
    for (int s = 16; s > 0; s >>= 1) m = fmaxf(m, __shfl_xor_sync(0xffffffffu, m, s));
    if ((tid & 31) == 0) red[tid >> 5] = m;
    __syncthreads();
    m = red[0];
#pragma unroll
    for (int w = 1; w < 8; w++) m = fmaxf(m, red[w]);

    float sum = 0.f;
#pragma unroll
    for (int j = 0; j < 4; j++) {
        v[j].x = __expf(v[j].x - m); sum += v[j].x;
        v[j].y = __expf(v[j].y - m); sum += v[j].y;
        v[j].z = __expf(v[j].z - m); sum += v[j].z;
        v[j].w = __expf(v[j].w - m); sum += v[j].w;
    }
#pragma unroll
    for (int s = 16; s > 0; s >>= 1) sum += __shfl_xor_sync(0xffffffffu, sum, s);
    __syncthreads();
    if ((tid & 31) == 0) red[tid >> 5] = sum;
    __syncthreads();
    sum = 0.f;
#pragma unroll
    for (int w = 0; w < 8; w++) sum += red[w];
    float inv = 1.f / sum;
#pragma unroll
    for (int j = 0; j < 4; j++) {
        *(__half2*)(orow + tid * 16 + 4 * j)     = __floats2half2_rn(v[j].x * inv, v[j].y * inv);
        *(__half2*)(orow + tid * 16 + 4 * j + 2) = __floats2half2_rn(v[j].z * inv, v[j].w * inv);
    }
}

// ---------------------------------------------------------------------------
// LayerNorm(a+b)*g + beta, fp32 out + optional fp16 out
// ---------------------------------------------------------------------------
__global__ void add_ln_kernel(const float* __restrict__ Xa, const float* __restrict__ Xb,
                              const float* __restrict__ g, const float* __restrict__ beta,
                              float* __restrict__ out, __half* __restrict__ outH)
{
    int r = blockIdx.x;
    const float* a = Xa + (size_t)r * D_;
    const float* b = Xb + (size_t)r * D_;
    __shared__ float red[256];
    int tid = threadIdx.x;
    float v[3];
    float s = 0.f;
#pragma unroll
    for (int i = 0; i < 3; i++) { int c = tid + i * 256; v[i] = a[c] + b[c]; s += v[i]; }
    red[tid] = s; __syncthreads();
    for (int st = 128; st > 0; st >>= 1) {
        if (tid < st) red[tid] += red[tid + st];
        __syncthreads();
    }
    float mean = red[0] * (1.f / D_);
    __syncthreads();
    s = 0.f;
#pragma unroll
    for (int i = 0; i < 3; i++) { float d = v[i] - mean; s += d * d; }
    red[tid] = s; __syncthreads();
    for (int st = 128; st > 0; st >>= 1) {
        if (tid < st) red[tid] += red[tid + st];
        __syncthreads();
    }
    float rstd = rsqrtf(red[0] * (1.f / D_) + 1e-5f);
#pragma unroll
    for (int i = 0; i < 3; i++) {
        int c = tid + i * 256;
        float o = (v[i] - mean) * rstd * g[c] + beta[c];
        out[(size_t)r * D_ + c] = o;
        if (outH) outH[(size_t)r * D_ + c] = __float2half_rn(o);
    }
}

__global__ void make_queries_kernel(const float* __restrict__ x, const float* __restrict__ qc,
                                    float* __restrict__ q, __half* __restrict__ qh)
{
    int i = blockIdx.x * 256 + threadIdx.x;
    int d = i % D_;
    int m = (i / D_) & (M_ - 1);
    float v = x[i] + qc[m * D_ + d];
    q[i] = v;
    qh[i] = __float2half_rn(v);
}

__global__ void bias2_kernel(const float* __restrict__ vb, const float* __restrict__ hw,
                             const float* __restrict__ hb, float* __restrict__ out)
{
    int idx = blockIdx.x * 64 + threadIdx.x;
    int h = idx >> 6, f = idx & 63;
    const float* vbh = vb + h * 64;
    const float* hwh = hw + h * 4096;
    float s = hb[idx];
#pragma unroll 8
    for (int e = 0; e < 64; e++) s += vbh[e] * hwh[e * 64 + f];
    out[idx] = s;
}

// ---------------------------------------------------------------------------
// Host side
// ---------------------------------------------------------------------------
static void hgemm(const __half* A, const __half* B, float* C, __half* Ch, const float* bias,
                  int M, int N, int K, int lda, int ldb, int ldc,
                  long sAi, long sAj, long sBi, long sBj, long sCi, long sCj,
                  long sbj, int I, int J, float alpha, int act)
{
    dim3 grid(N / 128, (M + 127) / 128, I * J);
    hgemm_kernel<<<grid, 128, HG_SMEM>>>(A, B, C, Ch, bias, M, N, K, lda, ldb, ldc,
                                         sAi, sAj, sBi, sBj, sCi, sCj, sbj, J, alpha, act);
}

static void sgemm64(bool transB, const float* A, const float* B, float* C, __half* Ch,
                    const float* bias, int M, int N, int K, int lda, int ldb, int ldc,
                    long sAi, long sAj, long sBi, long sBj, long sCi, long sCj,
                    long sbj, int I, int J, float alpha)
{
    dim3 grid(N / 64, M / 64, I * J);
    if (transB)
        sgemm64_kernel<true><<<grid, 128>>>(A, B, C, Ch, bias, K, lda, ldb, ldc,
                                            sAi, sAj, sBi, sBj, sCi, sCj, sbj, J, alpha);
    else
        sgemm64_kernel<false><<<grid, 128>>>(A, B, C, Ch, bias, K, lda, ldb, ldc,
                                             sAi, sAj, sBi, sBj, sCi, sCj, sbj, J, alpha);
}

template <typename T>
static T* sym(const void* symbol)
{
    void* p = nullptr;
    cudaGetSymbolAddress(&p, symbol);
    return (T*)p;
}

extern "C" void kernel_launch(void* const* d_in, const int* in_sizes, int n_in,
                              void* d_out, int out_size)
{
    cudaFuncSetAttribute(hgemm_kernel, cudaFuncAttributeMaxDynamicSharedMemorySize, HG_SMEM);

    const float* latent = (const float*)d_in[0];
    const float* selector = (const float*)d_in[1];
    const float* qc = (const float*)d_in[2];
    const float* qw = (const float*)d_in[3];
    const float* qb = (const float*)d_in[4];
    const float* kw = (const float*)d_in[5];
    // kb (d_in[6]) cancels exactly in softmax
    const float* vw = (const float*)d_in[7];
    const float* vb = (const float*)d_in[8];
    const float* hw = (const float*)d_in[9];
    const float* hb = (const float*)d_in[10];
    const float* ow = (const float*)d_in[11];
    const float* ob = (const float*)d_in[12];
    const float* w1 = (const float*)d_in[13];
    const float* b1 = (const float*)d_in[14];
    const float* w2 = (const float*)d_in[15];
    const float* b2 = (const float*)d_in[16];
    const float* g1 = (const float*)d_in[17];
    const float* be1 = (const float*)d_in[18];
    const float* g2 = (const float*)d_in[19];
    const float* be2 = (const float*)d_in[20];

    float* S    = sym<float>(g_S);
    float* x    = sym<float>(g_x);
    float* qu   = sym<float>(g_queries);
    float* q2   = sym<float>(g_q2);
    float* ot   = sym<float>(g_ot);
    float* Wf   = sym<float>(g_Wf);
    float* bi2  = sym<float>(g_bias2);
    float* o3   = sym<float>(g_o3);
    float* x1   = sym<float>(g_x1);
    float* mo   = sym<float>(g_mout);
    float* part = sym<float>(g_part);
    float* px   = sym<float>(g_px);
    __half* lat_h  = sym<__half>(g_lat_h);
    __half* latT_h = sym<__half>(g_latT_h);
    __half* P      = sym<__half>(g_P);
    __half* Wq_h   = sym<__half>(g_Wq_h);
    __half* owT_h  = sym<__half>(g_owT_h);
    __half* w1T_h  = sym<__half>(g_w1T_h);
    __half* w2T_h  = sym<__half>(g_w2T_h);
    __half* sel_h  = sym<__half>(g_sel_h);
    __half* qu_h   = sym<__half>(g_qu_h);
    __half* qt_h   = sym<__half>(g_qt_h);
    __half* o2_h   = sym<__half>(g_o2_h);
    __half* x1_h   = sym<__half>(g_x1_h);
    __half* hid_h  = sym<__half>(g_hid_h);
    float* out = (float*)d_out;

    const long LAT_B = (long)N_ * D_;     // 3145728
    const long WHD   = (long)D_ * HD_;    // 49152
    const long WL    = (long)H_ * WHD;
    const long PCH   = (long)BM_ * D_;    // 393216

    dim3 tb(32, 8);

    // ---- pre-pass: fp16 conversions / transposes ----
    cvt_kernel<<<(B_ * N_ * D_) / 1024, 256>>>(latent, lat_h, B_ * N_ * D_);
    cvt_kernel<<<(M_ * D_) / 1024, 256>>>(selector, sel_h, M_ * D_);
    tconv_kernel<<<dim3(D_ / 32, N_ / 32, B_), tb>>>(latent, latT_h, N_, D_, LAT_B, LAT_B);
    // qw[l][h][d][e] -> Wq_h[l][h*64+e][d]; per-z strides both = WHD
    tconv_kernel<<<dim3(HD_ / 32, D_ / 32, L_ * H_), tb>>>(qw, Wq_h, D_, HD_, WHD, WHD);
    tconv_kernel<<<dim3(D_ / 32, D_ / 32, L_), tb>>>(ow, owT_h, D_, D_, (long)D_ * D_, (long)D_ * D_);
    tconv_kernel<<<dim3(DH_ / 32, D_ / 32, L_), tb>>>(w1, w1T_h, D_, DH_, (long)D_ * DH_, (long)D_ * DH_);
    tconv_kernel<<<dim3(D_ / 32, DH_ / 32, L_), tb>>>(w2, w2T_h, DH_, D_, (long)DH_ * D_, (long)DH_ * D_);

    // ---- pooling ----
    // logits: sel_h @ lat_h^T
    hgemm(sel_h, lat_h, S, nullptr, nullptr,
          M_, N_, D_, D_, D_, N_,
          0, 0, LAT_B, 0, (long)M_ * N_, 0, 0, B_, 1, 1.0f, 0);
    softmax4096_kernel<<<B_ * M_, 256>>>(S, P);
    // x = P @ latent  (B = latT_h), split-K 4 over N=4096
    hgemm(P, latT_h, px, nullptr, nullptr,
          M_, D_, 1024, N_, N_, D_,
          (long)M_ * N_, 1024, LAT_B, 1024, (long)M_ * D_, (long)B_ * M_ * D_,
          0, B_, 4, 1.0f, 0);
    reduce_kernel<<<(B_ * M_ * D_ + 255) / 256, 256>>>(px, nullptr, x, nullptr,
                                                       B_ * M_ * D_, 4, (long)B_ * M_ * D_, D_, 0);

    for (int l = 0; l < L_; l++) {
        make_queries_kernel<<<(BM_ * D_) / 256, 256>>>(x, qc + (long)l * M_ * D_, qu, qu_h);

        // q2 = queries @ Wq[l]^T + qb[l]  (fp16, split-K 8, K chunks 96)
        hgemm(qu_h, Wq_h + (long)l * D_ * D_, part, nullptr, nullptr,
              BM_, D_, 96, D_, D_, D_,
              0, 96, 0, 96, 0, PCH, 0, 1, 8, 1.0f, 0);
        reduce_kernel<<<(BM_ * D_ + 255) / 256, 256>>>(part, qb + (long)l * D_, q2, nullptr,
                                                       BM_ * D_, 8, PCH, D_, 0);

        // qt_h = q2 @ kw^T  (fp32 compute, fp16 out; batched (b,h))
        sgemm64(true, q2, kw + (long)l * WL, nullptr, qt_h, nullptr,
                M_, D_, HD_, D_, HD_, D_,
                (long)M_ * D_, HD_, 0, WHD, (long)H_ * M_ * D_, (long)M_ * D_,
                0, B_, H_, 1.0f);

        // S = scale * qt @ latent^T  (fp16, batched b)
        hgemm(qt_h, lat_h, S, nullptr, nullptr,
              H_ * M_, N_, D_, D_, D_, N_,
              (long)H_ * M_ * D_, 0, LAT_B, 0, (long)H_ * M_ * N_, 0,
              0, B_, 1, ATTN_SCALE, 0);

        softmax4096_kernel<<<B_ * H_ * M_, 256>>>(S, P);

        // ot = P @ latent  (fp16, batched b; B = latT_h)
        hgemm(P, latT_h, ot, nullptr, nullptr,
              H_ * M_, D_, N_, N_, N_, D_,
              (long)H_ * M_ * N_, 0, LAT_B, 0, (long)H_ * M_ * D_, 0,
              0, B_, 1, 1.0f, 0);

        // Wf[h] = vw[l,h] @ hw[l,h]  (fp32)
        sgemm64(false, vw + (long)l * WL, hw + (long)l * H_ * HD_ * HD_, Wf, nullptr, nullptr,
                D_, HD_, HD_, HD_, HD_, HD_,
                0, WHD, 0, (long)HD_ * HD_, 0, WHD, 0, 1, H_, 1.0f);
        bias2_kernel<<<H_, 64>>>(vb + (long)l * H_ * HD_, hw + (long)l * H_ * HD_ * HD_,
                                 hb + (long)l * H_ * HD_, bi2);

        // o2_h = ot @ Wf + bias2  (fp32 compute, fp16 out; batched (b,h))
        sgemm64(false, ot, Wf, nullptr, o2_h, bi2,
                M_, HD_, D_, D_, HD_, D_,
                (long)H_ * M_ * D_, WHD, 0, WHD, (long)M_ * D_, HD_,
                HD_, B_, H_, 1.0f);

        // o3 = o2 @ ow[l] + ob[l]  (fp16, split-K 8)
        hgemm(o2_h, owT_h + (long)l * D_ * D_, part, nullptr, nullptr,
              BM_, D_, 96, D_, D_, D_,
              0, 96, 0, 96, 0, PCH, 0, 1, 8, 1.0f, 0);
        reduce_kernel<<<(BM_ * D_ + 255) / 256, 256>>>(part, ob + (long)l * D_, o3, nullptr,
                                                       BM_ * D_, 8, PCH, D_, 0);

        add_ln_kernel<<<BM_, 256>>>(o3, qu, g1 + (long)l * D_, be1 + (long)l * D_, x1, x1_h);

        // hid = gelu(x1 @ w1 + b1)  (fp16, split-K 2; gelu+bias in reduce, fp16 out)
        hgemm(x1_h, w1T_h + (long)l * D_ * DH_, part, nullptr, nullptr,
              BM_, DH_, 384, D_, D_, DH_,
              0, 384, 0, 384, 0, (long)BM_ * DH_, 0, 1, 2, 1.0f, 0);
        reduce_kernel<<<(BM_ * DH_ + 255) / 256, 256>>>(part, b1 + (long)l * DH_, nullptr, hid_h,
                                                        BM_ * DH_, 2, (long)BM_ * DH_, DH_, 1);

        // mout = hid @ w2 + b2  (fp16, split-K 8, K chunks 384)
        hgemm(hid_h, w2T_h + (long)l * DH_ * D_, part, nullptr, nullptr,
              BM_, D_, 384, DH_, DH_, D_,
              0, 384, 0, 384, 0, PCH, 0, 1, 8, 1.0f, 0);
        reduce_kernel<<<(BM_ * D_ + 255) / 256, 256>>>(part, b2 + (long)l * D_, mo, nullptr,
                                                       BM_ * D_, 8, PCH, D_, 0);

        add_ln_kernel<<<BM_, 256>>>(x1, mo, g2 + (long)l * D_, be2 + (long)l * D_,
                                    (l == L_ - 1) ? out : x, nullptr);
    }
}

// round 6
// speedup vs baseline: 6.0041x; 1.0978x over previous
#include <cuda_runtime.h>
#include <cuda_fp16.h>
#include <math.h>
#include <stdint.h>

// Problem constants
#define B_   8
#define N_   4096
#define D_   768
#define H_   12
#define M_   64
#define L_   4
#define HD_  64
#define BM_  (B_ * M_)      // 512
#define DH_  (4 * D_)       // 3072
#define ATTN_SCALE 0.125f

// ---------------------------------------------------------------------------
// Scratch (device globals)
// ---------------------------------------------------------------------------
__device__ float g_S[B_ * H_ * M_ * N_];     // fp32 logits
__device__ float g_x[BM_ * D_];
__device__ float g_queries[BM_ * D_];
__device__ float g_q2[BM_ * D_];
__device__ float g_ot[B_ * H_ * M_ * D_];
__device__ float g_Wf[H_ * D_ * HD_];
__device__ float g_bias2[H_ * HD_];
__device__ float g_o3[BM_ * D_];
__device__ float g_x1[BM_ * D_];
__device__ float g_mout[BM_ * D_];
__device__ float g_part[8 * BM_ * D_];       // split-K partials
__device__ float g_px[4 * B_ * M_ * D_];

// fp16 operand buffers
__device__ __half g_lat_h[B_ * N_ * D_];     // latent fp16 [b][n][d]
__device__ __half g_latT_h[B_ * N_ * D_];    // latent^T fp16 [b][d][n]
__device__ __half g_P[B_ * H_ * M_ * N_];    // probs fp16
__device__ __half g_Wq_h[L_ * D_ * D_];      // qw as [l][h*64+e][d]
__device__ __half g_owT_h[L_ * D_ * D_];     // ow^T per layer [f][d]
__device__ __half g_w1T_h[L_ * D_ * DH_];    // w1^T [l][4D][D]
__device__ __half g_w2T_h[L_ * DH_ * D_];    // w2^T [l][D][4D]
__device__ __half g_sel_h[M_ * D_];
__device__ __half g_qu_h[BM_ * D_];
__device__ __half g_qt_h[B_ * H_ * M_ * D_];
__device__ __half g_o2_h[BM_ * D_];
__device__ __half g_x1_h[BM_ * D_];
__device__ __half g_hid_h[BM_ * DH_];

// ---------------------------------------------------------------------------
// helpers
// ---------------------------------------------------------------------------
__device__ __forceinline__ void mma_f16(float c[4], const uint32_t a[4], const uint32_t b[2])
{
    asm volatile(
        "mma.sync.aligned.m16n8k16.row.col.f32.f16.f16.f32 "
        "{%0,%1,%2,%3}, {%4,%5,%6,%7}, {%8,%9}, {%0,%1,%2,%3};\n"
        : "+f"(c[0]), "+f"(c[1]), "+f"(c[2]), "+f"(c[3])
        : "r"(a[0]), "r"(a[1]), "r"(a[2]), "r"(a[3]), "r"(b[0]), "r"(b[1]));
}
__device__ __forceinline__ uint32_t smem_u32(const void* p)
{
    return (uint32_t)__cvta_generic_to_shared(p);
}
__device__ __forceinline__ void cpasync16(uint32_t dst, const void* src, int sz)
{
    asm volatile("cp.async.cg.shared.global [%0], [%1], 16, %2;\n"
                 :: "r"(dst), "l"(src), "r"(sz));
}
__device__ __forceinline__ void cp_commit() { asm volatile("cp.async.commit_group;\n"); }
__device__ __forceinline__ void cp_wait2()  { asm volatile("cp.async.wait_group 2;\n"); }

// ---------------------------------------------------------------------------
// hgemm: fp16 tensor GEMM, C(fp32 or fp16) = alpha * A @ B^T (+bias)(+gelu)
// A: [M][K] row-major fp16 (lda). B: [N][K] k-major fp16 (ldb).
// CTA 128x128x32, 128 threads = 4 warps of 64x64 (mt4 x nt8), m16n8k16.
// 4-stage cp.async; fragments via ldmatrix.m8n8.x4 (pad-40 rows: conflict-free).
// Requires K%32==0, N%128==0; M arbitrary (guarded).
// ---------------------------------------------------------------------------
#define HG_STAGES 4
#define HG_SMEM (2 * HG_STAGES * 128 * 40 * 2)   // 81920 bytes

__global__ __launch_bounds__(128, 2)
void hgemm_kernel(const __half* __restrict__ A, const __half* __restrict__ Bm,
                  float* __restrict__ C, __half* __restrict__ Ch,
                  const float* __restrict__ bias,
                  int M, int N, int K, int lda, int ldb, int ldc,
                  long sAi, long sAj, long sBi, long sBj, long sCi, long sCj,
                  long sbj, int J, float alpha, int act)
{
    extern __shared__ __half sm[];
    __half* As = sm;                         // [4][128][40]
    __half* Bs = sm + HG_STAGES * 128 * 40;  // [4][128][40]

    int bz = blockIdx.z;
    int bi = bz / J, bj = bz - bi * J;
    A  += (size_t)bi * sAi + (size_t)bj * sAj;
    Bm += (size_t)bi * sBi + (size_t)bj * sBj;
    if (bias) bias += (size_t)bj * sbj;
    size_t coff = (size_t)bi * sCi + (size_t)bj * sCj;

    const int tid = threadIdx.x;
    const int lane = tid & 31;
    const int g = lane >> 2, t = lane & 3;
    const int warp = tid >> 5;
    const int wm = (warp & 1) * 64;
    const int wn = (warp >> 1) * 64;
    const int row0 = blockIdx.y * 128;
    const int col0 = blockIdx.x * 128;

    const uint32_t sA = smem_u32(As);
    const uint32_t sB = smem_u32(Bs);

    // ldmatrix lane mapping (sel picks the quadrant of the x4 load)
    const int sel = lane >> 3, l7 = lane & 7;
    const int a_m = (sel & 1) * 8 + l7;      // row offset within warp A tile
    const int a_k = (sel >> 1) * 8;          // k offset
    const int b_n = (sel >> 1) * 8 + l7;     // n offset within nt-pair
    const int b_k = (sel & 1) * 8;           // k offset

    float acc[4][8][4];
#pragma unroll
    for (int i = 0; i < 4; i++)
#pragma unroll
        for (int j = 0; j < 8; j++)
#pragma unroll
            for (int v = 0; v < 4; v++) acc[i][j][v] = 0.f;

    // loader: 512 16B-chunk tasks per operand tile / 128 threads = 4 each
    auto issue = [&](int st, int k0) {
#pragma unroll
        for (int s = 0; s < 4; s++) {
            int idx = s * 128 + tid;
            int row = idx >> 2;
            int ch  = (idx & 3) * 8;        // half offset within k32
            {
                int r = row0 + row;
                bool ok = (r < M);
                const __half* ga = ok ? (A + (size_t)r * lda + k0 + ch) : A;
                uint32_t da = sA + (uint32_t)(((st * 128 + row) * 40 + ch) * 2);
                cpasync16(da, ga, ok ? 16 : 0);
            }
            {
                const __half* gb = Bm + (size_t)(col0 + row) * ldb + k0 + ch;
                uint32_t db = sB + (uint32_t)(((st * 128 + row) * 40 + ch) * 2);
                cpasync16(db, gb, 16);
            }
        }
    };

    auto compute = [&](int buf) {
        const uint32_t Ab = sA + (uint32_t)(buf * (128 * 40) * 2);
        const uint32_t Bb = sB + (uint32_t)(buf * (128 * 40) * 2);
#pragma unroll
        for (int ko = 0; ko < 32; ko += 16) {
            uint32_t af[4][4];
#pragma unroll
            for (int mt = 0; mt < 4; mt++) {
                uint32_t addr = Ab + (uint32_t)((((wm + mt * 16 + a_m) * 40) + ko + a_k) * 2);
                asm volatile(
                    "ldmatrix.sync.aligned.m8n8.x4.shared.b16 {%0,%1,%2,%3}, [%4];"
                    : "=r"(af[mt][0]), "=r"(af[mt][1]), "=r"(af[mt][2]), "=r"(af[mt][3])
                    : "r"(addr));
            }
            uint32_t bf[8][2];
#pragma unroll
            for (int p = 0; p < 4; p++) {
                uint32_t addr = Bb + (uint32_t)((((wn + p * 16 + b_n) * 40) + ko + b_k) * 2);
                asm volatile(
                    "ldmatrix.sync.aligned.m8n8.x4.shared.b16 {%0,%1,%2,%3}, [%4];"
                    : "=r"(bf[2 * p][0]), "=r"(bf[2 * p][1]),
                      "=r"(bf[2 * p + 1][0]), "=r"(bf[2 * p + 1][1])
                    : "r"(addr));
            }
#pragma unroll
            for (int mt = 0; mt < 4; mt++)
#pragma unroll
                for (int nt = 0; nt < 8; nt++)
                    mma_f16(acc[mt][nt], af[mt], bf[nt]);
        }
    };

    const int KT = K >> 5;
#pragma unroll
    for (int s = 0; s < HG_STAGES - 1; s++) {
        if (s < KT) issue(s, s * 32);
        cp_commit();
    }

    for (int kt = 0; kt < KT; kt++) {
        cp_wait2();
        __syncthreads();
        compute(kt & 3);
        int ns = kt + HG_STAGES - 1;
        if (ns < KT) issue(ns & 3, ns * 32);
        cp_commit();
    }

    // Epilogue
#pragma unroll
    for (int mt = 0; mt < 4; mt++) {
#pragma unroll
        for (int v = 0; v < 2; v++) {
            int r = row0 + wm + mt * 16 + g + v * 8;
            if (r >= M) continue;
#pragma unroll
            for (int nt = 0; nt < 8; nt++) {
                int c = col0 + wn + nt * 8 + 2 * t;
                float v0 = acc[mt][nt][v * 2 + 0] * alpha;
                float v1 = acc[mt][nt][v * 2 + 1] * alpha;
                if (bias) { v0 += bias[c]; v1 += bias[c + 1]; }
                if (act == 1) {
                    v0 = 0.5f * v0 * (1.f + erff(v0 * 0.7071067811865475f));
                    v1 = 0.5f * v1 * (1.f + erff(v1 * 0.7071067811865475f));
                }
                if (Ch) {
                    *(__half2*)&Ch[coff + (size_t)r * ldc + c] = __floats2half2_rn(v0, v1);
                } else {
                    *(float2*)&C[coff + (size_t)r * ldc + c] = make_float2(v0, v1);
                }
            }
        }
    }
}

// ---------------------------------------------------------------------------
// sgemm64: fp32 GEMM for small shapes, optional fp16 output.
// ---------------------------------------------------------------------------
template <bool TRANSB>
__global__ __launch_bounds__(128)
void sgemm64_kernel(const float* __restrict__ A, const float* __restrict__ Bm,
                    float* __restrict__ C, __half* __restrict__ Ch,
                    const float* __restrict__ bias,
                    int K, int lda, int ldb, int ldc,
                    long sAi, long sAj, long sBi, long sBj, long sCi, long sCj,
                    long sbj, int J, float alpha)
{
    __shared__ float As[2][16][68];
    __shared__ float Bs[2][16][68];

    int bz = blockIdx.z;
    int bi = bz / J, bj = bz - bi * J;
    A  += (size_t)bi * sAi + (size_t)bj * sAj;
    Bm += (size_t)bi * sBi + (size_t)bj * sBj;
    size_t coff = (size_t)bi * sCi + (size_t)bj * sCj;
    if (bias) bias += (size_t)bj * sbj;

    const int tid = threadIdx.x;
    const int row_t = tid & 15;
    const int col_t = tid >> 4;
    const int row0 = blockIdx.y * 64;
    const int col0 = blockIdx.x * 64;

    const int l_r  = tid >> 1;
    const int l_kc = (tid & 1) * 8;
    const int lb_k = tid >> 3;
    const int lb_n = (tid & 7) * 8;

    float acc[4][8];
#pragma unroll
    for (int i = 0; i < 4; i++)
#pragma unroll
        for (int j = 0; j < 8; j++) acc[i][j] = 0.f;

    auto load = [&](int buf, int k0) {
        {
            const float* p = A + (size_t)(row0 + l_r) * lda + k0 + l_kc;
            float4 v0 = *(const float4*)p;
            float4 v1 = *(const float4*)(p + 4);
            As[buf][l_kc + 0][l_r] = v0.x; As[buf][l_kc + 1][l_r] = v0.y;
            As[buf][l_kc + 2][l_r] = v0.z; As[buf][l_kc + 3][l_r] = v0.w;
            As[buf][l_kc + 4][l_r] = v1.x; As[buf][l_kc + 5][l_r] = v1.y;
            As[buf][l_kc + 6][l_r] = v1.z; As[buf][l_kc + 7][l_r] = v1.w;
        }
        if (TRANSB) {
            const float* p = Bm + (size_t)(col0 + l_r) * ldb + k0 + l_kc;
            float4 v0 = *(const float4*)p;
            float4 v1 = *(const float4*)(p + 4);
            Bs[buf][l_kc + 0][l_r] = v0.x; Bs[buf][l_kc + 1][l_r] = v0.y;
            Bs[buf][l_kc + 2][l_r] = v0.z; Bs[buf][l_kc + 3][l_r] = v0.w;
            Bs[buf][l_kc + 4][l_r] = v1.x; Bs[buf][l_kc + 5][l_r] = v1.y;
            Bs[buf][l_kc + 6][l_r] = v1.z; Bs[buf][l_kc + 7][l_r] = v1.w;
        } else {
            const float* p = Bm + (size_t)(k0 + lb_k) * ldb + col0 + lb_n;
            *(float4*)&Bs[buf][lb_k][lb_n] = *(const float4*)p;
            *(float4*)&Bs[buf][lb_k][lb_n + 4] = *(const float4*)(p + 4);
        }
    };

    load(0, 0);
    __syncthreads();
    int buf = 0;
    for (int k0 = 0; k0 < K; k0 += 16) {
        if (k0 + 16 < K) load(buf ^ 1, k0 + 16);
#pragma unroll
        for (int kk = 0; kk < 16; kk++) {
            float4 a = *(const float4*)&As[buf][kk][row_t * 4];
            float4 b0 = *(const float4*)&Bs[buf][kk][col_t * 8];
            float4 b1 = *(const float4*)&Bs[buf][kk][col_t * 8 + 4];
            float ar[4] = {a.x, a.y, a.z, a.w};
            float br[8] = {b0.x, b0.y, b0.z, b0.w, b1.x, b1.y, b1.z, b1.w};
#pragma unroll
            for (int i = 0; i < 4; i++)
#pragma unroll
                for (int j = 0; j < 8; j++) acc[i][j] += ar[i] * br[j];
        }
        buf ^= 1;
        __syncthreads();
    }

#pragma unroll
    for (int i = 0; i < 4; i++) {
        int r = row0 + row_t * 4 + i;
#pragma unroll
        for (int j = 0; j < 8; j++) {
            int c = col0 + col_t * 8 + j;
            float v = acc[i][j] * alpha;
            if (bias) v += bias[c];
            if (Ch) Ch[coff + (size_t)r * ldc + c] = __float2half_rn(v);
            else    C[coff + (size_t)r * ldc + c] = v;
        }
    }
}

// ---------------------------------------------------------------------------
// split-K reduce: s = sum_c part[i+c*cs] (+bias) (gelu?) -> fp32 and/or fp16
// ---------------------------------------------------------------------------
__global__ void reduce_kernel(const float* __restrict__ part, const float* __restrict__ bias,
                              float* __restrict__ outF, __half* __restrict__ outH,
                              int total, int C, long cs, int nb, int act)
{
    int i = blockIdx.x * 256 + threadIdx.x;
    if (i >= total) return;
    float s = 0.f;
    for (int c = 0; c < C; c++) s += part[i + (size_t)c * cs];
    if (bias) s += bias[i % nb];
    if (act) s = 0.5f * s * (1.f + erff(s * 0.7071067811865475f));
    if (outH) outH[i] = __float2half_rn(s);
    if (outF) outF[i] = s;
}

// ---------------------------------------------------------------------------
// transpose + convert: in [R][C] fp32 -> out [C][R] fp16, batched
// ---------------------------------------------------------------------------
__global__ void tconv_kernel(const float* __restrict__ in, __half* __restrict__ out,
                             int R, int C, long sIn, long sOut)
{
    __shared__ float tbuf[32][33];
    in  += (size_t)blockIdx.z * sIn;
    out += (size_t)blockIdx.z * sOut;
    int r0 = blockIdx.y * 32, c0 = blockIdx.x * 32;
    int tx = threadIdx.x, ty = threadIdx.y;
#pragma unroll
    for (int i = 0; i < 4; i++)
        tbuf[ty + i * 8][tx] = in[(size_t)(r0 + ty + i * 8) * C + c0 + tx];
    __syncthreads();
#pragma unroll
    for (int i = 0; i < 4; i++)
        out[(size_t)(c0 + ty + i * 8) * R + r0 + tx] = __float2half_rn(tbuf[tx][ty + i * 8]);
}

// elementwise fp32 -> fp16
__global__ void cvt_kernel(const float* __restrict__ in, __half* __restrict__ out, int n)
{
    int i = (blockIdx.x * 256 + threadIdx.x) * 4;
    if (i >= n) return;
    float4 v = *(const float4*)(in + i);
    *(__half2*)(out + i)     = __floats2half2_rn(v.x, v.y);
    *(__half2*)(out + i + 2) = __floats2half2_rn(v.z, v.w);
}

// ---------------------------------------------------------------------------
// softmax over 4096 cols: fp32 in -> fp16 out
// ---------------------------------------------------------------------------
__global__ __launch_bounds__(256)
void softmax4096_kernel(const float* __restrict__ X, __half* __restrict__ O)
{
    const float* row = X + (size_t)blockIdx.x * 4096;
    __half* orow = O + (size_t)blockIdx.x * 4096;
    int tid = threadIdx.x;
    float4 v[4];
#pragma unroll
    for (int j = 0; j < 4; j++) v[j] = *(const float4*)(row + tid * 16 + 4 * j);

    float m = -1e30f;
#pragma unroll
    for (int j = 0; j < 4; j++)
        m = fmaxf(m, fmaxf(fmaxf(v[j].x, v[j].y), fmaxf(v[j].z, v[j].w)));
    __shared__ float red[8];
#pragma unroll
    for (int s = 16; s > 0; s >>= 1) m = fmaxf(m, __shfl_xor_sync(0xffffffffu, m, s));
    if ((tid & 31) == 0) red[tid >> 5] = m;
    __syncthreads();
    m = red[0];
#pragma unroll
    for (int w = 1; w < 8; w++) m = fmaxf(m, red[w]);

    float sum = 0.f;
#pragma unroll
    for (int j = 0; j < 4; j++) {
        v[j].x = __expf(v[j].x - m); sum += v[j].x;
        v[j].y = __expf(v[j].y - m); sum += v[j].y;
        v[j].z = __expf(v[j].z - m); sum += v[j].z;
        v[j].w = __expf(v[j].w - m); sum += v[j].w;
    }
#pragma unroll
    for (int s = 16; s > 0; s >>= 1) sum += __shfl_xor_sync(0xffffffffu, sum, s);
    __syncthreads();
    if ((tid & 31) == 0) red[tid >> 5] = sum;
    __syncthreads();
    sum = 0.f;
#pragma unroll
    for (int w = 0; w < 8; w++) sum += red[w];
    float inv = 1.f / sum;
#pragma unroll
    for (int j = 0; j < 4; j++) {
        *(__half2*)(orow + tid * 16 + 4 * j)     = __floats2half2_rn(v[j].x * inv, v[j].y * inv);
        *(__half2*)(orow + tid * 16 + 4 * j + 2) = __floats2half2_rn(v[j].z * inv, v[j].w * inv);
    }
}

// ---------------------------------------------------------------------------
// LayerNorm(a+b)*g + beta, fp32 out + optional fp16 out
// ---------------------------------------------------------------------------
__global__ void add_ln_kernel(const float* __restrict__ Xa, const float* __restrict__ Xb,
                              const float* __restrict__ g, const float* __restrict__ beta,
                              float* __restrict__ out, __half* __restrict__ outH)
{
    int r = blockIdx.x;
    const float* a = Xa + (size_t)r * D_;
    const float* b = Xb + (size_t)r * D_;
    __shared__ float red[256];
    int tid = threadIdx.x;
    float v[3];
    float s = 0.f;
#pragma unroll
    for (int i = 0; i < 3; i++) { int c = tid + i * 256; v[i] = a[c] + b[c]; s += v[i]; }
    red[tid] = s; __syncthreads();
    for (int st = 128; st > 0; st >>= 1) {
        if (tid < st) red[tid] += red[tid + st];
        __syncthreads();
    }
    float mean = red[0] * (1.f / D_);
    __syncthreads();
    s = 0.f;
#pragma unroll
    for (int i = 0; i < 3; i++) { float d = v[i] - mean; s += d * d; }
    red[tid] = s; __syncthreads();
    for (int st = 128; st > 0; st >>= 1) {
        if (tid < st) red[tid] += red[tid + st];
        __syncthreads();
    }
    float rstd = rsqrtf(red[0] * (1.f / D_) + 1e-5f);
#pragma unroll
    for (int i = 0; i < 3; i++) {
        int c = tid + i * 256;
        float o = (v[i] - mean) * rstd * g[c] + beta[c];
        out[(size_t)r * D_ + c] = o;
        if (outH) outH[(size_t)r * D_ + c] = __float2half_rn(o);
    }
}

__global__ void make_queries_kernel(const float* __restrict__ x, const float* __restrict__ qc,
                                    float* __restrict__ q, __half* __restrict__ qh)
{
    int i = blockIdx.x * 256 + threadIdx.x;
    int d = i % D_;
    int m = (i / D_) & (M_ - 1);
    float v = x[i] + qc[m * D_ + d];
    q[i] = v;
    qh[i] = __float2half_rn(v);
}

__global__ void bias2_kernel(const float* __restrict__ vb, const float* __restrict__ hw,
                             const float* __restrict__ hb, float* __restrict__ out)
{
    int idx = blockIdx.x * 64 + threadIdx.x;
    int h = idx >> 6, f = idx & 63;
    const float* vbh = vb + h * 64;
    const float* hwh = hw + h * 4096;
    float s = hb[idx];
#pragma unroll 8
    for (int e = 0; e < 64; e++) s += vbh[e] * hwh[e * 64 + f];
    out[idx] = s;
}

// ---------------------------------------------------------------------------
// Host side
// ---------------------------------------------------------------------------
static void hgemm(const __half* A, const __half* B, float* C, __half* Ch, const float* bias,
                  int M, int N, int K, int lda, int ldb, int ldc,
                  long sAi, long sAj, long sBi, long sBj, long sCi, long sCj,
                  long sbj, int I, int J, float alpha, int act)
{
    dim3 grid(N / 128, (M + 127) / 128, I * J);
    hgemm_kernel<<<grid, 128, HG_SMEM>>>(A, B, C, Ch, bias, M, N, K, lda, ldb, ldc,
                                         sAi, sAj, sBi, sBj, sCi, sCj, sbj, J, alpha, act);
}

static void sgemm64(bool transB, const float* A, const float* B, float* C, __half* Ch,
                    const float* bias, int M, int N, int K, int lda, int ldb, int ldc,
                    long sAi, long sAj, long sBi, long sBj, long sCi, long sCj,
                    long sbj, int I, int J, float alpha)
{
    dim3 grid(N / 64, M / 64, I * J);
    if (transB)
        sgemm64_kernel<true><<<grid, 128>>>(A, B, C, Ch, bias, K, lda, ldb, ldc,
                                            sAi, sAj, sBi, sBj, sCi, sCj, sbj, J, alpha);
    else
        sgemm64_kernel<false><<<grid, 128>>>(A, B, C, Ch, bias, K, lda, ldb, ldc,
                                             sAi, sAj, sBi, sBj, sCi, sCj, sbj, J, alpha);
}

template <typename T>
static T* sym(const void* symbol)
{
    void* p = nullptr;
    cudaGetSymbolAddress(&p, symbol);
    return (T*)p;
}

extern "C" void kernel_launch(void* const* d_in, const int* in_sizes, int n_in,
                              void* d_out, int out_size)
{
    cudaFuncSetAttribute(hgemm_kernel, cudaFuncAttributeMaxDynamicSharedMemorySize, HG_SMEM);

    const float* latent = (const float*)d_in[0];
    const float* selector = (const float*)d_in[1];
    const float* qc = (const float*)d_in[2];
    const float* qw = (const float*)d_in[3];
    const float* qb = (const float*)d_in[4];
    const float* kw = (const float*)d_in[5];
    // kb (d_in[6]) cancels exactly in softmax
    const float* vw = (const float*)d_in[7];
    const float* vb = (const float*)d_in[8];
    const float* hw = (const float*)d_in[9];
    const float* hb = (const float*)d_in[10];
    const float* ow = (const float*)d_in[11];
    const float* ob = (const float*)d_in[12];
    const float* w1 = (const float*)d_in[13];
    const float* b1 = (const float*)d_in[14];
    const float* w2 = (const float*)d_in[15];
    const float* b2 = (const float*)d_in[16];
    const float* g1 = (const float*)d_in[17];
    const float* be1 = (const float*)d_in[18];
    const float* g2 = (const float*)d_in[19];
    const float* be2 = (const float*)d_in[20];

    float* S    = sym<float>(g_S);
    float* x    = sym<float>(g_x);
    float* qu   = sym<float>(g_queries);
    float* q2   = sym<float>(g_q2);
    float* ot   = sym<float>(g_ot);
    float* Wf   = sym<float>(g_Wf);
    float* bi2  = sym<float>(g_bias2);
    float* o3   = sym<float>(g_o3);
    float* x1   = sym<float>(g_x1);
    float* mo   = sym<float>(g_mout);
    float* part = sym<float>(g_part);
    float* px   = sym<float>(g_px);
    __half* lat_h  = sym<__half>(g_lat_h);
    __half* latT_h = sym<__half>(g_latT_h);
    __half* P      = sym<__half>(g_P);
    __half* Wq_h   = sym<__half>(g_Wq_h);
    __half* owT_h  = sym<__half>(g_owT_h);
    __half* w1T_h  = sym<__half>(g_w1T_h);
    __half* w2T_h  = sym<__half>(g_w2T_h);
    __half* sel_h  = sym<__half>(g_sel_h);
    __half* qu_h   = sym<__half>(g_qu_h);
    __half* qt_h   = sym<__half>(g_qt_h);
    __half* o2_h   = sym<__half>(g_o2_h);
    __half* x1_h   = sym<__half>(g_x1_h);
    __half* hid_h  = sym<__half>(g_hid_h);
    float* out = (float*)d_out;

    const long LAT_B = (long)N_ * D_;     // 3145728
    const long WHD   = (long)D_ * HD_;    // 49152
    const long WL    = (long)H_ * WHD;
    const long PCH   = (long)BM_ * D_;    // 393216
    const long HMD   = (long)H_ * M_ * D_;   // 589824
    const long HMN   = (long)H_ * M_ * N_;   // 3145728

    dim3 tb(32, 8);

    // ---- pre-pass: fp16 conversions / transposes ----
    cvt_kernel<<<(B_ * N_ * D_) / 1024, 256>>>(latent, lat_h, B_ * N_ * D_);
    cvt_kernel<<<(M_ * D_) / 1024, 256>>>(selector, sel_h, M_ * D_);
    tconv_kernel<<<dim3(D_ / 32, N_ / 32, B_), tb>>>(latent, latT_h, N_, D_, LAT_B, LAT_B);
    tconv_kernel<<<dim3(HD_ / 32, D_ / 32, L_ * H_), tb>>>(qw, Wq_h, D_, HD_, WHD, WHD);
    tconv_kernel<<<dim3(D_ / 32, D_ / 32, L_), tb>>>(ow, owT_h, D_, D_, (long)D_ * D_, (long)D_ * D_);
    tconv_kernel<<<dim3(DH_ / 32, D_ / 32, L_), tb>>>(w1, w1T_h, D_, DH_, (long)D_ * DH_, (long)D_ * DH_);
    tconv_kernel<<<dim3(D_ / 32, DH_ / 32, L_), tb>>>(w2, w2T_h, DH_, D_, (long)DH_ * D_, (long)DH_ * D_);

    // ---- pooling ----
    hgemm(sel_h, lat_h, S, nullptr, nullptr,
          M_, N_, D_, D_, D_, N_,
          0, 0, LAT_B, 0, (long)M_ * N_, 0, 0, B_, 1, 1.0f, 0);
    softmax4096_kernel<<<B_ * M_, 256>>>(S, P);
    hgemm(P, latT_h, px, nullptr, nullptr,
          M_, D_, 1024, N_, N_, D_,
          (long)M_ * N_, 1024, LAT_B, 1024, (long)M_ * D_, (long)B_ * M_ * D_,
          0, B_, 4, 1.0f, 0);
    reduce_kernel<<<(B_ * M_ * D_ + 255) / 256, 256>>>(px, nullptr, x, nullptr,
                                                       B_ * M_ * D_, 4, (long)B_ * M_ * D_, D_, 0);

    for (int l = 0; l < L_; l++) {
        make_queries_kernel<<<(BM_ * D_) / 256, 256>>>(x, qc + (long)l * M_ * D_, qu, qu_h);

        // q2 = queries @ Wq[l]^T + qb[l]  (fp16, split-K 8)
        hgemm(qu_h, Wq_h + (long)l * D_ * D_, part, nullptr, nullptr,
              BM_, D_, 96, D_, D_, D_,
              0, 96, 0, 96, 0, PCH, 0, 1, 8, 1.0f, 0);
        reduce_kernel<<<(BM_ * D_ + 255) / 256, 256>>>(part, qb + (long)l * D_, q2, nullptr,
                                                       BM_ * D_, 8, PCH, D_, 0);

        // qt_h = q2 @ kw^T  (fp32 compute, fp16 out; batched (b,h))
        sgemm64(true, q2, kw + (long)l * WL, nullptr, qt_h, nullptr,
                M_, D_, HD_, D_, HD_, D_,
                (long)M_ * D_, HD_, 0, WHD, HMD, (long)M_ * D_,
                0, B_, H_, 1.0f);

        // S = scale * qt @ latent^T  (fp16, batched b)
        hgemm(qt_h, lat_h, S, nullptr, nullptr,
              H_ * M_, N_, D_, D_, D_, N_,
              HMD, 0, LAT_B, 0, HMN, 0,
              0, B_, 1, ATTN_SCALE, 0);

        softmax4096_kernel<<<B_ * H_ * M_, 256>>>(S, P);

        // ot = P @ latent  (fp16, batched b; B = latT_h)
        hgemm(P, latT_h, ot, nullptr, nullptr,
              H_ * M_, D_, N_, N_, N_, D_,
              HMN, 0, LAT_B, 0, HMD, 0,
              0, B_, 1, 1.0f, 0);

        // Wf[h] = vw[l,h] @ hw[l,h]  (fp32)
        sgemm64(false, vw + (long)l * WL, hw + (long)l * H_ * HD_ * HD_, Wf, nullptr, nullptr,
                D_, HD_, HD_, HD_, HD_, HD_,
                0, WHD, 0, (long)HD_ * HD_, 0, WHD, 0, 1, H_, 1.0f);
        bias2_kernel<<<H_, 64>>>(vb + (long)l * H_ * HD_, hw + (long)l * H_ * HD_ * HD_,
                                 hb + (long)l * H_ * HD_, bi2);

        // o2_h = ot @ Wf + bias2  (fp32 compute, fp16 out; batched (b,h))
        sgemm64(false, ot, Wf, nullptr, o2_h, bi2,
                M_, HD_, D_, D_, HD_, D_,
                HMD, WHD, 0, WHD, (long)M_ * D_, HD_,
                HD_, B_, H_, 1.0f);

        // o3 = o2 @ ow[l] + ob[l]  (fp16, split-K 8)
        hgemm(o2_h, owT_h + (long)l * D_ * D_, part, nullptr, nullptr,
              BM_, D_, 96, D_, D_, D_,
              0, 96, 0, 96, 0, PCH, 0, 1, 8, 1.0f, 0);
        reduce_kernel<<<(BM_ * D_ + 255) / 256, 256>>>(part, ob + (long)l * D_, o3, nullptr,
                                                       BM_ * D_, 8, PCH, D_, 0);

        add_ln_kernel<<<BM_, 256>>>(o3, qu, g1 + (long)l * D_, be1 + (long)l * D_, x1, x1_h);

        // hid = gelu(x1 @ w1 + b1)  (fp16, split-K 2)
        hgemm(x1_h, w1T_h + (long)l * D_ * DH_, part, nullptr, nullptr,
              BM_, DH_, 384, D_, D_, DH_,
              0, 384, 0, 384, 0, (long)BM_ * DH_, 0, 1, 2, 1.0f, 0);
        reduce_kernel<<<(BM_ * DH_ + 255) / 256, 256>>>(part, b1 + (long)l * DH_, nullptr, hid_h,
                                                        BM_ * DH_, 2, (long)BM_ * DH_, DH_, 1);

        // mout = hid @ w2 + b2  (fp16, split-K 8)
        hgemm(hid_h, w2T_h + (long)l * DH_ * D_, part, nullptr, nullptr,
              BM_, D_, 384, DH_, DH_, D_,
              0, 384, 0, 384, 0, PCH, 0, 1, 8, 1.0f, 0);
        reduce_kernel<<<(BM_ * D_ + 255) / 256, 256>>>(part, b2 + (long)l * D_, mo, nullptr,
                                                       BM_ * D_, 8, PCH, D_, 0);

        add_ln_kernel<<<BM_, 256>>>(x1, mo, g2 + (long)l * D_, be2 + (long)l * D_,
                                    (l == L_ - 1) ? out : x, nullptr);
    }
}

// round 7
// speedup vs baseline: 6.4016x; 1.0662x over previous
#include <cuda_runtime.h>
#include <cuda_fp16.h>
#include <math.h>
#include <stdint.h>

// Problem constants
#define B_   8
#define N_   4096
#define D_   768
#define H_   12
#define M_   64
#define L_   4
#define HD_  64
#define BM_  (B_ * M_)      // 512
#define DH_  (4 * D_)       // 3072
#define ATTN_SCALE 0.125f

// ---------------------------------------------------------------------------
// Scratch (device globals)
// ---------------------------------------------------------------------------
__device__ float g_S[B_ * M_ * N_];          // fp32 pooling logits only
__device__ float g_x[BM_ * D_];
__device__ float g_queries[BM_ * D_];
__device__ float g_q2[BM_ * D_];
__device__ float g_ot[B_ * H_ * M_ * D_];
__device__ float g_Wf[H_ * D_ * HD_];
__device__ float g_bias2[H_ * HD_];
__device__ float g_o3[BM_ * D_];
__device__ float g_x1[BM_ * D_];
__device__ float g_mout[BM_ * D_];
__device__ float g_part[8 * BM_ * D_];       // split-K partials
__device__ float g_px[4 * B_ * M_ * D_];

// fp16 operand buffers
__device__ __half g_lat_h[B_ * N_ * D_];     // latent fp16 [b][n][d]
__device__ __half g_latT_h[B_ * N_ * D_];    // latent^T fp16 [b][d][n]
__device__ __half g_P[B_ * H_ * M_ * N_];    // logits/probs fp16 (in-place softmax)
__device__ __half g_Wq_h[L_ * D_ * D_];      // qw as [l][h*64+e][d]
__device__ __half g_owT_h[L_ * D_ * D_];     // ow^T per layer [f][d]
__device__ __half g_w1T_h[L_ * D_ * DH_];    // w1^T [l][4D][D]
__device__ __half g_w2T_h[L_ * DH_ * D_];    // w2^T [l][D][4D]
__device__ __half g_sel_h[M_ * D_];
__device__ __half g_qu_h[BM_ * D_];
__device__ __half g_qt_h[B_ * H_ * M_ * D_];
__device__ __half g_o2_h[BM_ * D_];
__device__ __half g_x1_h[BM_ * D_];
__device__ __half g_hid_h[BM_ * DH_];

// ---------------------------------------------------------------------------
// helpers
// ---------------------------------------------------------------------------
__device__ __forceinline__ void mma_f16(float c[4], const uint32_t a[4], const uint32_t b[2])
{
    asm volatile(
        "mma.sync.aligned.m16n8k16.row.col.f32.f16.f16.f32 "
        "{%0,%1,%2,%3}, {%4,%5,%6,%7}, {%8,%9}, {%0,%1,%2,%3};\n"
        : "+f"(c[0]), "+f"(c[1]), "+f"(c[2]), "+f"(c[3])
        : "r"(a[0]), "r"(a[1]), "r"(a[2]), "r"(a[3]), "r"(b[0]), "r"(b[1]));
}
__device__ __forceinline__ uint32_t smem_u32(const void* p)
{
    return (uint32_t)__cvta_generic_to_shared(p);
}
__device__ __forceinline__ void cpasync16(uint32_t dst, const void* src, int sz)
{
    asm volatile("cp.async.cg.shared.global [%0], [%1], 16, %2;\n"
                 :: "r"(dst), "l"(src), "r"(sz));
}
__device__ __forceinline__ void cp_commit() { asm volatile("cp.async.commit_group;\n"); }
__device__ __forceinline__ void cp_wait2()  { asm volatile("cp.async.wait_group 2;\n"); }

// ---------------------------------------------------------------------------
// hgemm: fp16 tensor GEMM, C(fp32 or fp16) = alpha * A @ B^T (+bias)(+gelu)
// A: [M][K] row-major fp16 (lda). B: [N][K] k-major fp16 (ldb).
// CTA 128x128x32, 128 threads = 4 warps of 64x64 (mt4 x nt8), m16n8k16.
// 4-stage cp.async; fragments via ldmatrix.m8n8.x4 (pad-40 rows: conflict-free).
// Requires K%32==0, N%128==0; M arbitrary (guarded).
// ---------------------------------------------------------------------------
#define HG_STAGES 4
#define HG_SMEM (2 * HG_STAGES * 128 * 40 * 2)   // 81920 bytes

__global__ __launch_bounds__(128, 2)
void hgemm_kernel(const __half* __restrict__ A, const __half* __restrict__ Bm,
                  float* __restrict__ C, __half* __restrict__ Ch,
                  const float* __restrict__ bias,
                  int M, int N, int K, int lda, int ldb, int ldc,
                  long sAi, long sAj, long sBi, long sBj, long sCi, long sCj,
                  long sbj, int J, float alpha, int act)
{
    extern __shared__ __half sm[];
    __half* As = sm;                         // [4][128][40]
    __half* Bs = sm + HG_STAGES * 128 * 40;  // [4][128][40]

    int bz = blockIdx.z;
    int bi = bz / J, bj = bz - bi * J;
    A  += (size_t)bi * sAi + (size_t)bj * sAj;
    Bm += (size_t)bi * sBi + (size_t)bj * sBj;
    if (bias) bias += (size_t)bj * sbj;
    size_t coff = (size_t)bi * sCi + (size_t)bj * sCj;

    const int tid = threadIdx.x;
    const int lane = tid & 31;
    const int g = lane >> 2, t = lane & 3;
    const int warp = tid >> 5;
    const int wm = (warp & 1) * 64;
    const int wn = (warp >> 1) * 64;
    const int row0 = blockIdx.y * 128;
    const int col0 = blockIdx.x * 128;

    const uint32_t sA = smem_u32(As);
    const uint32_t sB = smem_u32(Bs);

    // ldmatrix lane mapping (sel picks the quadrant of the x4 load)
    const int sel = lane >> 3, l7 = lane & 7;
    const int a_m = (sel & 1) * 8 + l7;
    const int a_k = (sel >> 1) * 8;
    const int b_n = (sel >> 1) * 8 + l7;
    const int b_k = (sel & 1) * 8;

    float acc[4][8][4];
#pragma unroll
    for (int i = 0; i < 4; i++)
#pragma unroll
        for (int j = 0; j < 8; j++)
#pragma unroll
            for (int v = 0; v < 4; v++) acc[i][j][v] = 0.f;

    // loader: 512 16B-chunk tasks per operand tile / 128 threads = 4 each
    auto issue = [&](int st, int k0) {
#pragma unroll
        for (int s = 0; s < 4; s++) {
            int idx = s * 128 + tid;
            int row = idx >> 2;
            int ch  = (idx & 3) * 8;        // half offset within k32
            {
                int r = row0 + row;
                bool ok = (r < M);
                const __half* ga = ok ? (A + (size_t)r * lda + k0 + ch) : A;
                uint32_t da = sA + (uint32_t)(((st * 128 + row) * 40 + ch) * 2);
                cpasync16(da, ga, ok ? 16 : 0);
            }
            {
                const __half* gb = Bm + (size_t)(col0 + row) * ldb + k0 + ch;
                uint32_t db = sB + (uint32_t)(((st * 128 + row) * 40 + ch) * 2);
                cpasync16(db, gb, 16);
            }
        }
    };

    auto compute = [&](int buf) {
        const uint32_t Ab = sA + (uint32_t)(buf * (128 * 40) * 2);
        const uint32_t Bb = sB + (uint32_t)(buf * (128 * 40) * 2);
#pragma unroll
        for (int ko = 0; ko < 32; ko += 16) {
            uint32_t af[4][4];
#pragma unroll
            for (int mt = 0; mt < 4; mt++) {
                uint32_t addr = Ab + (uint32_t)((((wm + mt * 16 + a_m) * 40) + ko + a_k) * 2);
                asm volatile(
                    "ldmatrix.sync.aligned.m8n8.x4.shared.b16 {%0,%1,%2,%3}, [%4];"
                    : "=r"(af[mt][0]), "=r"(af[mt][1]), "=r"(af[mt][2]), "=r"(af[mt][3])
                    : "r"(addr));
            }
            uint32_t bf[8][2];
#pragma unroll
            for (int p = 0; p < 4; p++) {
                uint32_t addr = Bb + (uint32_t)((((wn + p * 16 + b_n) * 40) + ko + b_k) * 2);
                asm volatile(
                    "ldmatrix.sync.aligned.m8n8.x4.shared.b16 {%0,%1,%2,%3}, [%4];"
                    : "=r"(bf[2 * p][0]), "=r"(bf[2 * p][1]),
                      "=r"(bf[2 * p + 1][0]), "=r"(bf[2 * p + 1][1])
                    : "r"(addr));
            }
#pragma unroll
            for (int mt = 0; mt < 4; mt++)
#pragma unroll
                for (int nt = 0; nt < 8; nt++)
                    mma_f16(acc[mt][nt], af[mt], bf[nt]);
        }
    };

    const int KT = K >> 5;
#pragma unroll
    for (int s = 0; s < HG_STAGES - 1; s++) {
        if (s < KT) issue(s, s * 32);
        cp_commit();
    }

    for (int kt = 0; kt < KT; kt++) {
        cp_wait2();
        __syncthreads();
        compute(kt & 3);
        int ns = kt + HG_STAGES - 1;
        if (ns < KT) issue(ns & 3, ns * 32);
        cp_commit();
    }

    // Epilogue
#pragma unroll
    for (int mt = 0; mt < 4; mt++) {
#pragma unroll
        for (int v = 0; v < 2; v++) {
            int r = row0 + wm + mt * 16 + g + v * 8;
            if (r >= M) continue;
#pragma unroll
            for (int nt = 0; nt < 8; nt++) {
                int c = col0 + wn + nt * 8 + 2 * t;
                float v0 = acc[mt][nt][v * 2 + 0] * alpha;
                float v1 = acc[mt][nt][v * 2 + 1] * alpha;
                if (bias) { v0 += bias[c]; v1 += bias[c + 1]; }
                if (act == 1) {
                    v0 = 0.5f * v0 * (1.f + erff(v0 * 0.7071067811865475f));
                    v1 = 0.5f * v1 * (1.f + erff(v1 * 0.7071067811865475f));
                }
                if (Ch) {
                    *(__half2*)&Ch[coff + (size_t)r * ldc + c] = __floats2half2_rn(v0, v1);
                } else {
                    *(float2*)&C[coff + (size_t)r * ldc + c] = make_float2(v0, v1);
                }
            }
        }
    }
}

// ---------------------------------------------------------------------------
// sgemm64: fp32 GEMM for small shapes, optional fp16 output.
// ---------------------------------------------------------------------------
template <bool TRANSB>
__global__ __launch_bounds__(128)
void sgemm64_kernel(const float* __restrict__ A, const float* __restrict__ Bm,
                    float* __restrict__ C, __half* __restrict__ Ch,
                    const float* __restrict__ bias,
                    int K, int lda, int ldb, int ldc,
                    long sAi, long sAj, long sBi, long sBj, long sCi, long sCj,
                    long sbj, int J, float alpha)
{
    __shared__ float As[2][16][68];
    __shared__ float Bs[2][16][68];

    int bz = blockIdx.z;
    int bi = bz / J, bj = bz - bi * J;
    A  += (size_t)bi * sAi + (size_t)bj * sAj;
    Bm += (size_t)bi * sBi + (size_t)bj * sBj;
    size_t coff = (size_t)bi * sCi + (size_t)bj * sCj;
    if (bias) bias += (size_t)bj * sbj;

    const int tid = threadIdx.x;
    const int row_t = tid & 15;
    const int col_t = tid >> 4;
    const int row0 = blockIdx.y * 64;
    const int col0 = blockIdx.x * 64;

    const int l_r  = tid >> 1;
    const int l_kc = (tid & 1) * 8;
    const int lb_k = tid >> 3;
    const int lb_n = (tid & 7) * 8;

    float acc[4][8];
#pragma unroll
    for (int i = 0; i < 4; i++)
#pragma unroll
        for (int j = 0; j < 8; j++) acc[i][j] = 0.f;

    auto load = [&](int buf, int k0) {
        {
            const float* p = A + (size_t)(row0 + l_r) * lda + k0 + l_kc;
            float4 v0 = *(const float4*)p;
            float4 v1 = *(const float4*)(p + 4);
            As[buf][l_kc + 0][l_r] = v0.x; As[buf][l_kc + 1][l_r] = v0.y;
            As[buf][l_kc + 2][l_r] = v0.z; As[buf][l_kc + 3][l_r] = v0.w;
            As[buf][l_kc + 4][l_r] = v1.x; As[buf][l_kc + 5][l_r] = v1.y;
            As[buf][l_kc + 6][l_r] = v1.z; As[buf][l_kc + 7][l_r] = v1.w;
        }
        if (TRANSB) {
            const float* p = Bm + (size_t)(col0 + l_r) * ldb + k0 + l_kc;
            float4 v0 = *(const float4*)p;
            float4 v1 = *(const float4*)(p + 4);
            Bs[buf][l_kc + 0][l_r] = v0.x; Bs[buf][l_kc + 1][l_r] = v0.y;
            Bs[buf][l_kc + 2][l_r] = v0.z; Bs[buf][l_kc + 3][l_r] = v0.w;
            Bs[buf][l_kc + 4][l_r] = v1.x; Bs[buf][l_kc + 5][l_r] = v1.y;
            Bs[buf][l_kc + 6][l_r] = v1.z; Bs[buf][l_kc + 7][l_r] = v1.w;
        } else {
            const float* p = Bm + (size_t)(k0 + lb_k) * ldb + col0 + lb_n;
            *(float4*)&Bs[buf][lb_k][lb_n] = *(const float4*)p;
            *(float4*)&Bs[buf][lb_k][lb_n + 4] = *(const float4*)(p + 4);
        }
    };

    load(0, 0);
    __syncthreads();
    int buf = 0;
    for (int k0 = 0; k0 < K; k0 += 16) {
        if (k0 + 16 < K) load(buf ^ 1, k0 + 16);
#pragma unroll
        for (int kk = 0; kk < 16; kk++) {
            float4 a = *(const float4*)&As[buf][kk][row_t * 4];
            float4 b0 = *(const float4*)&Bs[buf][kk][col_t * 8];
            float4 b1 = *(const float4*)&Bs[buf][kk][col_t * 8 + 4];
            float ar[4] = {a.x, a.y, a.z, a.w};
            float br[8] = {b0.x, b0.y, b0.z, b0.w, b1.x, b1.y, b1.z, b1.w};
#pragma unroll
            for (int i = 0; i < 4; i++)
#pragma unroll
                for (int j = 0; j < 8; j++) acc[i][j] += ar[i] * br[j];
        }
        buf ^= 1;
        __syncthreads();
    }

#pragma unroll
    for (int i = 0; i < 4; i++) {
        int r = row0 + row_t * 4 + i;
#pragma unroll
        for (int j = 0; j < 8; j++) {
            int c = col0 + col_t * 8 + j;
            float v = acc[i][j] * alpha;
            if (bias) v += bias[c];
            if (Ch) Ch[coff + (size_t)r * ldc + c] = __float2half_rn(v);
            else    C[coff + (size_t)r * ldc + c] = v;
        }
    }
}

// ---------------------------------------------------------------------------
// split-K reduce: s = sum_c part[i+c*cs] (+bias) (gelu?) -> fp32 and/or fp16
// ---------------------------------------------------------------------------
__global__ void reduce_kernel(const float* __restrict__ part, const float* __restrict__ bias,
                              float* __restrict__ outF, __half* __restrict__ outH,
                              int total, int C, long cs, int nb, int act)
{
    int i = blockIdx.x * 256 + threadIdx.x;
    if (i >= total) return;
    float s = 0.f;
    for (int c = 0; c < C; c++) s += part[i + (size_t)c * cs];
    if (bias) s += bias[i % nb];
    if (act) s = 0.5f * s * (1.f + erff(s * 0.7071067811865475f));
    if (outH) outH[i] = __float2half_rn(s);
    if (outF) outF[i] = s;
}

// ---------------------------------------------------------------------------
// transpose + convert: in [R][C] fp32 -> out [C][R] fp16, batched
// ---------------------------------------------------------------------------
__global__ void tconv_kernel(const float* __restrict__ in, __half* __restrict__ out,
                             int R, int C, long sIn, long sOut)
{
    __shared__ float tbuf[32][33];
    in  += (size_t)blockIdx.z * sIn;
    out += (size_t)blockIdx.z * sOut;
    int r0 = blockIdx.y * 32, c0 = blockIdx.x * 32;
    int tx = threadIdx.x, ty = threadIdx.y;
#pragma unroll
    for (int i = 0; i < 4; i++)
        tbuf[ty + i * 8][tx] = in[(size_t)(r0 + ty + i * 8) * C + c0 + tx];
    __syncthreads();
#pragma unroll
    for (int i = 0; i < 4; i++)
        out[(size_t)(c0 + ty + i * 8) * R + r0 + tx] = __float2half_rn(tbuf[tx][ty + i * 8]);
}

// elementwise fp32 -> fp16
__global__ void cvt_kernel(const float* __restrict__ in, __half* __restrict__ out, int n)
{
    int i = (blockIdx.x * 256 + threadIdx.x) * 4;
    if (i >= n) return;
    float4 v = *(const float4*)(in + i);
    *(__half2*)(out + i)     = __floats2half2_rn(v.x, v.y);
    *(__half2*)(out + i + 2) = __floats2half2_rn(v.z, v.w);
}

// ---------------------------------------------------------------------------
// softmax over 4096 cols: fp32 in -> fp16 out (pooling path)
// ---------------------------------------------------------------------------
__global__ __launch_bounds__(256)
void softmax4096_kernel(const float* __restrict__ X, __half* __restrict__ O)
{
    const float* row = X + (size_t)blockIdx.x * 4096;
    __half* orow = O + (size_t)blockIdx.x * 4096;
    int tid = threadIdx.x;
    float4 v[4];
#pragma unroll
    for (int j = 0; j < 4; j++) v[j] = *(const float4*)(row + tid * 16 + 4 * j);

    float m = -1e30f;
#pragma unroll
    for (int j = 0; j < 4; j++)
        m = fmaxf(m, fmaxf(fmaxf(v[j].x, v[j].y), fmaxf(v[j].z, v[j].w)));
    __shared__ float red[8];
#pragma unroll
    for (int s = 16; s > 0; s >>= 1) m = fmaxf(m, __shfl_xor_sync(0xffffffffu, m, s));
    if ((tid & 31) == 0) red[tid >> 5] = m;
    __syncthreads();
    m = red[0];
#pragma unroll
    for (int w = 1; w < 8; w++) m = fmaxf(m, red[w]);

    float sum = 0.f;
#pragma unroll
    for (int j = 0; j < 4; j++) {
        v[j].x = __expf(v[j].x - m); sum += v[j].x;
        v[j].y = __expf(v[j].y - m); sum += v[j].y;
        v[j].z = __expf(v[j].z - m); sum += v[j].z;
        v[j].w = __expf(v[j].w - m); sum += v[j].w;
    }
#pragma unroll
    for (int s = 16; s > 0; s >>= 1) sum += __shfl_xor_sync(0xffffffffu, sum, s);
    __syncthreads();
    if ((tid & 31) == 0) red[tid >> 5] = sum;
    __syncthreads();
    sum = 0.f;
#pragma unroll
    for (int w = 0; w < 8; w++) sum += red[w];
    float inv = 1.f / sum;
#pragma unroll
    for (int j = 0; j < 4; j++) {
        *(__half2*)(orow + tid * 16 + 4 * j)     = __floats2half2_rn(v[j].x * inv, v[j].y * inv);
        *(__half2*)(orow + tid * 16 + 4 * j + 2) = __floats2half2_rn(v[j].z * inv, v[j].w * inv);
    }
}

// ---------------------------------------------------------------------------
// softmax over 4096 cols: in-place fp16 (attention path)
// ---------------------------------------------------------------------------
__global__ __launch_bounds__(256)
void softmax4096h_kernel(__half* __restrict__ X)
{
    __half* row = X + (size_t)blockIdx.x * 4096;
    int tid = threadIdx.x;
    uint4 u0 = *(uint4*)(row + tid * 16);
    uint4 u1 = *(uint4*)(row + tid * 16 + 8);
    float v[16];
    {
        uint32_t w[8] = {u0.x, u0.y, u0.z, u0.w, u1.x, u1.y, u1.z, u1.w};
#pragma unroll
        for (int j = 0; j < 8; j++) {
            float2 f = __half22float2(*(__half2*)&w[j]);
            v[2 * j] = f.x; v[2 * j + 1] = f.y;
        }
    }
    float m = -1e30f;
#pragma unroll
    for (int j = 0; j < 16; j++) m = fmaxf(m, v[j]);
    __shared__ float red[8];
#pragma unroll
    for (int s = 16; s > 0; s >>= 1) m = fmaxf(m, __shfl_xor_sync(0xffffffffu, m, s));
    if ((tid & 31) == 0) red[tid >> 5] = m;
    __syncthreads();
    m = red[0];
#pragma unroll
    for (int w = 1; w < 8; w++) m = fmaxf(m, red[w]);

    float sum = 0.f;
#pragma unroll
    for (int j = 0; j < 16; j++) { v[j] = __expf(v[j] - m); sum += v[j]; }
#pragma unroll
    for (int s = 16; s > 0; s >>= 1) sum += __shfl_xor_sync(0xffffffffu, sum, s);
    __syncthreads();
    if ((tid & 31) == 0) red[tid >> 5] = sum;
    __syncthreads();
    sum = 0.f;
#pragma unroll
    for (int w = 0; w < 8; w++) sum += red[w];
    float inv = 1.f / sum;
#pragma unroll
    for (int j = 0; j < 8; j++)
        *(__half2*)(row + tid * 16 + 2 * j) = __floats2half2_rn(v[2 * j] * inv, v[2 * j + 1] * inv);
}

// ---------------------------------------------------------------------------
// LayerNorm(a+b)*g + beta, fp32 out + optional fp16 out
// ---------------------------------------------------------------------------
__global__ void add_ln_kernel(const float* __restrict__ Xa, const float* __restrict__ Xb,
                              const float* __restrict__ g, const float* __restrict__ beta,
                              float* __restrict__ out, __half* __restrict__ outH)
{
    int r = blockIdx.x;
    const float* a = Xa + (size_t)r * D_;
    const float* b = Xb + (size_t)r * D_;
    __shared__ float red[256];
    int tid = threadIdx.x;
    float v[3];
    float s = 0.f;
#pragma unroll
    for (int i = 0; i < 3; i++) { int c = tid + i * 256; v[i] = a[c] + b[c]; s += v[i]; }
    red[tid] = s; __syncthreads();
    for (int st = 128; st > 0; st >>= 1) {
        if (tid < st) red[tid] += red[tid + st];
        __syncthreads();
    }
    float mean = red[0] * (1.f / D_);
    __syncthreads();
    s = 0.f;
#pragma unroll
    for (int i = 0; i < 3; i++) { float d = v[i] - mean; s += d * d; }
    red[tid] = s; __syncthreads();
    for (int st = 128; st > 0; st >>= 1) {
        if (tid < st) red[tid] += red[tid + st];
        __syncthreads();
    }
    float rstd = rsqrtf(red[0] * (1.f / D_) + 1e-5f);
#pragma unroll
    for (int i = 0; i < 3; i++) {
        int c = tid + i * 256;
        float o = (v[i] - mean) * rstd * g[c] + beta[c];
        out[(size_t)r * D_ + c] = o;
        if (outH) outH[(size_t)r * D_ + c] = __float2half_rn(o);
    }
}

__global__ void make_queries_kernel(const float* __restrict__ x, const float* __restrict__ qc,
                                    float* __restrict__ q, __half* __restrict__ qh)
{
    int i = blockIdx.x * 256 + threadIdx.x;
    int d = i % D_;
    int m = (i / D_) & (M_ - 1);
    float v = x[i] + qc[m * D_ + d];
    q[i] = v;
    qh[i] = __float2half_rn(v);
}

__global__ void bias2_kernel(const float* __restrict__ vb, const float* __restrict__ hw,
                             const float* __restrict__ hb, float* __restrict__ out)
{
    int idx = blockIdx.x * 64 + threadIdx.x;
    int h = idx >> 6, f = idx & 63;
    const float* vbh = vb + h * 64;
    const float* hwh = hw + h * 4096;
    float s = hb[idx];
#pragma unroll 8
    for (int e = 0; e < 64; e++) s += vbh[e] * hwh[e * 64 + f];
    out[idx] = s;
}

// ---------------------------------------------------------------------------
// Host side
// ---------------------------------------------------------------------------
static void hgemm(const __half* A, const __half* B, float* C, __half* Ch, const float* bias,
                  int M, int N, int K, int lda, int ldb, int ldc,
                  long sAi, long sAj, long sBi, long sBj, long sCi, long sCj,
                  long sbj, int I, int J, float alpha, int act)
{
    dim3 grid(N / 128, (M + 127) / 128, I * J);
    hgemm_kernel<<<grid, 128, HG_SMEM>>>(A, B, C, Ch, bias, M, N, K, lda, ldb, ldc,
                                         sAi, sAj, sBi, sBj, sCi, sCj, sbj, J, alpha, act);
}

static void sgemm64(bool transB, const float* A, const float* B, float* C, __half* Ch,
                    const float* bias, int M, int N, int K, int lda, int ldb, int ldc,
                    long sAi, long sAj, long sBi, long sBj, long sCi, long sCj,
                    long sbj, int I, int J, float alpha)
{
    dim3 grid(N / 64, M / 64, I * J);
    if (transB)
        sgemm64_kernel<true><<<grid, 128>>>(A, B, C, Ch, bias, K, lda, ldb, ldc,
                                            sAi, sAj, sBi, sBj, sCi, sCj, sbj, J, alpha);
    else
        sgemm64_kernel<false><<<grid, 128>>>(A, B, C, Ch, bias, K, lda, ldb, ldc,
                                             sAi, sAj, sBi, sBj, sCi, sCj, sbj, J, alpha);
}

template <typename T>
static T* sym(const void* symbol)
{
    void* p = nullptr;
    cudaGetSymbolAddress(&p, symbol);
    return (T*)p;
}

extern "C" void kernel_launch(void* const* d_in, const int* in_sizes, int n_in,
                              void* d_out, int out_size)
{
    cudaFuncSetAttribute(hgemm_kernel, cudaFuncAttributeMaxDynamicSharedMemorySize, HG_SMEM);

    const float* latent = (const float*)d_in[0];
    const float* selector = (const float*)d_in[1];
    const float* qc = (const float*)d_in[2];
    const float* qw = (const float*)d_in[3];
    const float* qb = (const float*)d_in[4];
    const float* kw = (const float*)d_in[5];
    // kb (d_in[6]) cancels exactly in softmax
    const float* vw = (const float*)d_in[7];
    const float* vb = (const float*)d_in[8];
    const float* hw = (const float*)d_in[9];
    const float* hb = (const float*)d_in[10];
    const float* ow = (const float*)d_in[11];
    const float* ob = (const float*)d_in[12];
    const float* w1 = (const float*)d_in[13];
    const float* b1 = (const float*)d_in[14];
    const float* w2 = (const float*)d_in[15];
    const float* b2 = (const float*)d_in[16];
    const float* g1 = (const float*)d_in[17];
    const float* be1 = (const float*)d_in[18];
    const float* g2 = (const float*)d_in[19];
    const float* be2 = (const float*)d_in[20];

    float* S    = sym<float>(g_S);
    float* x    = sym<float>(g_x);
    float* qu   = sym<float>(g_queries);
    float* q2   = sym<float>(g_q2);
    float* ot   = sym<float>(g_ot);
    float* Wf   = sym<float>(g_Wf);
    float* bi2  = sym<float>(g_bias2);
    float* o3   = sym<float>(g_o3);
    float* x1   = sym<float>(g_x1);
    float* mo   = sym<float>(g_mout);
    float* part = sym<float>(g_part);
    float* px   = sym<float>(g_px);
    __half* lat_h  = sym<__half>(g_lat_h);
    __half* latT_h = sym<__half>(g_latT_h);
    __half* P      = sym<__half>(g_P);
    __half* Wq_h   = sym<__half>(g_Wq_h);
    __half* owT_h  = sym<__half>(g_owT_h);
    __half* w1T_h  = sym<__half>(g_w1T_h);
    __half* w2T_h  = sym<__half>(g_w2T_h);
    __half* sel_h  = sym<__half>(g_sel_h);
    __half* qu_h   = sym<__half>(g_qu_h);
    __half* qt_h   = sym<__half>(g_qt_h);
    __half* o2_h   = sym<__half>(g_o2_h);
    __half* x1_h   = sym<__half>(g_x1_h);
    __half* hid_h  = sym<__half>(g_hid_h);
    float* out = (float*)d_out;

    const long LAT_B = (long)N_ * D_;     // 3145728
    const long WHD   = (long)D_ * HD_;    // 49152
    const long WL    = (long)H_ * WHD;
    const long PCH   = (long)BM_ * D_;    // 393216
    const long HMD   = (long)H_ * M_ * D_;   // 589824
    const long HMN   = (long)H_ * M_ * N_;   // 3145728

    dim3 tb(32, 8);

    // ---- pre-pass: fp16 conversions / transposes ----
    cvt_kernel<<<(B_ * N_ * D_) / 1024, 256>>>(latent, lat_h, B_ * N_ * D_);
    cvt_kernel<<<(M_ * D_) / 1024, 256>>>(selector, sel_h, M_ * D_);
    tconv_kernel<<<dim3(D_ / 32, N_ / 32, B_), tb>>>(latent, latT_h, N_, D_, LAT_B, LAT_B);
    tconv_kernel<<<dim3(HD_ / 32, D_ / 32, L_ * H_), tb>>>(qw, Wq_h, D_, HD_, WHD, WHD);
    tconv_kernel<<<dim3(D_ / 32, D_ / 32, L_), tb>>>(ow, owT_h, D_, D_, (long)D_ * D_, (long)D_ * D_);
    tconv_kernel<<<dim3(DH_ / 32, D_ / 32, L_), tb>>>(w1, w1T_h, D_, DH_, (long)D_ * DH_, (long)D_ * DH_);
    tconv_kernel<<<dim3(D_ / 32, DH_ / 32, L_), tb>>>(w2, w2T_h, DH_, D_, (long)DH_ * D_, (long)DH_ * D_);

    // ---- pooling ----
    hgemm(sel_h, lat_h, S, nullptr, nullptr,
          M_, N_, D_, D_, D_, N_,
          0, 0, LAT_B, 0, (long)M_ * N_, 0, 0, B_, 1, 1.0f, 0);
    softmax4096_kernel<<<B_ * M_, 256>>>(S, P);
    hgemm(P, latT_h, px, nullptr, nullptr,
          M_, D_, 1024, N_, N_, D_,
          (long)M_ * N_, 1024, LAT_B, 1024, (long)M_ * D_, (long)B_ * M_ * D_,
          0, B_, 4, 1.0f, 0);
    reduce_kernel<<<(B_ * M_ * D_ + 255) / 256, 256>>>(px, nullptr, x, nullptr,
                                                       B_ * M_ * D_, 4, (long)B_ * M_ * D_, D_, 0);

    for (int l = 0; l < L_; l++) {
        make_queries_kernel<<<(BM_ * D_) / 256, 256>>>(x, qc + (long)l * M_ * D_, qu, qu_h);

        // q2 = queries @ Wq[l]^T + qb[l]  (fp16, split-K 8)
        hgemm(qu_h, Wq_h + (long)l * D_ * D_, part, nullptr, nullptr,
              BM_, D_, 96, D_, D_, D_,
              0, 96, 0, 96, 0, PCH, 0, 1, 8, 1.0f, 0);
        reduce_kernel<<<(BM_ * D_ + 255) / 256, 256>>>(part, qb + (long)l * D_, q2, nullptr,
                                                       BM_ * D_, 8, PCH, D_, 0);

        // qt_h = q2 @ kw^T  (fp32 compute, fp16 out; batched (b,h))
        sgemm64(true, q2, kw + (long)l * WL, nullptr, qt_h, nullptr,
                M_, D_, HD_, D_, HD_, D_,
                (long)M_ * D_, HD_, 0, WHD, HMD, (long)M_ * D_,
                0, B_, H_, 1.0f);

        // S-logits written fp16 straight into P  (batched b)
        hgemm(qt_h, lat_h, nullptr, P, nullptr,
              H_ * M_, N_, D_, D_, D_, N_,
              HMD, 0, LAT_B, 0, HMN, 0,
              0, B_, 1, ATTN_SCALE, 0);

        // in-place fp16 softmax
        softmax4096h_kernel<<<B_ * H_ * M_, 256>>>(P);

        // ot = P @ latent  (fp16, batched b; B = latT_h)
        hgemm(P, latT_h, ot, nullptr, nullptr,
              H_ * M_, D_, N_, N_, N_, D_,
              HMN, 0, LAT_B, 0, HMD, 0,
              0, B_, 1, 1.0f, 0);

        // Wf[h] = vw[l,h] @ hw[l,h]  (fp32)
        sgemm64(false, vw + (long)l * WL, hw + (long)l * H_ * HD_ * HD_, Wf, nullptr, nullptr,
                D_, HD_, HD_, HD_, HD_, HD_,
                0, WHD, 0, (long)HD_ * HD_, 0, WHD, 0, 1, H_, 1.0f);
        bias2_kernel<<<H_, 64>>>(vb + (long)l * H_ * HD_, hw + (long)l * H_ * HD_ * HD_,
                                 hb + (long)l * H_ * HD_, bi2);

        // o2_h = ot @ Wf + bias2  (fp32 compute, fp16 out; batched (b,h))
        sgemm64(false, ot, Wf, nullptr, o2_h, bi2,
                M_, HD_, D_, D_, HD_, D_,
                HMD, WHD, 0, WHD, (long)M_ * D_, HD_,
                HD_, B_, H_, 1.0f);

        // o3 = o2 @ ow[l] + ob[l]  (fp16, split-K 8)
        hgemm(o2_h, owT_h + (long)l * D_ * D_, part, nullptr, nullptr,
              BM_, D_, 96, D_, D_, D_,
              0, 96, 0, 96, 0, PCH, 0, 1, 8, 1.0f, 0);
        reduce_kernel<<<(BM_ * D_ + 255) / 256, 256>>>(part, ob + (long)l * D_, o3, nullptr,
                                                       BM_ * D_, 8, PCH, D_, 0);

        add_ln_kernel<<<BM_, 256>>>(o3, qu, g1 + (long)l * D_, be1 + (long)l * D_, x1, x1_h);

        // hid = gelu(x1 @ w1 + b1)  (fp16, split-K 2)
        hgemm(x1_h, w1T_h + (long)l * D_ * DH_, part, nullptr, nullptr,
              BM_, DH_, 384, D_, D_, DH_,
              0, 384, 0, 384, 0, (long)BM_ * DH_, 0, 1, 2, 1.0f, 0);
        reduce_kernel<<<(BM_ * DH_ + 255) / 256, 256>>>(part, b1 + (long)l * DH_, nullptr, hid_h,
                                                        BM_ * DH_, 2, (long)BM_ * DH_, DH_, 1);

        // mout = hid @ w2 + b2  (fp16, split-K 8)
        hgemm(hid_h, w2T_h + (long)l * DH_ * D_, part, nullptr, nullptr,
              BM_, D_, 384, DH_, DH_, D_,
              0, 384, 0, 384, 0, PCH, 0, 1, 8, 1.0f, 0);
        reduce_kernel<<<(BM_ * D_ + 255) / 256, 256>>>(part, b2 + (long)l * D_, mo, nullptr,
                                                       BM_ * D_, 8, PCH, D_, 0);

        add_ln_kernel<<<BM_, 256>>>(x1, mo, g2 + (long)l * D_, be2 + (long)l * D_,
                                    (l == L_ - 1) ? out : x, nullptr);
    }
}

// round 8
// speedup vs baseline: 6.5328x; 1.0205x over previous
#include <cuda_runtime.h>
#include <cuda_fp16.h>
#include <math.h>
#include <stdint.h>

// Problem constants
#define B_   8
#define N_   4096
#define D_   768
#define H_   12
#define M_   64
#define L_   4
#define HD_  64
#define BM_  (B_ * M_)      // 512
#define DH_  (4 * D_)       // 3072
#define ATTN_SCALE 0.125f

// ---------------------------------------------------------------------------
// Scratch (device globals)
// ---------------------------------------------------------------------------
__device__ float g_x[BM_ * D_];
__device__ float g_queries[BM_ * D_];
__device__ float g_q2[BM_ * D_];
__device__ float g_bias2[L_ * H_ * HD_];     // all layers' fused v/h bias
__device__ float g_o3[BM_ * D_];
__device__ float g_x1[BM_ * D_];
__device__ float g_mout[BM_ * D_];
__device__ float g_part[8 * BM_ * D_];       // split-K partials
__device__ float g_px[4 * B_ * M_ * D_];

// fp16 operand buffers
__device__ __half g_lat_h[B_ * N_ * D_];     // latent fp16 [b][n][d]
__device__ __half g_latT_h[B_ * N_ * D_];    // latent^T fp16 [b][d][n]
__device__ __half g_P[B_ * H_ * M_ * N_];    // logits/probs fp16 (in-place softmax)
__device__ __half g_Wq_h[L_ * D_ * D_];      // qw as [l][h*64+e][d]
__device__ __half g_owT_h[L_ * D_ * D_];     // ow^T per layer [f][d]
__device__ __half g_w1T_h[L_ * D_ * DH_];    // w1^T [l][4D][D]
__device__ __half g_w2T_h[L_ * DH_ * D_];    // w2^T [l][D][4D]
__device__ __half g_Wf_h[L_ * H_ * D_ * HD_];// all layers' fused vw@hw, fp16
__device__ __half g_ot_h[B_ * H_ * M_ * D_]; // attention output, fp16
__device__ __half g_sel_h[M_ * D_];
__device__ __half g_qu_h[BM_ * D_];
__device__ __half g_qt_h[B_ * H_ * M_ * D_];
__device__ __half g_o2_h[BM_ * D_];
__device__ __half g_x1_h[BM_ * D_];
__device__ __half g_hid_h[BM_ * DH_];

// ---------------------------------------------------------------------------
// helpers
// ---------------------------------------------------------------------------
__device__ __forceinline__ void mma_f16(float c[4], const uint32_t a[4], const uint32_t b[2])
{
    asm volatile(
        "mma.sync.aligned.m16n8k16.row.col.f32.f16.f16.f32 "
        "{%0,%1,%2,%3}, {%4,%5,%6,%7}, {%8,%9}, {%0,%1,%2,%3};\n"
        : "+f"(c[0]), "+f"(c[1]), "+f"(c[2]), "+f"(c[3])
        : "r"(a[0]), "r"(a[1]), "r"(a[2]), "r"(a[3]), "r"(b[0]), "r"(b[1]));
}
__device__ __forceinline__ uint32_t smem_u32(const void* p)
{
    return (uint32_t)__cvta_generic_to_shared(p);
}
__device__ __forceinline__ void cpasync16(uint32_t dst, const void* src, int sz)
{
    asm volatile("cp.async.cg.shared.global [%0], [%1], 16, %2;\n"
                 :: "r"(dst), "l"(src), "r"(sz));
}
__device__ __forceinline__ void cp_commit() { asm volatile("cp.async.commit_group;\n"); }
__device__ __forceinline__ void cp_wait2()  { asm volatile("cp.async.wait_group 2;\n"); }

// ---------------------------------------------------------------------------
// hgemm: fp16 tensor GEMM, C(fp32 or fp16) = alpha * A @ B^T (+bias)(+gelu)
// A: [M][K] row-major fp16 (lda). B: [N][K] k-major fp16 (ldb).
// CTA 128x128x32, 128 threads = 4 warps of 64x64 (mt4 x nt8), m16n8k16.
// 4-stage cp.async; fragments via ldmatrix.m8n8.x4 (pad-40 rows: conflict-free).
// Requires K%32==0, N%128==0; M arbitrary (guarded).
// ---------------------------------------------------------------------------
#define HG_STAGES 4
#define HG_SMEM (2 * HG_STAGES * 128 * 40 * 2)   // 81920 bytes

__global__ __launch_bounds__(128, 2)
void hgemm_kernel(const __half* __restrict__ A, const __half* __restrict__ Bm,
                  float* __restrict__ C, __half* __restrict__ Ch,
                  const float* __restrict__ bias,
                  int M, int N, int K, int lda, int ldb, int ldc,
                  long sAi, long sAj, long sBi, long sBj, long sCi, long sCj,
                  long sbj, int J, float alpha, int act)
{
    extern __shared__ __half sm[];
    __half* As = sm;                         // [4][128][40]
    __half* Bs = sm + HG_STAGES * 128 * 40;  // [4][128][40]

    int bz = blockIdx.z;
    int bi = bz / J, bj = bz - bi * J;
    A  += (size_t)bi * sAi + (size_t)bj * sAj;
    Bm += (size_t)bi * sBi + (size_t)bj * sBj;
    if (bias) bias += (size_t)bj * sbj;
    size_t coff = (size_t)bi * sCi + (size_t)bj * sCj;

    const int tid = threadIdx.x;
    const int lane = tid & 31;
    const int g = lane >> 2, t = lane & 3;
    const int warp = tid >> 5;
    const int wm = (warp & 1) * 64;
    const int wn = (warp >> 1) * 64;
    const int row0 = blockIdx.y * 128;
    const int col0 = blockIdx.x * 128;

    const uint32_t sA = smem_u32(As);
    const uint32_t sB = smem_u32(Bs);

    // ldmatrix lane mapping
    const int sel = lane >> 3, l7 = lane & 7;
    const int a_m = (sel & 1) * 8 + l7;
    const int a_k = (sel >> 1) * 8;
    const int b_n = (sel >> 1) * 8 + l7;
    const int b_k = (sel & 1) * 8;

    float acc[4][8][4];
#pragma unroll
    for (int i = 0; i < 4; i++)
#pragma unroll
        for (int j = 0; j < 8; j++)
#pragma unroll
            for (int v = 0; v < 4; v++) acc[i][j][v] = 0.f;

    auto issue = [&](int st, int k0) {
#pragma unroll
        for (int s = 0; s < 4; s++) {
            int idx = s * 128 + tid;
            int row = idx >> 2;
            int ch  = (idx & 3) * 8;
            {
                int r = row0 + row;
                bool ok = (r < M);
                const __half* ga = ok ? (A + (size_t)r * lda + k0 + ch) : A;
                uint32_t da = sA + (uint32_t)(((st * 128 + row) * 40 + ch) * 2);
                cpasync16(da, ga, ok ? 16 : 0);
            }
            {
                const __half* gb = Bm + (size_t)(col0 + row) * ldb + k0 + ch;
                uint32_t db = sB + (uint32_t)(((st * 128 + row) * 40 + ch) * 2);
                cpasync16(db, gb, 16);
            }
        }
    };

    auto compute = [&](int buf) {
        const uint32_t Ab = sA + (uint32_t)(buf * (128 * 40) * 2);
        const uint32_t Bb = sB + (uint32_t)(buf * (128 * 40) * 2);
#pragma unroll
        for (int ko = 0; ko < 32; ko += 16) {
            uint32_t af[4][4];
#pragma unroll
            for (int mt = 0; mt < 4; mt++) {
                uint32_t addr = Ab + (uint32_t)((((wm + mt * 16 + a_m) * 40) + ko + a_k) * 2);
                asm volatile(
                    "ldmatrix.sync.aligned.m8n8.x4.shared.b16 {%0,%1,%2,%3}, [%4];"
                    : "=r"(af[mt][0]), "=r"(af[mt][1]), "=r"(af[mt][2]), "=r"(af[mt][3])
                    : "r"(addr));
            }
            uint32_t bf[8][2];
#pragma unroll
            for (int p = 0; p < 4; p++) {
                uint32_t addr = Bb + (uint32_t)((((wn + p * 16 + b_n) * 40) + ko + b_k) * 2);
                asm volatile(
                    "ldmatrix.sync.aligned.m8n8.x4.shared.b16 {%0,%1,%2,%3}, [%4];"
                    : "=r"(bf[2 * p][0]), "=r"(bf[2 * p][1]),
                      "=r"(bf[2 * p + 1][0]), "=r"(bf[2 * p + 1][1])
                    : "r"(addr));
            }
#pragma unroll
            for (int mt = 0; mt < 4; mt++)
#pragma unroll
                for (int nt = 0; nt < 8; nt++)
                    mma_f16(acc[mt][nt], af[mt], bf[nt]);
        }
    };

    const int KT = K >> 5;
#pragma unroll
    for (int s = 0; s < HG_STAGES - 1; s++) {
        if (s < KT) issue(s, s * 32);
        cp_commit();
    }

    for (int kt = 0; kt < KT; kt++) {
        cp_wait2();
        __syncthreads();
        compute(kt & 3);
        int ns = kt + HG_STAGES - 1;
        if (ns < KT) issue(ns & 3, ns * 32);
        cp_commit();
    }

    // Epilogue
#pragma unroll
    for (int mt = 0; mt < 4; mt++) {
#pragma unroll
        for (int v = 0; v < 2; v++) {
            int r = row0 + wm + mt * 16 + g + v * 8;
            if (r >= M) continue;
#pragma unroll
            for (int nt = 0; nt < 8; nt++) {
                int c = col0 + wn + nt * 8 + 2 * t;
                float v0 = acc[mt][nt][v * 2 + 0] * alpha;
                float v1 = acc[mt][nt][v * 2 + 1] * alpha;
                if (bias) { v0 += bias[c]; v1 += bias[c + 1]; }
                if (act == 1) {
                    v0 = 0.5f * v0 * (1.f + erff(v0 * 0.7071067811865475f));
                    v1 = 0.5f * v1 * (1.f + erff(v1 * 0.7071067811865475f));
                }
                if (Ch) {
                    *(__half2*)&Ch[coff + (size_t)r * ldc + c] = __floats2half2_rn(v0, v1);
                } else {
                    *(float2*)&C[coff + (size_t)r * ldc + c] = make_float2(v0, v1);
                }
            }
        }
    }
}

// ---------------------------------------------------------------------------
// sgemm64: fp32 GEMM for small shapes, optional fp16 output.
// ---------------------------------------------------------------------------
template <bool TRANSB>
__global__ __launch_bounds__(128)
void sgemm64_kernel(const float* __restrict__ A, const float* __restrict__ Bm,
                    float* __restrict__ C, __half* __restrict__ Ch,
                    const float* __restrict__ bias,
                    int K, int lda, int ldb, int ldc,
                    long sAi, long sAj, long sBi, long sBj, long sCi, long sCj,
                    long sbj, int J, float alpha)
{
    __shared__ float As[2][16][68];
    __shared__ float Bs[2][16][68];

    int bz = blockIdx.z;
    int bi = bz / J, bj = bz - bi * J;
    A  += (size_t)bi * sAi + (size_t)bj * sAj;
    Bm += (size_t)bi * sBi + (size_t)bj * sBj;
    size_t coff = (size_t)bi * sCi + (size_t)bj * sCj;
    if (bias) bias += (size_t)bj * sbj;

    const int tid = threadIdx.x;
    const int row_t = tid & 15;
    const int col_t = tid >> 4;
    const int row0 = blockIdx.y * 64;
    const int col0 = blockIdx.x * 64;

    const int l_r  = tid >> 1;
    const int l_kc = (tid & 1) * 8;
    const int lb_k = tid >> 3;
    const int lb_n = (tid & 7) * 8;

    float acc[4][8];
#pragma unroll
    for (int i = 0; i < 4; i++)
#pragma unroll
        for (int j = 0; j < 8; j++) acc[i][j] = 0.f;

    auto load = [&](int buf, int k0) {
        {
            const float* p = A + (size_t)(row0 + l_r) * lda + k0 + l_kc;
            float4 v0 = *(const float4*)p;
            float4 v1 = *(const float4*)(p + 4);
            As[buf][l_kc + 0][l_r] = v0.x; As[buf][l_kc + 1][l_r] = v0.y;
            As[buf][l_kc + 2][l_r] = v0.z; As[buf][l_kc + 3][l_r] = v0.w;
            As[buf][l_kc + 4][l_r] = v1.x; As[buf][l_kc + 5][l_r] = v1.y;
            As[buf][l_kc + 6][l_r] = v1.z; As[buf][l_kc + 7][l_r] = v1.w;
        }
        if (TRANSB) {
            const float* p = Bm + (size_t)(col0 + l_r) * ldb + k0 + l_kc;
            float4 v0 = *(const float4*)p;
            float4 v1 = *(const float4*)(p + 4);
            Bs[buf][l_kc + 0][l_r] = v0.x; Bs[buf][l_kc + 1][l_r] = v0.y;
            Bs[buf][l_kc + 2][l_r] = v0.z; Bs[buf][l_kc + 3][l_r] = v0.w;
            Bs[buf][l_kc + 4][l_r] = v1.x; Bs[buf][l_kc + 5][l_r] = v1.y;
            Bs[buf][l_kc + 6][l_r] = v1.z; Bs[buf][l_kc + 7][l_r] = v1.w;
        } else {
            const float* p = Bm + (size_t)(k0 + lb_k) * ldb + col0 + lb_n;
            *(float4*)&Bs[buf][lb_k][lb_n] = *(const float4*)p;
            *(float4*)&Bs[buf][lb_k][lb_n + 4] = *(const float4*)(p + 4);
        }
    };

    load(0, 0);
    __syncthreads();
    int buf = 0;
    for (int k0 = 0; k0 < K; k0 += 16) {
        if (k0 + 16 < K) load(buf ^ 1, k0 + 16);
#pragma unroll
        for (int kk = 0; kk < 16; kk++) {
            float4 a = *(const float4*)&As[buf][kk][row_t * 4];
            float4 b0 = *(const float4*)&Bs[buf][kk][col_t * 8];
            float4 b1 = *(const float4*)&Bs[buf][kk][col_t * 8 + 4];
            float ar[4] = {a.x, a.y, a.z, a.w};
            float br[8] = {b0.x, b0.y, b0.z, b0.w, b1.x, b1.y, b1.z, b1.w};
#pragma unroll
            for (int i = 0; i < 4; i++)
#pragma unroll
                for (int j = 0; j < 8; j++) acc[i][j] += ar[i] * br[j];
        }
        buf ^= 1;
        __syncthreads();
    }

#pragma unroll
    for (int i = 0; i < 4; i++) {
        int r = row0 + row_t * 4 + i;
#pragma unroll
        for (int j = 0; j < 8; j++) {
            int c = col0 + col_t * 8 + j;
            float v = acc[i][j] * alpha;
            if (bias) v += bias[c];
            if (Ch) Ch[coff + (size_t)r * ldc + c] = __float2half_rn(v);
            else    C[coff + (size_t)r * ldc + c] = v;
        }
    }
}

// ---------------------------------------------------------------------------
// sgemm64h: fp16-input / fp32-compute GEMM (NN only), 64x64 tile, for o2.
// A: [M][K] fp16 (lda), B: [K][N] fp16 (ldb). M,N multiples of 64, K%16==0.
// ---------------------------------------------------------------------------
__global__ __launch_bounds__(128)
void sgemm64h_kernel(const __half* __restrict__ A, const __half* __restrict__ Bm,
                     __half* __restrict__ Ch, const float* __restrict__ bias,
                     int K, int lda, int ldb, int ldc,
                     long sAi, long sAj, long sBi, long sBj, long sCi, long sCj,
                     long sbj, int J)
{
    __shared__ float As[2][16][68];
    __shared__ float Bs[2][16][68];

    int bz = blockIdx.z;
    int bi = bz / J, bj = bz - bi * J;
    A  += (size_t)bi * sAi + (size_t)bj * sAj;
    Bm += (size_t)bi * sBi + (size_t)bj * sBj;
    size_t coff = (size_t)bi * sCi + (size_t)bj * sCj;
    if (bias) bias += (size_t)bj * sbj;

    const int tid = threadIdx.x;
    const int row_t = tid & 15;
    const int col_t = tid >> 4;
    const int row0 = blockIdx.y * 64;
    const int col0 = blockIdx.x * 64;

    const int l_r  = tid >> 1;
    const int l_kc = (tid & 1) * 8;
    const int lb_k = tid >> 3;
    const int lb_n = (tid & 7) * 8;

    float acc[4][8];
#pragma unroll
    for (int i = 0; i < 4; i++)
#pragma unroll
        for (int j = 0; j < 8; j++) acc[i][j] = 0.f;

    auto load = [&](int buf, int k0) {
        {
            const __half* p = A + (size_t)(row0 + l_r) * lda + k0 + l_kc;
            uint4 u = *(const uint4*)p;
            float2 f0 = __half22float2(*(__half2*)&u.x);
            float2 f1 = __half22float2(*(__half2*)&u.y);
            float2 f2 = __half22float2(*(__half2*)&u.z);
            float2 f3 = __half22float2(*(__half2*)&u.w);
            As[buf][l_kc + 0][l_r] = f0.x; As[buf][l_kc + 1][l_r] = f0.y;
            As[buf][l_kc + 2][l_r] = f1.x; As[buf][l_kc + 3][l_r] = f1.y;
            As[buf][l_kc + 4][l_r] = f2.x; As[buf][l_kc + 5][l_r] = f2.y;
            As[buf][l_kc + 6][l_r] = f3.x; As[buf][l_kc + 7][l_r] = f3.y;
        }
        {
            const __half* p = Bm + (size_t)(k0 + lb_k) * ldb + col0 + lb_n;
            uint4 u = *(const uint4*)p;
            float2 f0 = __half22float2(*(__half2*)&u.x);
            float2 f1 = __half22float2(*(__half2*)&u.y);
            float2 f2 = __half22float2(*(__half2*)&u.z);
            float2 f3 = __half22float2(*(__half2*)&u.w);
            Bs[buf][lb_k][lb_n + 0] = f0.x; Bs[buf][lb_k][lb_n + 1] = f0.y;
            Bs[buf][lb_k][lb_n + 2] = f1.x; Bs[buf][lb_k][lb_n + 3] = f1.y;
            Bs[buf][lb_k][lb_n + 4] = f2.x; Bs[buf][lb_k][lb_n + 5] = f2.y;
            Bs[buf][lb_k][lb_n + 6] = f3.x; Bs[buf][lb_k][lb_n + 7] = f3.y;
        }
    };

    load(0, 0);
    __syncthreads();
    int buf = 0;
    for (int k0 = 0; k0 < K; k0 += 16) {
        if (k0 + 16 < K) load(buf ^ 1, k0 + 16);
#pragma unroll
        for (int kk = 0; kk < 16; kk++) {
            float4 a = *(const float4*)&As[buf][kk][row_t * 4];
            float4 b0 = *(const float4*)&Bs[buf][kk][col_t * 8];
            float4 b1 = *(const float4*)&Bs[buf][kk][col_t * 8 + 4];
            float ar[4] = {a.x, a.y, a.z, a.w};
            float br[8] = {b0.x, b0.y, b0.z, b0.w, b1.x, b1.y, b1.z, b1.w};
#pragma unroll
            for (int i = 0; i < 4; i++)
#pragma unroll
                for (int j = 0; j < 8; j++) acc[i][j] += ar[i] * br[j];
        }
        buf ^= 1;
        __syncthreads();
    }

#pragma unroll
    for (int i = 0; i < 4; i++) {
        int r = row0 + row_t * 4 + i;
#pragma unroll
        for (int j = 0; j < 8; j++) {
            int c = col0 + col_t * 8 + j;
            float v = acc[i][j];
            if (bias) v += bias[c];
            Ch[coff + (size_t)r * ldc + c] = __float2half_rn(v);
        }
    }
}

// ---------------------------------------------------------------------------
// split-K reduce
// ---------------------------------------------------------------------------
__global__ void reduce_kernel(const float* __restrict__ part, const float* __restrict__ bias,
                              float* __restrict__ outF, __half* __restrict__ outH,
                              int total, int C, long cs, int nb, int act)
{
    int i = blockIdx.x * 256 + threadIdx.x;
    if (i >= total) return;
    float s = 0.f;
    for (int c = 0; c < C; c++) s += part[i + (size_t)c * cs];
    if (bias) s += bias[i % nb];
    if (act) s = 0.5f * s * (1.f + erff(s * 0.7071067811865475f));
    if (outH) outH[i] = __float2half_rn(s);
    if (outF) outF[i] = s;
}

// ---------------------------------------------------------------------------
// fused latent prep: read fp32 latent once, write lat_h (same layout)
// and latT_h (transposed) fp16
// ---------------------------------------------------------------------------
__global__ void latprep_kernel(const float* __restrict__ in,
                               __half* __restrict__ outN, __half* __restrict__ outT)
{
    __shared__ float tbuf[32][33];
    size_t zo = (size_t)blockIdx.z * N_ * D_;
    int r0 = blockIdx.y * 32, c0 = blockIdx.x * 32;   // r = n, c = d
    int tx = threadIdx.x, ty = threadIdx.y;
#pragma unroll
    for (int i = 0; i < 4; i++) {
        int r = r0 + ty + i * 8;
        float v = in[zo + (size_t)r * D_ + c0 + tx];
        tbuf[ty + i * 8][tx] = v;
        outN[zo + (size_t)r * D_ + c0 + tx] = __float2half_rn(v);
    }
    __syncthreads();
#pragma unroll
    for (int i = 0; i < 4; i++)
        outT[zo + (size_t)(c0 + ty + i * 8) * N_ + r0 + tx] = __float2half_rn(tbuf[tx][ty + i * 8]);
}

// transpose + convert fp32 [R][C] -> fp16 [C][R], batched (weights)
__global__ void tconv_kernel(const float* __restrict__ in, __half* __restrict__ out,
                             int R, int C, long sIn, long sOut)
{
    __shared__ float tbuf[32][33];
    in  += (size_t)blockIdx.z * sIn;
    out += (size_t)blockIdx.z * sOut;
    int r0 = blockIdx.y * 32, c0 = blockIdx.x * 32;
    int tx = threadIdx.x, ty = threadIdx.y;
#pragma unroll
    for (int i = 0; i < 4; i++)
        tbuf[ty + i * 8][tx] = in[(size_t)(r0 + ty + i * 8) * C + c0 + tx];
    __syncthreads();
#pragma unroll
    for (int i = 0; i < 4; i++)
        out[(size_t)(c0 + ty + i * 8) * R + r0 + tx] = __float2half_rn(tbuf[tx][ty + i * 8]);
}

// elementwise fp32 -> fp16
__global__ void cvt_kernel(const float* __restrict__ in, __half* __restrict__ out, int n)
{
    int i = (blockIdx.x * 256 + threadIdx.x) * 4;
    if (i >= n) return;
    float4 v = *(const float4*)(in + i);
    *(__half2*)(out + i)     = __floats2half2_rn(v.x, v.y);
    *(__half2*)(out + i + 2) = __floats2half2_rn(v.z, v.w);
}

// ---------------------------------------------------------------------------
// softmax over 4096 cols: in-place fp16
// ---------------------------------------------------------------------------
__global__ __launch_bounds__(256)
void softmax4096h_kernel(__half* __restrict__ X)
{
    __half* row = X + (size_t)blockIdx.x * 4096;
    int tid = threadIdx.x;
    uint4 u0 = *(uint4*)(row + tid * 16);
    uint4 u1 = *(uint4*)(row + tid * 16 + 8);
    float v[16];
    {
        uint32_t w[8] = {u0.x, u0.y, u0.z, u0.w, u1.x, u1.y, u1.z, u1.w};
#pragma unroll
        for (int j = 0; j < 8; j++) {
            float2 f = __half22float2(*(__half2*)&w[j]);
            v[2 * j] = f.x; v[2 * j + 1] = f.y;
        }
    }
    float m = -1e30f;
#pragma unroll
    for (int j = 0; j < 16; j++) m = fmaxf(m, v[j]);
    __shared__ float red[8];
#pragma unroll
    for (int s = 16; s > 0; s >>= 1) m = fmaxf(m, __shfl_xor_sync(0xffffffffu, m, s));
    if ((tid & 31) == 0) red[tid >> 5] = m;
    __syncthreads();
    m = red[0];
#pragma unroll
    for (int w = 1; w < 8; w++) m = fmaxf(m, red[w]);

    float sum = 0.f;
#pragma unroll
    for (int j = 0; j < 16; j++) { v[j] = __expf(v[j] - m); sum += v[j]; }
#pragma unroll
    for (int s = 16; s > 0; s >>= 1) sum += __shfl_xor_sync(0xffffffffu, sum, s);
    __syncthreads();
    if ((tid & 31) == 0) red[tid >> 5] = sum;
    __syncthreads();
    sum = 0.f;
#pragma unroll
    for (int w = 0; w < 8; w++) sum += red[w];
    float inv = 1.f / sum;
#pragma unroll
    for (int j = 0; j < 8; j++)
        *(__half2*)(row + tid * 16 + 2 * j) = __floats2half2_rn(v[2 * j] * inv, v[2 * j + 1] * inv);
}

// ---------------------------------------------------------------------------
// LayerNorm(a+b)*g + beta, fp32 out + optional fp16 out
// ---------------------------------------------------------------------------
__global__ void add_ln_kernel(const float* __restrict__ Xa, const float* __restrict__ Xb,
                              const float* __restrict__ g, const float* __restrict__ beta,
                              float* __restrict__ out, __half* __restrict__ outH)
{
    int r = blockIdx.x;
    const float* a = Xa + (size_t)r * D_;
    const float* b = Xb + (size_t)r * D_;
    __shared__ float red[256];
    int tid = threadIdx.x;
    float v[3];
    float s = 0.f;
#pragma unroll
    for (int i = 0; i < 3; i++) { int c = tid + i * 256; v[i] = a[c] + b[c]; s += v[i]; }
    red[tid] = s; __syncthreads();
    for (int st = 128; st > 0; st >>= 1) {
        if (tid < st) red[tid] += red[tid + st];
        __syncthreads();
    }
    float mean = red[0] * (1.f / D_);
    __syncthreads();
    s = 0.f;
#pragma unroll
    for (int i = 0; i < 3; i++) { float d = v[i] - mean; s += d * d; }
    red[tid] = s; __syncthreads();
    for (int st = 128; st > 0; st >>= 1) {
        if (tid < st) red[tid] += red[tid + st];
        __syncthreads();
    }
    float rstd = rsqrtf(red[0] * (1.f / D_) + 1e-5f);
#pragma unroll
    for (int i = 0; i < 3; i++) {
        int c = tid + i * 256;
        float o = (v[i] - mean) * rstd * g[c] + beta[c];
        out[(size_t)r * D_ + c] = o;
        if (outH) outH[(size_t)r * D_ + c] = __float2half_rn(o);
    }
}

__global__ void make_queries_kernel(const float* __restrict__ x, const float* __restrict__ qc,
                                    float* __restrict__ q, __half* __restrict__ qh)
{
    int i = blockIdx.x * 256 + threadIdx.x;
    int d = i % D_;
    int m = (i / D_) & (M_ - 1);
    float v = x[i] + qc[m * D_ + d];
    q[i] = v;
    qh[i] = __float2half_rn(v);
}

// bias2[lh,f] = sum_e vb[lh,e]*hw[lh,e,f] + hb[lh,f]   (all L*H at once)
__global__ void bias2_kernel(const float* __restrict__ vb, const float* __restrict__ hw,
                             const float* __restrict__ hb, float* __restrict__ out)
{
    int idx = blockIdx.x * 64 + threadIdx.x;   // <<<L*H, 64>>>
    int h = idx >> 6, f = idx & 63;
    const float* vbh = vb + h * 64;
    const float* hwh = hw + h * 4096;
    float s = hb[idx];
#pragma unroll 8
    for (int e = 0; e < 64; e++) s += vbh[e] * hwh[e * 64 + f];
    out[idx] = s;
}

// ---------------------------------------------------------------------------
// Host side
// ---------------------------------------------------------------------------
static void hgemm(const __half* A, const __half* B, float* C, __half* Ch, const float* bias,
                  int M, int N, int K, int lda, int ldb, int ldc,
                  long sAi, long sAj, long sBi, long sBj, long sCi, long sCj,
                  long sbj, int I, int J, float alpha, int act)
{
    dim3 grid(N / 128, (M + 127) / 128, I * J);
    hgemm_kernel<<<grid, 128, HG_SMEM>>>(A, B, C, Ch, bias, M, N, K, lda, ldb, ldc,
                                         sAi, sAj, sBi, sBj, sCi, sCj, sbj, J, alpha, act);
}

static void sgemm64(bool transB, const float* A, const float* B, float* C, __half* Ch,
                    const float* bias, int M, int N, int K, int lda, int ldb, int ldc,
                    long sAi, long sAj, long sBi, long sBj, long sCi, long sCj,
                    long sbj, int I, int J, float alpha)
{
    dim3 grid(N / 64, M / 64, I * J);
    if (transB)
        sgemm64_kernel<true><<<grid, 128>>>(A, B, C, Ch, bias, K, lda, ldb, ldc,
                                            sAi, sAj, sBi, sBj, sCi, sCj, sbj, J, alpha);
    else
        sgemm64_kernel<false><<<grid, 128>>>(A, B, C, Ch, bias, K, lda, ldb, ldc,
                                             sAi, sAj, sBi, sBj, sCi, sCj, sbj, J, alpha);
}

template <typename T>
static T* sym(const void* symbol)
{
    void* p = nullptr;
    cudaGetSymbolAddress(&p, symbol);
    return (T*)p;
}

extern "C" void kernel_launch(void* const* d_in, const int* in_sizes, int n_in,
                              void* d_out, int out_size)
{
    cudaFuncSetAttribute(hgemm_kernel, cudaFuncAttributeMaxDynamicSharedMemorySize, HG_SMEM);

    const float* latent = (const float*)d_in[0];
    const float* selector = (const float*)d_in[1];
    const float* qc = (const float*)d_in[2];
    const float* qw = (const float*)d_in[3];
    const float* qb = (const float*)d_in[4];
    const float* kw = (const float*)d_in[5];
    // kb (d_in[6]) cancels exactly in softmax
    const float* vw = (const float*)d_in[7];
    const float* vb = (const float*)d_in[8];
    const float* hw = (const float*)d_in[9];
    const float* hb = (const float*)d_in[10];
    const float* ow = (const float*)d_in[11];
    const float* ob = (const float*)d_in[12];
    const float* w1 = (const float*)d_in[13];
    const float* b1 = (const float*)d_in[14];
    const float* w2 = (const float*)d_in[15];
    const float* b2 = (const float*)d_in[16];
    const float* g1 = (const float*)d_in[17];
    const float* be1 = (const float*)d_in[18];
    const float* g2 = (const float*)d_in[19];
    const float* be2 = (const float*)d_in[20];

    float* x    = sym<float>(g_x);
    float* qu   = sym<float>(g_queries);
    float* q2   = sym<float>(g_q2);
    float* bi2  = sym<float>(g_bias2);
    float* o3   = sym<float>(g_o3);
    float* x1   = sym<float>(g_x1);
    float* mo   = sym<float>(g_mout);
    float* part = sym<float>(g_part);
    float* px   = sym<float>(g_px);
    __half* lat_h  = sym<__half>(g_lat_h);
    __half* latT_h = sym<__half>(g_latT_h);
    __half* P      = sym<__half>(g_P);
    __half* Wq_h   = sym<__half>(g_Wq_h);
    __half* owT_h  = sym<__half>(g_owT_h);
    __half* w1T_h  = sym<__half>(g_w1T_h);
    __half* w2T_h  = sym<__half>(g_w2T_h);
    __half* Wf_h   = sym<__half>(g_Wf_h);
    __half* ot_h   = sym<__half>(g_ot_h);
    __half* sel_h  = sym<__half>(g_sel_h);
    __half* qu_h   = sym<__half>(g_qu_h);
    __half* qt_h   = sym<__half>(g_qt_h);
    __half* o2_h   = sym<__half>(g_o2_h);
    __half* x1_h   = sym<__half>(g_x1_h);
    __half* hid_h  = sym<__half>(g_hid_h);
    float* out = (float*)d_out;

    const long LAT_B = (long)N_ * D_;     // 3145728
    const long WHD   = (long)D_ * HD_;    // 49152
    const long WL    = (long)H_ * WHD;
    const long PCH   = (long)BM_ * D_;    // 393216
    const long HMD   = (long)H_ * M_ * D_;   // 589824
    const long HMN   = (long)H_ * M_ * N_;   // 3145728

    dim3 tb(32, 8);

    // ---- pre-pass: conversions / transposes / layer-invariant fusions ----
    latprep_kernel<<<dim3(D_ / 32, N_ / 32, B_), tb>>>(latent, lat_h, latT_h);
    cvt_kernel<<<(M_ * D_) / 1024, 256>>>(selector, sel_h, M_ * D_);
    tconv_kernel<<<dim3(HD_ / 32, D_ / 32, L_ * H_), tb>>>(qw, Wq_h, D_, HD_, WHD, WHD);
    tconv_kernel<<<dim3(D_ / 32, D_ / 32, L_), tb>>>(ow, owT_h, D_, D_, (long)D_ * D_, (long)D_ * D_);
    tconv_kernel<<<dim3(DH_ / 32, D_ / 32, L_), tb>>>(w1, w1T_h, D_, DH_, (long)D_ * DH_, (long)D_ * DH_);
    tconv_kernel<<<dim3(D_ / 32, DH_ / 32, L_), tb>>>(w2, w2T_h, DH_, D_, (long)DH_ * D_, (long)DH_ * D_);
    // Wf[lh] = vw[lh] @ hw[lh]  (fp32 compute, fp16 out; all L*H heads)
    sgemm64(false, vw, hw, nullptr, Wf_h, nullptr,
            D_, HD_, HD_, HD_, HD_, HD_,
            0, WHD, 0, (long)HD_ * HD_, 0, WHD, 0, 1, L_ * H_, 1.0f);
    bias2_kernel<<<L_ * H_, 64>>>(vb, hw, hb, bi2);

    // ---- pooling ----
    // logits fp16 straight into P, in-place softmax
    hgemm(sel_h, lat_h, nullptr, P, nullptr,
          M_, N_, D_, D_, D_, N_,
          0, 0, LAT_B, 0, (long)M_ * N_, 0, 0, B_, 1, 1.0f, 0);
    softmax4096h_kernel<<<B_ * M_, 256>>>(P);
    hgemm(P, latT_h, px, nullptr, nullptr,
          M_, D_, 1024, N_, N_, D_,
          (long)M_ * N_, 1024, LAT_B, 1024, (long)M_ * D_, (long)B_ * M_ * D_,
          0, B_, 4, 1.0f, 0);
    reduce_kernel<<<(B_ * M_ * D_ + 255) / 256, 256>>>(px, nullptr, x, nullptr,
                                                       B_ * M_ * D_, 4, (long)B_ * M_ * D_, D_, 0);

    for (int l = 0; l < L_; l++) {
        make_queries_kernel<<<(BM_ * D_) / 256, 256>>>(x, qc + (long)l * M_ * D_, qu, qu_h);

        // q2 = queries @ Wq[l]^T + qb[l]  (fp16, split-K 8)
        hgemm(qu_h, Wq_h + (long)l * D_ * D_, part, nullptr, nullptr,
              BM_, D_, 96, D_, D_, D_,
              0, 96, 0, 96, 0, PCH, 0, 1, 8, 1.0f, 0);
        reduce_kernel<<<(BM_ * D_ + 255) / 256, 256>>>(part, qb + (long)l * D_, q2, nullptr,
                                                       BM_ * D_, 8, PCH, D_, 0);

        // qt_h = q2 @ kw^T  (fp32 compute, fp16 out; batched (b,h))
        sgemm64(true, q2, kw + (long)l * WL, nullptr, qt_h, nullptr,
                M_, D_, HD_, D_, HD_, D_,
                (long)M_ * D_, HD_, 0, WHD, HMD, (long)M_ * D_,
                0, B_, H_, 1.0f);

        // S-logits written fp16 straight into P  (batched b)
        hgemm(qt_h, lat_h, nullptr, P, nullptr,
              H_ * M_, N_, D_, D_, D_, N_,
              HMD, 0, LAT_B, 0, HMN, 0,
              0, B_, 1, ATTN_SCALE, 0);

        softmax4096h_kernel<<<B_ * H_ * M_, 256>>>(P);

        // ot (fp16) = P @ latent  (batched b; B = latT_h)
        hgemm(P, latT_h, nullptr, ot_h, nullptr,
              H_ * M_, D_, N_, N_, N_, D_,
              HMN, 0, LAT_B, 0, HMD, 0,
              0, B_, 1, 1.0f, 0);

        // o2_h = ot_h @ Wf_h[l] + bias2[l]  (fp16 in, fp32 FFMA; batched (b,h))
        {
            dim3 grid(1, 1, B_ * H_);
            sgemm64h_kernel<<<grid, 128>>>(ot_h, Wf_h + (long)l * WL, o2_h,
                                           bi2 + (long)l * H_ * HD_,
                                           D_, D_, HD_, D_,
                                           HMD, WHD, 0, WHD, (long)M_ * D_, HD_,
                                           HD_, H_);
        }

        // o3 = o2 @ ow[l] + ob[l]  (fp16, split-K 8)
        hgemm(o2_h, owT_h + (long)l * D_ * D_, part, nullptr, nullptr,
              BM_, D_, 96, D_, D_, D_,
              0, 96, 0, 96, 0, PCH, 0, 1, 8, 1.0f, 0);
        reduce_kernel<<<(BM_ * D_ + 255) / 256, 256>>>(part, ob + (long)l * D_, o3, nullptr,
                                                       BM_ * D_, 8, PCH, D_, 0);

        add_ln_kernel<<<BM_, 256>>>(o3, qu, g1 + (long)l * D_, be1 + (long)l * D_, x1, x1_h);

        // hid = gelu(x1 @ w1 + b1)  (fp16, split-K 2)
        hgemm(x1_h, w1T_h + (long)l * D_ * DH_, part, nullptr, nullptr,
              BM_, DH_, 384, D_, D_, DH_,
              0, 384, 0, 384, 0, (long)BM_ * DH_, 0, 1, 2, 1.0f, 0);
        reduce_kernel<<<(BM_ * DH_ + 255) / 256, 256>>>(part, b1 + (long)l * DH_, nullptr, hid_h,
                                                        BM_ * DH_, 2, (long)BM_ * DH_, DH_, 1);

        // mout = hid @ w2 + b2  (fp16, split-K 8)
        hgemm(hid_h, w2T_h + (long)l * DH_ * D_, part, nullptr, nullptr,
              BM_, D_, 384, DH_, DH_, D_,
              0, 384, 0, 384, 0, PCH, 0, 1, 8, 1.0f, 0);
        reduce_kernel<<<(BM_ * D_ + 255) / 256, 256>>>(part, b2 + (long)l * D_, mo, nullptr,
                                                       BM_ * D_, 8, PCH, D_, 0);

        add_ln_kernel<<<BM_, 256>>>(x1, mo, g2 + (long)l * D_, be2 + (long)l * D_,
                                    (l == L_ - 1) ? out : x, nullptr);
    }
}

// round 9
// speedup vs baseline: 6.7809x; 1.0380x over previous
#include <cuda_runtime.h>
#include <cuda_fp16.h>
#include <math.h>
#include <stdint.h>

// Problem constants
#define B_   8
#define N_   4096
#define D_   768
#define H_   12
#define M_   64
#define L_   4
#define HD_  64
#define BM_  (B_ * M_)      // 512
#define DH_  (4 * D_)       // 3072
#define ATTN_SCALE 0.125f

// ---------------------------------------------------------------------------
// Scratch (device globals)
// ---------------------------------------------------------------------------
__device__ float g_x[BM_ * D_];
__device__ float g_queries[BM_ * D_];
__device__ float g_bias2[L_ * H_ * HD_];     // all layers' fused v/h bias
__device__ float g_x1[BM_ * D_];
__device__ float g_part[8 * BM_ * D_];       // split-K partials
__device__ float g_px[4 * B_ * M_ * D_];

// fp16 operand buffers
__device__ __half g_lat_h[B_ * N_ * D_];     // latent fp16 [b][n][d]
__device__ __half g_latT_h[B_ * N_ * D_];    // latent^T fp16 [b][d][n]
__device__ __half g_P[B_ * H_ * M_ * N_];    // logits/probs fp16 (in-place softmax)
__device__ __half g_Wq_h[L_ * D_ * D_];      // qw as [l][h*64+e][d]
__device__ __half g_kw_h[L_ * H_ * D_ * HD_];// kw fp16 (same layout as input)
__device__ __half g_owT_h[L_ * D_ * D_];     // ow^T per layer [f][d]
__device__ __half g_w1T_h[L_ * D_ * DH_];    // w1^T [l][4D][D]
__device__ __half g_w2T_h[L_ * DH_ * D_];    // w2^T [l][D][4D]
__device__ __half g_Wf_h[L_ * H_ * D_ * HD_];// all layers' fused vw@hw, fp16
__device__ __half g_ot_h[B_ * H_ * M_ * D_]; // attention output, fp16
__device__ __half g_sel_h[M_ * D_];
__device__ __half g_qu_h[BM_ * D_];
__device__ __half g_q2_h[BM_ * D_];
__device__ __half g_qt_h[B_ * H_ * M_ * D_];
__device__ __half g_o2_h[BM_ * D_];
__device__ __half g_x1_h[BM_ * D_];
__device__ __half g_hid_h[BM_ * DH_];

// ---------------------------------------------------------------------------
// helpers
// ---------------------------------------------------------------------------
__device__ __forceinline__ void mma_f16(float c[4], const uint32_t a[4], const uint32_t b[2])
{
    asm volatile(
        "mma.sync.aligned.m16n8k16.row.col.f32.f16.f16.f32 "
        "{%0,%1,%2,%3}, {%4,%5,%6,%7}, {%8,%9}, {%0,%1,%2,%3};\n"
        : "+f"(c[0]), "+f"(c[1]), "+f"(c[2]), "+f"(c[3])
        : "r"(a[0]), "r"(a[1]), "r"(a[2]), "r"(a[3]), "r"(b[0]), "r"(b[1]));
}
__device__ __forceinline__ uint32_t smem_u32(const void* p)
{
    return (uint32_t)__cvta_generic_to_shared(p);
}
__device__ __forceinline__ void cpasync16(uint32_t dst, const void* src, int sz)
{
    asm volatile("cp.async.cg.shared.global [%0], [%1], 16, %2;\n"
                 :: "r"(dst), "l"(src), "r"(sz));
}
__device__ __forceinline__ void cp_commit() { asm volatile("cp.async.commit_group;\n"); }
__device__ __forceinline__ void cp_wait2()  { asm volatile("cp.async.wait_group 2;\n"); }

// ---------------------------------------------------------------------------
// hgemm: fp16 tensor GEMM, C(fp32 or fp16) = alpha * A @ B^T (+bias)(+gelu)
// A: [M][K] row-major fp16 (lda). B: [N][K] k-major fp16 (ldb).
// CTA 128x128x32, 128 threads = 4 warps of 64x64 (mt4 x nt8), m16n8k16.
// 4-stage cp.async; fragments via ldmatrix.m8n8.x4 (pad-40 rows: conflict-free).
// Requires K%32==0, N%128==0; M arbitrary (guarded). Works for KT>=1.
// ---------------------------------------------------------------------------
#define HG_STAGES 4
#define HG_SMEM (2 * HG_STAGES * 128 * 40 * 2)   // 81920 bytes

__global__ __launch_bounds__(128, 2)
void hgemm_kernel(const __half* __restrict__ A, const __half* __restrict__ Bm,
                  float* __restrict__ C, __half* __restrict__ Ch,
                  const float* __restrict__ bias,
                  int M, int N, int K, int lda, int ldb, int ldc,
                  long sAi, long sAj, long sBi, long sBj, long sCi, long sCj,
                  long sbj, int J, float alpha, int act)
{
    extern __shared__ __half sm[];
    __half* As = sm;                         // [4][128][40]
    __half* Bs = sm + HG_STAGES * 128 * 40;  // [4][128][40]

    int bz = blockIdx.z;
    int bi = bz / J, bj = bz - bi * J;
    A  += (size_t)bi * sAi + (size_t)bj * sAj;
    Bm += (size_t)bi * sBi + (size_t)bj * sBj;
    if (bias) bias += (size_t)bj * sbj;
    size_t coff = (size_t)bi * sCi + (size_t)bj * sCj;

    const int tid = threadIdx.x;
    const int lane = tid & 31;
    const int g = lane >> 2, t = lane & 3;
    const int warp = tid >> 5;
    const int wm = (warp & 1) * 64;
    const int wn = (warp >> 1) * 64;
    const int row0 = blockIdx.y * 128;
    const int col0 = blockIdx.x * 128;

    const uint32_t sA = smem_u32(As);
    const uint32_t sB = smem_u32(Bs);

    // ldmatrix lane mapping
    const int sel = lane >> 3, l7 = lane & 7;
    const int a_m = (sel & 1) * 8 + l7;
    const int a_k = (sel >> 1) * 8;
    const int b_n = (sel >> 1) * 8 + l7;
    const int b_k = (sel & 1) * 8;

    float acc[4][8][4];
#pragma unroll
    for (int i = 0; i < 4; i++)
#pragma unroll
        for (int j = 0; j < 8; j++)
#pragma unroll
            for (int v = 0; v < 4; v++) acc[i][j][v] = 0.f;

    auto issue = [&](int st, int k0) {
#pragma unroll
        for (int s = 0; s < 4; s++) {
            int idx = s * 128 + tid;
            int row = idx >> 2;
            int ch  = (idx & 3) * 8;
            {
                int r = row0 + row;
                bool ok = (r < M);
                const __half* ga = ok ? (A + (size_t)r * lda + k0 + ch) : A;
                uint32_t da = sA + (uint32_t)(((st * 128 + row) * 40 + ch) * 2);
                cpasync16(da, ga, ok ? 16 : 0);
            }
            {
                const __half* gb = Bm + (size_t)(col0 + row) * ldb + k0 + ch;
                uint32_t db = sB + (uint32_t)(((st * 128 + row) * 40 + ch) * 2);
                cpasync16(db, gb, 16);
            }
        }
    };

    auto compute = [&](int buf) {
        const uint32_t Ab = sA + (uint32_t)(buf * (128 * 40) * 2);
        const uint32_t Bb = sB + (uint32_t)(buf * (128 * 40) * 2);
#pragma unroll
        for (int ko = 0; ko < 32; ko += 16) {
            uint32_t af[4][4];
#pragma unroll
            for (int mt = 0; mt < 4; mt++) {
                uint32_t addr = Ab + (uint32_t)((((wm + mt * 16 + a_m) * 40) + ko + a_k) * 2);
                asm volatile(
                    "ldmatrix.sync.aligned.m8n8.x4.shared.b16 {%0,%1,%2,%3}, [%4];"
                    : "=r"(af[mt][0]), "=r"(af[mt][1]), "=r"(af[mt][2]), "=r"(af[mt][3])
                    : "r"(addr));
            }
            uint32_t bf[8][2];
#pragma unroll
            for (int p = 0; p < 4; p++) {
                uint32_t addr = Bb + (uint32_t)((((wn + p * 16 + b_n) * 40) + ko + b_k) * 2);
                asm volatile(
                    "ldmatrix.sync.aligned.m8n8.x4.shared.b16 {%0,%1,%2,%3}, [%4];"
                    : "=r"(bf[2 * p][0]), "=r"(bf[2 * p][1]),
                      "=r"(bf[2 * p + 1][0]), "=r"(bf[2 * p + 1][1])
                    : "r"(addr));
            }
#pragma unroll
            for (int mt = 0; mt < 4; mt++)
#pragma unroll
                for (int nt = 0; nt < 8; nt++)
                    mma_f16(acc[mt][nt], af[mt], bf[nt]);
        }
    };

    const int KT = K >> 5;
#pragma unroll
    for (int s = 0; s < HG_STAGES - 1; s++) {
        if (s < KT) issue(s, s * 32);
        cp_commit();
    }

    for (int kt = 0; kt < KT; kt++) {
        cp_wait2();
        __syncthreads();
        compute(kt & 3);
        int ns = kt + HG_STAGES - 1;
        if (ns < KT) issue(ns & 3, ns * 32);
        cp_commit();
    }

    // Epilogue
#pragma unroll
    for (int mt = 0; mt < 4; mt++) {
#pragma unroll
        for (int v = 0; v < 2; v++) {
            int r = row0 + wm + mt * 16 + g + v * 8;
            if (r >= M) continue;
#pragma unroll
            for (int nt = 0; nt < 8; nt++) {
                int c = col0 + wn + nt * 8 + 2 * t;
                float v0 = acc[mt][nt][v * 2 + 0] * alpha;
                float v1 = acc[mt][nt][v * 2 + 1] * alpha;
                if (bias) { v0 += bias[c]; v1 += bias[c + 1]; }
                if (act == 1) {
                    v0 = 0.5f * v0 * (1.f + erff(v0 * 0.7071067811865475f));
                    v1 = 0.5f * v1 * (1.f + erff(v1 * 0.7071067811865475f));
                }
                if (Ch) {
                    *(__half2*)&Ch[coff + (size_t)r * ldc + c] = __floats2half2_rn(v0, v1);
                } else {
                    *(float2*)&C[coff + (size_t)r * ldc + c] = make_float2(v0, v1);
                }
            }
        }
    }
}

// ---------------------------------------------------------------------------
// sgemm64: fp32 GEMM for small shapes, optional fp16 output. (pre-pass Wf)
// ---------------------------------------------------------------------------
template <bool TRANSB>
__global__ __launch_bounds__(128)
void sgemm64_kernel(const float* __restrict__ A, const float* __restrict__ Bm,
                    float* __restrict__ C, __half* __restrict__ Ch,
                    const float* __restrict__ bias,
                    int K, int lda, int ldb, int ldc,
                    long sAi, long sAj, long sBi, long sBj, long sCi, long sCj,
                    long sbj, int J, float alpha)
{
    __shared__ float As[2][16][68];
    __shared__ float Bs[2][16][68];

    int bz = blockIdx.z;
    int bi = bz / J, bj = bz - bi * J;
    A  += (size_t)bi * sAi + (size_t)bj * sAj;
    Bm += (size_t)bi * sBi + (size_t)bj * sBj;
    size_t coff = (size_t)bi * sCi + (size_t)bj * sCj;
    if (bias) bias += (size_t)bj * sbj;

    const int tid = threadIdx.x;
    const int row_t = tid & 15;
    const int col_t = tid >> 4;
    const int row0 = blockIdx.y * 64;
    const int col0 = blockIdx.x * 64;

    const int l_r  = tid >> 1;
    const int l_kc = (tid & 1) * 8;
    const int lb_k = tid >> 3;
    const int lb_n = (tid & 7) * 8;

    float acc[4][8];
#pragma unroll
    for (int i = 0; i < 4; i++)
#pragma unroll
        for (int j = 0; j < 8; j++) acc[i][j] = 0.f;

    auto load = [&](int buf, int k0) {
        {
            const float* p = A + (size_t)(row0 + l_r) * lda + k0 + l_kc;
            float4 v0 = *(const float4*)p;
            float4 v1 = *(const float4*)(p + 4);
            As[buf][l_kc + 0][l_r] = v0.x; As[buf][l_kc + 1][l_r] = v0.y;
            As[buf][l_kc + 2][l_r] = v0.z; As[buf][l_kc + 3][l_r] = v0.w;
            As[buf][l_kc + 4][l_r] = v1.x; As[buf][l_kc + 5][l_r] = v1.y;
            As[buf][l_kc + 6][l_r] = v1.z; As[buf][l_kc + 7][l_r] = v1.w;
        }
        if (TRANSB) {
            const float* p = Bm + (size_t)(col0 + l_r) * ldb + k0 + l_kc;
            float4 v0 = *(const float4*)p;
            float4 v1 = *(const float4*)(p + 4);
            Bs[buf][l_kc + 0][l_r] = v0.x; Bs[buf][l_kc + 1][l_r] = v0.y;
            Bs[buf][l_kc + 2][l_r] = v0.z; Bs[buf][l_kc + 3][l_r] = v0.w;
            Bs[buf][l_kc + 4][l_r] = v1.x; Bs[buf][l_kc + 5][l_r] = v1.y;
            Bs[buf][l_kc + 6][l_r] = v1.z; Bs[buf][l_kc + 7][l_r] = v1.w;
        } else {
            const float* p = Bm + (size_t)(k0 + lb_k) * ldb + col0 + lb_n;
            *(float4*)&Bs[buf][lb_k][lb_n] = *(const float4*)p;
            *(float4*)&Bs[buf][lb_k][lb_n + 4] = *(const float4*)(p + 4);
        }
    };

    load(0, 0);
    __syncthreads();
    int buf = 0;
    for (int k0 = 0; k0 < K; k0 += 16) {
        if (k0 + 16 < K) load(buf ^ 1, k0 + 16);
#pragma unroll
        for (int kk = 0; kk < 16; kk++) {
            float4 a = *(const float4*)&As[buf][kk][row_t * 4];
            float4 b0 = *(const float4*)&Bs[buf][kk][col_t * 8];
            float4 b1 = *(const float4*)&Bs[buf][kk][col_t * 8 + 4];
            float ar[4] = {a.x, a.y, a.z, a.w};
            float br[8] = {b0.x, b0.y, b0.z, b0.w, b1.x, b1.y, b1.z, b1.w};
#pragma unroll
            for (int i = 0; i < 4; i++)
#pragma unroll
                for (int j = 0; j < 8; j++) acc[i][j] += ar[i] * br[j];
        }
        buf ^= 1;
        __syncthreads();
    }

#pragma unroll
    for (int i = 0; i < 4; i++) {
        int r = row0 + row_t * 4 + i;
#pragma unroll
        for (int j = 0; j < 8; j++) {
            int c = col0 + col_t * 8 + j;
            float v = acc[i][j] * alpha;
            if (bias) v += bias[c];
            if (Ch) Ch[coff + (size_t)r * ldc + c] = __float2half_rn(v);
            else    C[coff + (size_t)r * ldc + c] = v;
        }
    }
}

// ---------------------------------------------------------------------------
// sgemm64h: fp16-input / fp32-compute GEMM (NN only), 64x64 tile, for o2.
// ---------------------------------------------------------------------------
__global__ __launch_bounds__(128)
void sgemm64h_kernel(const __half* __restrict__ A, const __half* __restrict__ Bm,
                     __half* __restrict__ Ch, const float* __restrict__ bias,
                     int K, int lda, int ldb, int ldc,
                     long sAi, long sAj, long sBi, long sBj, long sCi, long sCj,
                     long sbj, int J)
{
    __shared__ float As[2][16][68];
    __shared__ float Bs[2][16][68];

    int bz = blockIdx.z;
    int bi = bz / J, bj = bz - bi * J;
    A  += (size_t)bi * sAi + (size_t)bj * sAj;
    Bm += (size_t)bi * sBi + (size_t)bj * sBj;
    size_t coff = (size_t)bi * sCi + (size_t)bj * sCj;
    if (bias) bias += (size_t)bj * sbj;

    const int tid = threadIdx.x;
    const int row_t = tid & 15;
    const int col_t = tid >> 4;
    const int row0 = blockIdx.y * 64;
    const int col0 = blockIdx.x * 64;

    const int l_r  = tid >> 1;
    const int l_kc = (tid & 1) * 8;
    const int lb_k = tid >> 3;
    const int lb_n = (tid & 7) * 8;

    float acc[4][8];
#pragma unroll
    for (int i = 0; i < 4; i++)
#pragma unroll
        for (int j = 0; j < 8; j++) acc[i][j] = 0.f;

    auto load = [&](int buf, int k0) {
        {
            const __half* p = A + (size_t)(row0 + l_r) * lda + k0 + l_kc;
            uint4 u = *(const uint4*)p;
            float2 f0 = __half22float2(*(__half2*)&u.x);
            float2 f1 = __half22float2(*(__half2*)&u.y);
            float2 f2 = __half22float2(*(__half2*)&u.z);
            float2 f3 = __half22float2(*(__half2*)&u.w);
            As[buf][l_kc + 0][l_r] = f0.x; As[buf][l_kc + 1][l_r] = f0.y;
            As[buf][l_kc + 2][l_r] = f1.x; As[buf][l_kc + 3][l_r] = f1.y;
            As[buf][l_kc + 4][l_r] = f2.x; As[buf][l_kc + 5][l_r] = f2.y;
            As[buf][l_kc + 6][l_r] = f3.x; As[buf][l_kc + 7][l_r] = f3.y;
        }
        {
            const __half* p = Bm + (size_t)(k0 + lb_k) * ldb + col0 + lb_n;
            uint4 u = *(const uint4*)p;
            float2 f0 = __half22float2(*(__half2*)&u.x);
            float2 f1 = __half22float2(*(__half2*)&u.y);
            float2 f2 = __half22float2(*(__half2*)&u.z);
            float2 f3 = __half22float2(*(__half2*)&u.w);
            Bs[buf][lb_k][lb_n + 0] = f0.x; Bs[buf][lb_k][lb_n + 1] = f0.y;
            Bs[buf][lb_k][lb_n + 2] = f1.x; Bs[buf][lb_k][lb_n + 3] = f1.y;
            Bs[buf][lb_k][lb_n + 4] = f2.x; Bs[buf][lb_k][lb_n + 5] = f2.y;
            Bs[buf][lb_k][lb_n + 6] = f3.x; Bs[buf][lb_k][lb_n + 7] = f3.y;
        }
    };

    load(0, 0);
    __syncthreads();
    int buf = 0;
    for (int k0 = 0; k0 < K; k0 += 16) {
        if (k0 + 16 < K) load(buf ^ 1, k0 + 16);
#pragma unroll
        for (int kk = 0; kk < 16; kk++) {
            float4 a = *(const float4*)&As[buf][kk][row_t * 4];
            float4 b0 = *(const float4*)&Bs[buf][kk][col_t * 8];
            float4 b1 = *(const float4*)&Bs[buf][kk][col_t * 8 + 4];
            float ar[4] = {a.x, a.y, a.z, a.w};
            float br[8] = {b0.x, b0.y, b0.z, b0.w, b1.x, b1.y, b1.z, b1.w};
#pragma unroll
            for (int i = 0; i < 4; i++)
#pragma unroll
                for (int j = 0; j < 8; j++) acc[i][j] += ar[i] * br[j];
        }
        buf ^= 1;
        __syncthreads();
    }

#pragma unroll
    for (int i = 0; i < 4; i++) {
        int r = row0 + row_t * 4 + i;
#pragma unroll
        for (int j = 0; j < 8; j++) {
            int c = col0 + col_t * 8 + j;
            float v = acc[i][j];
            if (bias) v += bias[c];
            Ch[coff + (size_t)r * ldc + c] = __float2half_rn(v);
        }
    }
}

// ---------------------------------------------------------------------------
// split-K reduce (pooling x, q2)
// ---------------------------------------------------------------------------
__global__ void reduce_kernel(const float* __restrict__ part, const float* __restrict__ bias,
                              float* __restrict__ outF, __half* __restrict__ outH,
                              int total, int C, long cs, int nb, int act)
{
    int i = blockIdx.x * 256 + threadIdx.x;
    if (i >= total) return;
    float s = 0.f;
    for (int c = 0; c < C; c++) s += part[i + (size_t)c * cs];
    if (bias) s += bias[i % nb];
    if (act) s = 0.5f * s * (1.f + erff(s * 0.7071067811865475f));
    if (outH) outH[i] = __float2half_rn(s);
    if (outF) outF[i] = s;
}

// ---------------------------------------------------------------------------
// fused latent prep: read fp32 latent once, write lat_h and latT_h fp16
// ---------------------------------------------------------------------------
__global__ void latprep_kernel(const float* __restrict__ in,
                               __half* __restrict__ outN, __half* __restrict__ outT)
{
    __shared__ float tbuf[32][33];
    size_t zo = (size_t)blockIdx.z * N_ * D_;
    int r0 = blockIdx.y * 32, c0 = blockIdx.x * 32;
    int tx = threadIdx.x, ty = threadIdx.y;
#pragma unroll
    for (int i = 0; i < 4; i++) {
        int r = r0 + ty + i * 8;
        float v = in[zo + (size_t)r * D_ + c0 + tx];
        tbuf[ty + i * 8][tx] = v;
        outN[zo + (size_t)r * D_ + c0 + tx] = __float2half_rn(v);
    }
    __syncthreads();
#pragma unroll
    for (int i = 0; i < 4; i++)
        outT[zo + (size_t)(c0 + ty + i * 8) * N_ + r0 + tx] = __float2half_rn(tbuf[tx][ty + i * 8]);
}

// transpose + convert fp32 [R][C] -> fp16 [C][R], batched (weights)
__global__ void tconv_kernel(const float* __restrict__ in, __half* __restrict__ out,
                             int R, int C, long sIn, long sOut)
{
    __shared__ float tbuf[32][33];
    in  += (size_t)blockIdx.z * sIn;
    out += (size_t)blockIdx.z * sOut;
    int r0 = blockIdx.y * 32, c0 = blockIdx.x * 32;
    int tx = threadIdx.x, ty = threadIdx.y;
#pragma unroll
    for (int i = 0; i < 4; i++)
        tbuf[ty + i * 8][tx] = in[(size_t)(r0 + ty + i * 8) * C + c0 + tx];
    __syncthreads();
#pragma unroll
    for (int i = 0; i < 4; i++)
        out[(size_t)(c0 + ty + i * 8) * R + r0 + tx] = __float2half_rn(tbuf[tx][ty + i * 8]);
}

// elementwise fp32 -> fp16
__global__ void cvt_kernel(const float* __restrict__ in, __half* __restrict__ out, int n)
{
    int i = (blockIdx.x * 256 + threadIdx.x) * 4;
    if (i >= n) return;
    float4 v = *(const float4*)(in + i);
    *(__half2*)(out + i)     = __floats2half2_rn(v.x, v.y);
    *(__half2*)(out + i + 2) = __floats2half2_rn(v.z, v.w);
}

// ---------------------------------------------------------------------------
// softmax over 4096 cols: in-place fp16
// ---------------------------------------------------------------------------
__global__ __launch_bounds__(256)
void softmax4096h_kernel(__half* __restrict__ X)
{
    __half* row = X + (size_t)blockIdx.x * 4096;
    int tid = threadIdx.x;
    uint4 u0 = *(uint4*)(row + tid * 16);
    uint4 u1 = *(uint4*)(row + tid * 16 + 8);
    float v[16];
    {
        uint32_t w[8] = {u0.x, u0.y, u0.z, u0.w, u1.x, u1.y, u1.z, u1.w};
#pragma unroll
        for (int j = 0; j < 8; j++) {
            float2 f = __half22float2(*(__half2*)&w[j]);
            v[2 * j] = f.x; v[2 * j + 1] = f.y;
        }
    }
    float m = -1e30f;
#pragma unroll
    for (int j = 0; j < 16; j++) m = fmaxf(m, v[j]);
    __shared__ float red[8];
#pragma unroll
    for (int s = 16; s > 0; s >>= 1) m = fmaxf(m, __shfl_xor_sync(0xffffffffu, m, s));
    if ((tid & 31) == 0) red[tid >> 5] = m;
    __syncthreads();
    m = red[0];
#pragma unroll
    for (int w = 1; w < 8; w++) m = fmaxf(m, red[w]);

    float sum = 0.f;
#pragma unroll
    for (int j = 0; j < 16; j++) { v[j] = __expf(v[j] - m); sum += v[j]; }
#pragma unroll
    for (int s = 16; s > 0; s >>= 1) sum += __shfl_xor_sync(0xffffffffu, sum, s);
    __syncthreads();
    if ((tid & 31) == 0) red[tid >> 5] = sum;
    __syncthreads();
    sum = 0.f;
#pragma unroll
    for (int w = 0; w < 8; w++) sum += red[w];
    float inv = 1.f / sum;
#pragma unroll
    for (int j = 0; j < 8; j++)
        *(__half2*)(row + tid * 16 + 2 * j) = __floats2half2_rn(v[2 * j] * inv, v[2 * j + 1] * inv);
}

// ---------------------------------------------------------------------------
// Fused split-K reduce + residual + LayerNorm:
//   val[c] = sum_{k<C} part[k*cs + r*768 + c] + bias[c] + other[r*768 + c]
//   out = LN(val)*g + beta   (fp32 out + optional fp16 out)
// ---------------------------------------------------------------------------
__global__ void add_ln_red_kernel(const float* __restrict__ part, int C, long cs,
                                  const float* __restrict__ bias,
                                  const float* __restrict__ other,
                                  const float* __restrict__ g, const float* __restrict__ beta,
                                  float* __restrict__ out, __half* __restrict__ outH)
{
    int r = blockIdx.x;
    const float* o = other + (size_t)r * D_;
    __shared__ float red[256];
    int tid = threadIdx.x;
    float v[3];
    float s = 0.f;
#pragma unroll
    for (int i = 0; i < 3; i++) {
        int c = tid + i * 256;
        float acc = o[c] + bias[c];
        size_t base = (size_t)r * D_ + c;
        for (int k = 0; k < C; k++) acc += part[base + (size_t)k * cs];
        v[i] = acc;
        s += acc;
    }
    red[tid] = s; __syncthreads();
    for (int st = 128; st > 0; st >>= 1) {
        if (tid < st) red[tid] += red[tid + st];
        __syncthreads();
    }
    float mean = red[0] * (1.f / D_);
    __syncthreads();
    s = 0.f;
#pragma unroll
    for (int i = 0; i < 3; i++) { float d = v[i] - mean; s += d * d; }
    red[tid] = s; __syncthreads();
    for (int st = 128; st > 0; st >>= 1) {
        if (tid < st) red[tid] += red[tid + st];
        __syncthreads();
    }
    float rstd = rsqrtf(red[0] * (1.f / D_) + 1e-5f);
#pragma unroll
    for (int i = 0; i < 3; i++) {
        int c = tid + i * 256;
        float oo = (v[i] - mean) * rstd * g[c] + beta[c];
        out[(size_t)r * D_ + c] = oo;
        if (outH) outH[(size_t)r * D_ + c] = __float2half_rn(oo);
    }
}

__global__ void make_queries_kernel(const float* __restrict__ x, const float* __restrict__ qc,
                                    float* __restrict__ q, __half* __restrict__ qh)
{
    int i = blockIdx.x * 256 + threadIdx.x;
    int d = i % D_;
    int m = (i / D_) & (M_ - 1);
    float v = x[i] + qc[m * D_ + d];
    q[i] = v;
    qh[i] = __float2half_rn(v);
}

// bias2[lh,f] = sum_e vb[lh,e]*hw[lh,e,f] + hb[lh,f]
__global__ void bias2_kernel(const float* __restrict__ vb, const float* __restrict__ hw,
                             const float* __restrict__ hb, float* __restrict__ out)
{
    int idx = blockIdx.x * 64 + threadIdx.x;
    int h = idx >> 6, f = idx & 63;
    const float* vbh = vb + h * 64;
    const float* hwh = hw + h * 4096;
    float s = hb[idx];
#pragma unroll 8
    for (int e = 0; e < 64; e++) s += vbh[e] * hwh[e * 64 + f];
    out[idx] = s;
}

// ---------------------------------------------------------------------------
// Host side
// ---------------------------------------------------------------------------
static void hgemm(const __half* A, const __half* B, float* C, __half* Ch, const float* bias,
                  int M, int N, int K, int lda, int ldb, int ldc,
                  long sAi, long sAj, long sBi, long sBj, long sCi, long sCj,
                  long sbj, int I, int J, float alpha, int act)
{
    dim3 grid(N / 128, (M + 127) / 128, I * J);
    hgemm_kernel<<<grid, 128, HG_SMEM>>>(A, B, C, Ch, bias, M, N, K, lda, ldb, ldc,
                                         sAi, sAj, sBi, sBj, sCi, sCj, sbj, J, alpha, act);
}

static void sgemm64(bool transB, const float* A, const float* B, float* C, __half* Ch,
                    const float* bias, int M, int N, int K, int lda, int ldb, int ldc,
                    long sAi, long sAj, long sBi, long sBj, long sCi, long sCj,
                    long sbj, int I, int J, float alpha)
{
    dim3 grid(N / 64, M / 64, I * J);
    if (transB)
        sgemm64_kernel<true><<<grid, 128>>>(A, B, C, Ch, bias, K, lda, ldb, ldc,
                                            sAi, sAj, sBi, sBj, sCi, sCj, sbj, J, alpha);
    else
        sgemm64_kernel<false><<<grid, 128>>>(A, B, C, Ch, bias, K, lda, ldb, ldc,
                                             sAi, sAj, sBi, sBj, sCi, sCj, sbj, J, alpha);
}

template <typename T>
static T* sym(const void* symbol)
{
    void* p = nullptr;
    cudaGetSymbolAddress(&p, symbol);
    return (T*)p;
}

extern "C" void kernel_launch(void* const* d_in, const int* in_sizes, int n_in,
                              void* d_out, int out_size)
{
    cudaFuncSetAttribute(hgemm_kernel, cudaFuncAttributeMaxDynamicSharedMemorySize, HG_SMEM);

    const float* latent = (const float*)d_in[0];
    const float* selector = (const float*)d_in[1];
    const float* qc = (const float*)d_in[2];
    const float* qw = (const float*)d_in[3];
    const float* qb = (const float*)d_in[4];
    const float* kw = (const float*)d_in[5];
    // kb (d_in[6]) cancels exactly in softmax
    const float* vw = (const float*)d_in[7];
    const float* vb = (const float*)d_in[8];
    const float* hw = (const float*)d_in[9];
    const float* hb = (const float*)d_in[10];
    const float* ow = (const float*)d_in[11];
    const float* ob = (const float*)d_in[12];
    const float* w1 = (const float*)d_in[13];
    const float* b1 = (const float*)d_in[14];
    const float* w2 = (const float*)d_in[15];
    const float* b2 = (const float*)d_in[16];
    const float* g1 = (const float*)d_in[17];
    const float* be1 = (const float*)d_in[18];
    const float* g2 = (const float*)d_in[19];
    const float* be2 = (const float*)d_in[20];

    float* x    = sym<float>(g_x);
    float* qu   = sym<float>(g_queries);
    float* bi2  = sym<float>(g_bias2);
    float* x1   = sym<float>(g_x1);
    float* part = sym<float>(g_part);
    float* px   = sym<float>(g_px);
    __half* lat_h  = sym<__half>(g_lat_h);
    __half* latT_h = sym<__half>(g_latT_h);
    __half* P      = sym<__half>(g_P);
    __half* Wq_h   = sym<__half>(g_Wq_h);
    __half* kw_h   = sym<__half>(g_kw_h);
    __half* owT_h  = sym<__half>(g_owT_h);
    __half* w1T_h  = sym<__half>(g_w1T_h);
    __half* w2T_h  = sym<__half>(g_w2T_h);
    __half* Wf_h   = sym<__half>(g_Wf_h);
    __half* ot_h   = sym<__half>(g_ot_h);
    __half* sel_h  = sym<__half>(g_sel_h);
    __half* qu_h   = sym<__half>(g_qu_h);
    __half* q2_h   = sym<__half>(g_q2_h);
    __half* qt_h   = sym<__half>(g_qt_h);
    __half* o2_h   = sym<__half>(g_o2_h);
    __half* x1_h   = sym<__half>(g_x1_h);
    __half* hid_h  = sym<__half>(g_hid_h);
    float* out = (float*)d_out;

    const long LAT_B = (long)N_ * D_;     // 3145728
    const long WHD   = (long)D_ * HD_;    // 49152
    const long WL    = (long)H_ * WHD;
    const long PCH   = (long)BM_ * D_;    // 393216
    const long HMD   = (long)H_ * M_ * D_;   // 589824
    const long HMN   = (long)H_ * M_ * N_;   // 3145728

    dim3 tb(32, 8);

    // ---- pre-pass: conversions / transposes / layer-invariant fusions ----
    latprep_kernel<<<dim3(D_ / 32, N_ / 32, B_), tb>>>(latent, lat_h, latT_h);
    cvt_kernel<<<(M_ * D_) / 1024, 256>>>(selector, sel_h, M_ * D_);
    cvt_kernel<<<(L_ * H_ * D_ * HD_) / 1024, 256>>>(kw, kw_h, L_ * H_ * D_ * HD_);
    tconv_kernel<<<dim3(HD_ / 32, D_ / 32, L_ * H_), tb>>>(qw, Wq_h, D_, HD_, WHD, WHD);
    tconv_kernel<<<dim3(D_ / 32, D_ / 32, L_), tb>>>(ow, owT_h, D_, D_, (long)D_ * D_, (long)D_ * D_);
    tconv_kernel<<<dim3(DH_ / 32, D_ / 32, L_), tb>>>(w1, w1T_h, D_, DH_, (long)D_ * DH_, (long)D_ * DH_);
    tconv_kernel<<<dim3(D_ / 32, DH_ / 32, L_), tb>>>(w2, w2T_h, DH_, D_, (long)DH_ * D_, (long)DH_ * D_);
    // Wf[lh] = vw[lh] @ hw[lh]  (fp32 compute, fp16 out; all L*H heads)
    sgemm64(false, vw, hw, nullptr, Wf_h, nullptr,
            D_, HD_, HD_, HD_, HD_, HD_,
            0, WHD, 0, (long)HD_ * HD_, 0, WHD, 0, 1, L_ * H_, 1.0f);
    bias2_kernel<<<L_ * H_, 64>>>(vb, hw, hb, bi2);

    // ---- pooling ----
    hgemm(sel_h, lat_h, nullptr, P, nullptr,
          M_, N_, D_, D_, D_, N_,
          0, 0, LAT_B, 0, (long)M_ * N_, 0, 0, B_, 1, 1.0f, 0);
    softmax4096h_kernel<<<B_ * M_, 256>>>(P);
    hgemm(P, latT_h, px, nullptr, nullptr,
          M_, D_, 1024, N_, N_, D_,
          (long)M_ * N_, 1024, LAT_B, 1024, (long)M_ * D_, (long)B_ * M_ * D_,
          0, B_, 4, 1.0f, 0);
    reduce_kernel<<<(B_ * M_ * D_ + 255) / 256, 256>>>(px, nullptr, x, nullptr,
                                                       B_ * M_ * D_, 4, (long)B_ * M_ * D_, D_, 0);

    for (int l = 0; l < L_; l++) {
        make_queries_kernel<<<(BM_ * D_) / 256, 256>>>(x, qc + (long)l * M_ * D_, qu, qu_h);

        // q2 = queries @ Wq[l]^T + qb[l]  (fp16, split-K 8; fp16 result)
        hgemm(qu_h, Wq_h + (long)l * D_ * D_, part, nullptr, nullptr,
              BM_, D_, 96, D_, D_, D_,
              0, 96, 0, 96, 0, PCH, 0, 1, 8, 1.0f, 0);
        reduce_kernel<<<(BM_ * D_ + 255) / 256, 256>>>(part, qb + (long)l * D_, nullptr, q2_h,
                                                       BM_ * D_, 8, PCH, D_, 0);

        // qt_h = q2_h @ kw_h^T  (tensor fp16; batched (b,h), K=64)
        hgemm(q2_h, kw_h + (long)l * WL, nullptr, qt_h, nullptr,
              M_, D_, HD_, D_, HD_, D_,
              (long)M_ * D_, HD_, 0, WHD, HMD, (long)M_ * D_,
              0, B_, H_, 1.0f, 0);

        // S-logits written fp16 straight into P  (batched b)
        hgemm(qt_h, lat_h, nullptr, P, nullptr,
              H_ * M_, N_, D_, D_, D_, N_,
              HMD, 0, LAT_B, 0, HMN, 0,
              0, B_, 1, ATTN_SCALE, 0);

        softmax4096h_kernel<<<B_ * H_ * M_, 256>>>(P);

        // ot (fp16) = P @ latent  (batched b; B = latT_h)
        hgemm(P, latT_h, nullptr, ot_h, nullptr,
              H_ * M_, D_, N_, N_, N_, D_,
              HMN, 0, LAT_B, 0, HMD, 0,
              0, B_, 1, 1.0f, 0);

        // o2_h = ot_h @ Wf_h[l] + bias2[l]  (fp16 in, fp32 FFMA; batched (b,h))
        {
            dim3 grid(1, 1, B_ * H_);
            sgemm64h_kernel<<<grid, 128>>>(ot_h, Wf_h + (long)l * WL, o2_h,
                                           bi2 + (long)l * H_ * HD_,
                                           D_, D_, HD_, D_,
                                           HMD, WHD, 0, WHD, (long)M_ * D_, HD_,
                                           HD_, H_);
        }

        // o3 partials = o2 @ ow[l]  (fp16, split-K 8)
        hgemm(o2_h, owT_h + (long)l * D_ * D_, part, nullptr, nullptr,
              BM_, D_, 96, D_, D_, D_,
              0, 96, 0, 96, 0, PCH, 0, 1, 8, 1.0f, 0);
        // x1 = LN(sum(part) + ob + queries)   (fused reduce + residual + LN)
        add_ln_red_kernel<<<BM_, 256>>>(part, 8, PCH, ob + (long)l * D_, qu,
                                        g1 + (long)l * D_, be1 + (long)l * D_, x1, x1_h);

        // hid = gelu(x1 @ w1 + b1)  (fp16, unsplit, bias+gelu in epilogue)
        hgemm(x1_h, w1T_h + (long)l * D_ * DH_, nullptr, hid_h, b1 + (long)l * DH_,
              BM_, DH_, D_, D_, D_, DH_,
              0, 0, 0, 0, 0, 0, 0, 1, 1, 1.0f, 1);

        // mout partials = hid @ w2  (fp16, split-K 8)
        hgemm(hid_h, w2T_h + (long)l * DH_ * D_, part, nullptr, nullptr,
              BM_, D_, 384, DH_, DH_, D_,
              0, 384, 0, 384, 0, PCH, 0, 1, 8, 1.0f, 0);
        // x = LN(sum(part) + b2 + x1)
        add_ln_red_kernel<<<BM_, 256>>>(part, 8, PCH, b2 + (long)l * D_, x1,
                                        g2 + (long)l * D_, be2 + (long)l * D_,
                                        (l == L_ - 1) ? out : x, nullptr);
    }
}